// round 1
// baseline (speedup 1.0000x reference)
#include <cuda_runtime.h>
#include <cstdint>

#define Bb   2
#define Tt   1024
#define DIMD 1024
#define Hh   8
#define DHh  64
#define Ee   5
#define KK   3
#define BT   2048          // B*T
#define HS   512           // H*DH
#define VN   2560          // H*E*DH
#define HE   40            // H*E
#define QSCALE 0.125f      // DH^-0.5

// ---------------- scratch (static device globals; no runtime allocation) ----
__device__ float g_Q  [BT * HS];
__device__ float g_K  [BT * HS];
__device__ float g_V  [BT * VN];   // per-expert V: [bt][(h*E+e)*64+d]
__device__ float g_Ss [BT * HE];   // source routing logits
__device__ float g_Sd [BT * HE];   // dest routing logits
__device__ float g_Vm [BT * HS];   // mixed V: [bt][h*64+d]
__device__ float g_sdg[BT * HE];   // 0/1 dest gates
__device__ float g_O  [BT * HS];   // attention out: [bt][h*64+d]
__device__ float g_A  [BT * VN];   // sd-gated o, GEMM A operand
__device__ float g_WoT[VN * DIMD]; // Wo transposed to [hec][d]

// ---------------- generic fp32 SGEMM body: 128x128x8, 8x8/thread ------------
__device__ __forceinline__ void sgemm_body(
    const float* __restrict__ A, const float* __restrict__ B, float* __restrict__ C,
    int N, int Kd, int col0, int row0)
{
    __shared__ float As[8][128];
    __shared__ float Bs[8][128];
    const int tid  = threadIdx.x;
    const int trow = (tid >> 4) << 3;      // 0..120
    const int tcol = (tid & 15) << 3;      // 0..120
    const int a_r  = tid >> 1;             // 0..127
    const int a_c  = (tid & 1) << 2;       // 0 or 4
    const int b_r  = tid >> 5;             // 0..7
    const int b_c  = (tid & 31) << 2;      // 0..124

    float acc[8][8];
#pragma unroll
    for (int i = 0; i < 8; i++)
#pragma unroll
        for (int j = 0; j < 8; j++) acc[i][j] = 0.f;

    const float* Aptr = A + (size_t)(row0 + a_r) * Kd + a_c;

    for (int k0 = 0; k0 < Kd; k0 += 8) {
        float4 av = *(const float4*)(Aptr + k0);
        As[a_c + 0][a_r] = av.x; As[a_c + 1][a_r] = av.y;
        As[a_c + 2][a_r] = av.z; As[a_c + 3][a_r] = av.w;

        float4 bv = make_float4(0.f, 0.f, 0.f, 0.f);
        int col = col0 + b_c;
        if (col < N) bv = *(const float4*)(B + (size_t)(k0 + b_r) * N + col);
        *(float4*)&Bs[b_r][b_c] = bv;
        __syncthreads();

#pragma unroll
        for (int kk = 0; kk < 8; kk++) {
            float4 a0 = *(float4*)&As[kk][trow];
            float4 a1 = *(float4*)&As[kk][trow + 4];
            float4 b0 = *(float4*)&Bs[kk][tcol];
            float4 b1 = *(float4*)&Bs[kk][tcol + 4];
            float ar[8] = {a0.x, a0.y, a0.z, a0.w, a1.x, a1.y, a1.z, a1.w};
            float br[8] = {b0.x, b0.y, b0.z, b0.w, b1.x, b1.y, b1.z, b1.w};
#pragma unroll
            for (int i = 0; i < 8; i++)
#pragma unroll
                for (int j = 0; j < 8; j++)
                    acc[i][j] = fmaf(ar[i], br[j], acc[i][j]);
        }
        __syncthreads();
    }

#pragma unroll
    for (int i = 0; i < 8; i++) {
        int r = row0 + trow + i;
#pragma unroll
        for (int j = 0; j < 8; j += 4) {
            int c = col0 + tcol + j;
            if (c < N)
                *(float4*)(C + (size_t)r * N + c) =
                    make_float4(acc[i][j], acc[i][j+1], acc[i][j+2], acc[i][j+3]);
        }
    }
}

// ---------------- kernel 1: fused x @ [Wq|Wk|Wv|Ws|Wd] ----------------------
__global__ __launch_bounds__(256)
void qkv_gemm(const float* __restrict__ x,
              const float* __restrict__ Wq, const float* __restrict__ Wk,
              const float* __restrict__ Wv, const float* __restrict__ Ws,
              const float* __restrict__ Wd)
{
    int bx = blockIdx.x;
    const float* B; float* C; int N; int col0;
    if      (bx < 4)  { B = Wq; C = g_Q;  N = 512;  col0 = bx * 128; }
    else if (bx < 8)  { B = Wk; C = g_K;  N = 512;  col0 = (bx - 4) * 128; }
    else if (bx < 28) { B = Wv; C = g_V;  N = 2560; col0 = (bx - 8) * 128; }
    else if (bx == 28){ B = Ws; C = g_Ss; N = 40;   col0 = 0; }
    else              { B = Wd; C = g_Sd; N = 40;   col0 = 0; }
    sgemm_body(x, B, C, N, DIMD, col0, blockIdx.y * 128);
}

// ---------------- kernel 2: routing gates + expert V mix --------------------
__global__ __launch_bounds__(256)
void route_mix()
{
    int gid = blockIdx.x * blockDim.x + threadIdx.x;   // over BT*H*64
    if (gid >= BT * Hh * 64) return;
    int d   = gid & 63;
    int bth = gid >> 6;
    int h   = bth & 7;
    int bt  = bth >> 3;

    const float* sl = g_Ss + bt * HE + h * Ee;
    float s[Ee];
#pragma unroll
    for (int e = 0; e < Ee; e++) s[e] = sl[e];

    float acc = 0.f;
#pragma unroll
    for (int e = 0; e < Ee; e++) {
        int rank = 0;
#pragma unroll
        for (int j = 0; j < Ee; j++)
            rank += (s[j] > s[e]) || (s[j] == s[e] && j < e);
        float gate = (rank < KK) ? 1.0f / (1.0f + expf(-s[e])) : 0.f;
        acc = fmaf(gate, g_V[(size_t)bt * VN + (h * Ee + e) * 64 + d], acc);
    }
    g_Vm[(size_t)bt * HS + h * 64 + d] = acc;

    if (d < Ee) {
        const float* dl = g_Sd + bt * HE + h * Ee;
        float t[Ee];
#pragma unroll
        for (int e = 0; e < Ee; e++) t[e] = dl[e];
        int e = d, rank = 0;
#pragma unroll
        for (int j = 0; j < Ee; j++)
            rank += (t[j] > t[e]) || (t[j] == t[e] && j < e);
        g_sdg[bt * HE + h * Ee + e] = (rank < KK) ? 1.f : 0.f;
    }
}

// ---------------- kernel 3: causal flash attention (64x64 tiles) ------------
#define ATTN_SMEM ((4096 + 64*68 + 4096) * 4)

__global__ __launch_bounds__(256)
void attn_kernel()
{
    extern __shared__ float smx[];
    float* Qs = smx;                    // [64][64]  q tile (pre-scaled)
    float* KP = smx + 4096;             // [64][68]  K^T tile, then P tile
    float* Vs = smx + 4096 + 64 * 68;   // [64][64]  V tile

    const int qt = blockIdx.x;          // query tile 0..15
    const int bh = blockIdx.y;          // 0..15
    const int b = bh >> 3, h = bh & 7;
    const int tid = threadIdx.x;
    const int ty = tid >> 4, tx = tid & 15;

    const float* Qb = g_Q  + (size_t)b * Tt * HS + h * 64;
    const float* Kb = g_K  + (size_t)b * Tt * HS + h * 64;
    const float* Vb = g_Vm + (size_t)b * Tt * HS + h * 64;

    {   // load + pre-scale Q tile
        int r  = tid >> 2;
        int c0 = (tid & 3) * 16;
        const float* src = Qb + (size_t)(qt * 64 + r) * HS + c0;
#pragma unroll
        for (int u = 0; u < 4; u++) {
            float4 v = *(const float4*)(src + u * 4);
            v.x *= QSCALE; v.y *= QSCALE; v.z *= QSCALE; v.w *= QSCALE;
            *(float4*)(Qs + r * 64 + c0 + u * 4) = v;
        }
    }

    float m[4], l[4], o[4][4];
#pragma unroll
    for (int i = 0; i < 4; i++) {
        m[i] = -1e30f; l[i] = 0.f;
#pragma unroll
        for (int j = 0; j < 4; j++) o[i][j] = 0.f;
    }

    for (int kt = 0; kt <= qt; kt++) {
        __syncthreads();
        // load K tile transposed -> KP[d][j], V tile -> Vs[j][d]
#pragma unroll
        for (int cc = 0; cc < 4; cc++) {
            int idx = cc * 256 + tid;
            int j   = idx >> 4;
            int d4  = (idx & 15) << 2;
            const float* kp = Kb + (size_t)(kt * 64 + j) * HS + d4;
            float4 kv = *(const float4*)kp;
            KP[(d4 + 0) * 68 + j] = kv.x;
            KP[(d4 + 1) * 68 + j] = kv.y;
            KP[(d4 + 2) * 68 + j] = kv.z;
            KP[(d4 + 3) * 68 + j] = kv.w;
            const float* vp = Vb + (size_t)(kt * 64 + j) * HS + d4;
            *(float4*)(Vs + j * 64 + d4) = *(const float4*)vp;
        }
        __syncthreads();

        // S fragment = Q_tile @ K_tile^T
        float s[4][4];
#pragma unroll
        for (int i = 0; i < 4; i++)
#pragma unroll
            for (int j = 0; j < 4; j++) s[i][j] = 0.f;

#pragma unroll 16
        for (int kk = 0; kk < 64; kk++) {
            float4 bq = *(float4*)(KP + kk * 68 + tx * 4);
            float a0 = Qs[(ty * 4 + 0) * 64 + kk];
            float a1 = Qs[(ty * 4 + 1) * 64 + kk];
            float a2 = Qs[(ty * 4 + 2) * 64 + kk];
            float a3 = Qs[(ty * 4 + 3) * 64 + kk];
            s[0][0]=fmaf(a0,bq.x,s[0][0]); s[0][1]=fmaf(a0,bq.y,s[0][1]); s[0][2]=fmaf(a0,bq.z,s[0][2]); s[0][3]=fmaf(a0,bq.w,s[0][3]);
            s[1][0]=fmaf(a1,bq.x,s[1][0]); s[1][1]=fmaf(a1,bq.y,s[1][1]); s[1][2]=fmaf(a1,bq.z,s[1][2]); s[1][3]=fmaf(a1,bq.w,s[1][3]);
            s[2][0]=fmaf(a2,bq.x,s[2][0]); s[2][1]=fmaf(a2,bq.y,s[2][1]); s[2][2]=fmaf(a2,bq.z,s[2][2]); s[2][3]=fmaf(a2,bq.w,s[2][3]);
            s[3][0]=fmaf(a3,bq.x,s[3][0]); s[3][1]=fmaf(a3,bq.y,s[3][1]); s[3][2]=fmaf(a3,bq.z,s[3][2]); s[3][3]=fmaf(a3,bq.w,s[3][3]);
        }

        if (kt == qt) {   // causal mask on diagonal tile (matches where(mask,-1e9,s))
#pragma unroll
            for (int i = 0; i < 4; i++)
#pragma unroll
                for (int j = 0; j < 4; j++)
                    if (tx * 4 + j > ty * 4 + i) s[i][j] = -1e9f;
        }

        // online softmax (row stats across the 16 tx lanes)
#pragma unroll
        for (int i = 0; i < 4; i++) {
            float mx = fmaxf(fmaxf(s[i][0], s[i][1]), fmaxf(s[i][2], s[i][3]));
#pragma unroll
            for (int off = 1; off < 16; off <<= 1)
                mx = fmaxf(mx, __shfl_xor_sync(0xffffffffu, mx, off));
            float mnew = fmaxf(m[i], mx);
            float corr = __expf(m[i] - mnew);
            float rs = 0.f;
#pragma unroll
            for (int j = 0; j < 4; j++) { s[i][j] = __expf(s[i][j] - mnew); rs += s[i][j]; }
#pragma unroll
            for (int off = 1; off < 16; off <<= 1)
                rs += __shfl_xor_sync(0xffffffffu, rs, off);
            l[i] = l[i] * corr + rs;
            m[i] = mnew;
#pragma unroll
            for (int j = 0; j < 4; j++) o[i][j] *= corr;
        }

        __syncthreads();           // everyone done reading KP as K^T
#pragma unroll
        for (int i = 0; i < 4; i++)
            *(float4*)(KP + (ty * 4 + i) * 68 + tx * 4) =
                make_float4(s[i][0], s[i][1], s[i][2], s[i][3]);
        __syncthreads();

        // O += P @ V
#pragma unroll 16
        for (int c = 0; c < 64; c++) {
            float4 vv = *(float4*)(Vs + c * 64 + tx * 4);
            float p0 = KP[(ty * 4 + 0) * 68 + c];
            float p1 = KP[(ty * 4 + 1) * 68 + c];
            float p2 = KP[(ty * 4 + 2) * 68 + c];
            float p3 = KP[(ty * 4 + 3) * 68 + c];
            o[0][0]=fmaf(p0,vv.x,o[0][0]); o[0][1]=fmaf(p0,vv.y,o[0][1]); o[0][2]=fmaf(p0,vv.z,o[0][2]); o[0][3]=fmaf(p0,vv.w,o[0][3]);
            o[1][0]=fmaf(p1,vv.x,o[1][0]); o[1][1]=fmaf(p1,vv.y,o[1][1]); o[1][2]=fmaf(p1,vv.z,o[1][2]); o[1][3]=fmaf(p1,vv.w,o[1][3]);
            o[2][0]=fmaf(p2,vv.x,o[2][0]); o[2][1]=fmaf(p2,vv.y,o[2][1]); o[2][2]=fmaf(p2,vv.z,o[2][2]); o[2][3]=fmaf(p2,vv.w,o[2][3]);
            o[3][0]=fmaf(p3,vv.x,o[3][0]); o[3][1]=fmaf(p3,vv.y,o[3][1]); o[3][2]=fmaf(p3,vv.z,o[3][2]); o[3][3]=fmaf(p3,vv.w,o[3][3]);
        }
    }

#pragma unroll
    for (int i = 0; i < 4; i++) {
        float inv = 1.0f / l[i];
        int t = qt * 64 + ty * 4 + i;
        float4 r = make_float4(o[i][0]*inv, o[i][1]*inv, o[i][2]*inv, o[i][3]*inv);
        *(float4*)(g_O + ((size_t)b * Tt + t) * HS + h * 64 + tx * 4) = r;
    }
}

// ---------------- kernel 4: Wo[h,e,d,c] -> WoT[(h,e,c), d] ------------------
__global__ void wo_transpose(const float* __restrict__ Wo)
{
    __shared__ float tile[32][33];
    int he = blockIdx.z;
    int d0 = blockIdx.x * 32;
    int c0 = blockIdx.y * 32;
    int x = threadIdx.x, y = threadIdx.y;   // block (32,8)
    const float* src = Wo + (size_t)he * (DIMD * DHh);
#pragma unroll
    for (int yy = 0; yy < 32; yy += 8)
        tile[y + yy][x] = src[(size_t)(d0 + y + yy) * DHh + c0 + x];
    __syncthreads();
#pragma unroll
    for (int yy = 0; yy < 32; yy += 8)
        g_WoT[(size_t)(he * DHh + c0 + y + yy) * DIMD + d0 + x] = tile[x][y + yy];
}

// ---------------- kernel 5: A[bt][(h,e,c)] = sd * o --------------------------
__global__ __launch_bounds__(256)
void build_a()
{
    int gid = blockIdx.x * blockDim.x + threadIdx.x;
    if (gid >= BT * VN) return;
    int col = gid % VN;
    int bt  = gid / VN;
    int he  = col >> 6;
    int c   = col & 63;
    int h   = he / Ee;
    g_A[gid] = g_sdg[bt * HE + he] * g_O[(size_t)bt * HS + h * 64 + c];
}

// ---------------- kernel 6: out = A @ WoT ------------------------------------
__global__ __launch_bounds__(256)
void out_gemm(float* __restrict__ out)
{
    sgemm_body(g_A, g_WoT, out, DIMD, VN, blockIdx.x * 128, blockIdx.y * 128);
}

// ---------------- launch ------------------------------------------------------
extern "C" void kernel_launch(void* const* d_in, const int* in_sizes, int n_in,
                              void* d_out, int out_size)
{
    const float* x  = (const float*)d_in[0];
    const float* Wq = (const float*)d_in[1];
    const float* Wk = (const float*)d_in[2];
    const float* Wv = (const float*)d_in[3];
    const float* Ws = (const float*)d_in[4];
    const float* Wd = (const float*)d_in[5];
    const float* Wo = (const float*)d_in[6];
    float* out = (float*)d_out;

    cudaFuncSetAttribute(attn_kernel, cudaFuncAttributeMaxDynamicSharedMemorySize, ATTN_SMEM);

    qkv_gemm   <<<dim3(30, 16), 256>>>(x, Wq, Wk, Wv, Ws, Wd);
    route_mix  <<<(BT * Hh * 64) / 256, 256>>>();
    attn_kernel<<<dim3(16, 16), 256, ATTN_SMEM>>>();
    wo_transpose<<<dim3(32, 2, 40), dim3(32, 8)>>>(Wo);
    build_a    <<<(BT * VN) / 256, 256>>>();
    out_gemm   <<<dim3(8, 16), 256>>>(out);
}

// round 3
// speedup vs baseline: 1.6409x; 1.6409x over previous
#include <cuda_runtime.h>
#include <cuda_bf16.h>
#include <cstdint>

#define Tt   1024
#define DIMD 1024
#define Hh   8
#define Ee   5
#define KK   3
#define BT   2048
#define HS   512
#define HE   40
#define QSCALE 0.125f

#define N1 3840      // fused projection width (Q512|K512|V2560|Ss40|Sd40|pad48)
#define K1 3072      // 3*1024 split-K (hi,hi,lo x hi,lo,hi)
#define N2 1024
#define K2 7680      // 3*2560 split-K
#define V2 2560

// ---------------- scratch ----------------------------------------------------
__device__ float          g_C1 [BT * N1];
__device__ __nv_bfloat16  g_A1 [BT * K1];
__device__ __nv_bfloat16  g_B1 [N1 * K1];
__device__ __nv_bfloat16  g_A2 [(size_t)BT * K2];
__device__ __nv_bfloat16  g_B2 [(size_t)N2 * K2];
__device__ float          g_Vm [BT * HS];
__device__ float          g_O  [BT * HS];
__device__ float          g_sdg[BT * HE];

// ---------------- async-copy helpers -----------------------------------------
__device__ __forceinline__ uint32_t smem_u32(const void* p) {
    uint32_t a;
    asm("{ .reg .u64 t; cvta.to.shared.u64 t, %1; cvt.u32.u64 %0, t; }" : "=r"(a) : "l"(p));
    return a;
}
__device__ __forceinline__ void cpasync16(uint32_t dst, const void* src) {
    asm volatile("cp.async.cg.shared.global [%0], [%1], 16;\n" :: "r"(dst), "l"(src));
}
__device__ __forceinline__ void cp_commit() { asm volatile("cp.async.commit_group;\n"); }
template<int N> __device__ __forceinline__ void cp_wait() { asm volatile("cp.async.wait_group %0;\n" :: "n"(N)); }

__device__ __forceinline__ void mma16816(float* c, const uint32_t* a, const uint32_t* b) {
    asm volatile(
        "mma.sync.aligned.m16n8k16.row.col.f32.bf16.bf16.f32 "
        "{%0,%1,%2,%3}, {%4,%5,%6,%7}, {%8,%9}, {%0,%1,%2,%3};"
        : "+f"(c[0]), "+f"(c[1]), "+f"(c[2]), "+f"(c[3])
        : "r"(a[0]), "r"(a[1]), "r"(a[2]), "r"(a[3]), "r"(b[0]), "r"(b[1]));
}

// ---------------- bf16 mma.sync SGEMM: 128x128 tile, BK=32, 3 stages ---------
// A [Mtot, KTOT] row-major bf16, Bm [Ntot, KTOT] row-major bf16 (= W^T),
// C [Mtot, Ntot] fp32.  C = A @ Bm^T.
// smem per stage: As[128][40] + Bs[128][40] bf16 (pad 40 -> conflict-free LDS)
#define BKs   32
#define SSTR  40                     // padded row stride (bf16 elems)
#define STAGE_B (2 * 128 * SSTR * 2) // A+B bytes per stage = 20480
#define GEMM_SMEM (3 * STAGE_B)

template<int KTOT>
__device__ __forceinline__ void gemm_body(const __nv_bfloat16* __restrict__ A,
                                          const __nv_bfloat16* __restrict__ Bm,
                                          float* __restrict__ C, int Ntot)
{
    extern __shared__ char sm_raw[];
    const uint32_t sbase = smem_u32(sm_raw);
    constexpr int NSTEP = KTOT / BKs;

    const int tid  = threadIdx.x;
    const int wid  = tid >> 5;
    const int lane = tid & 31;
    const int g    = lane >> 2;        // group id 0..7
    const int tig  = lane & 3;         // thread-in-group
    const int wm   = wid & 1;          // 2 m-warps (64 rows each)
    const int wn   = wid >> 1;         // 4 n-warps (32 cols each)

    const int m0 = blockIdx.y * 128;
    const int n0 = blockIdx.x * 128;

    const char* Ab = (const char*)(A  + (size_t)m0 * KTOT);
    const char* Bb = (const char*)(Bm + (size_t)n0 * KTOT);

    // per-thread cp.async assignment: 4 chunks (2 for A, 2 for B)
    // chunk c of 512: row = c>>2, off = (c&3)*16 bytes within 64B k-slab
    const int c0r = (tid * 2) >> 2,       c0o = ((tid * 2) & 3) * 16;
    const int c1r = (tid * 2 + 1) >> 2,   c1o = ((tid * 2 + 1) & 3) * 16;

    auto issue_stage = [&](int kt, int slot) {
        uint32_t as = sbase + slot * STAGE_B;
        uint32_t bs = as + 128 * SSTR * 2;
        const char* ag = Ab + (size_t)kt * (BKs * 2);
        const char* bg = Bb + (size_t)kt * (BKs * 2);
        cpasync16(as + c0r * (SSTR*2) + c0o, ag + (size_t)c0r * (KTOT*2) + c0o);
        cpasync16(as + c1r * (SSTR*2) + c1o, ag + (size_t)c1r * (KTOT*2) + c1o);
        cpasync16(bs + c0r * (SSTR*2) + c0o, bg + (size_t)c0r * (KTOT*2) + c0o);
        cpasync16(bs + c1r * (SSTR*2) + c1o, bg + (size_t)c1r * (KTOT*2) + c1o);
    };

    float acc[4][4][4];
#pragma unroll
    for (int i = 0; i < 4; i++)
#pragma unroll
        for (int j = 0; j < 4; j++)
#pragma unroll
            for (int q = 0; q < 4; q++) acc[i][j][q] = 0.f;

    issue_stage(0, 0); cp_commit();
    issue_stage(1, 1); cp_commit();

    for (int kt = 0; kt < NSTEP; kt++) {
        if (kt + 2 < NSTEP) issue_stage(kt + 2, (kt + 2) % 3);
        cp_commit();
        cp_wait<2>();
        __syncthreads();

        uint32_t as = sbase + (kt % 3) * STAGE_B;
        uint32_t bs = as + 128 * SSTR * 2;

#pragma unroll
        for (int ks = 0; ks < 2; ks++) {          // two k16 steps in BK=32
            uint32_t afr[4][4];
#pragma unroll
            for (int ti = 0; ti < 4; ti++) {
                uint32_t r0 = as + (wm * 64 + ti * 16 + g) * (SSTR*2) + (ks * 16 + tig * 2) * 2;
                uint32_t r1 = r0 + 8 * (SSTR*2);
                asm volatile("ld.shared.b32 %0, [%1];" : "=r"(afr[ti][0]) : "r"(r0));
                asm volatile("ld.shared.b32 %0, [%1];" : "=r"(afr[ti][1]) : "r"(r1));
                asm volatile("ld.shared.b32 %0, [%1];" : "=r"(afr[ti][2]) : "r"(r0 + 16));
                asm volatile("ld.shared.b32 %0, [%1];" : "=r"(afr[ti][3]) : "r"(r1 + 16));
            }
            uint32_t bfr[4][2];
#pragma unroll
            for (int tj = 0; tj < 4; tj++) {
                uint32_t r0 = bs + (wn * 32 + tj * 8 + g) * (SSTR*2) + (ks * 16 + tig * 2) * 2;
                asm volatile("ld.shared.b32 %0, [%1];" : "=r"(bfr[tj][0]) : "r"(r0));
                asm volatile("ld.shared.b32 %0, [%1];" : "=r"(bfr[tj][1]) : "r"(r0 + 16));
            }
#pragma unroll
            for (int ti = 0; ti < 4; ti++)
#pragma unroll
                for (int tj = 0; tj < 4; tj++)
                    mma16816(acc[ti][tj], afr[ti], bfr[tj]);
        }
        __syncthreads();
    }

    // epilogue
#pragma unroll
    for (int ti = 0; ti < 4; ti++) {
        int r0 = m0 + wm * 64 + ti * 16 + g;
#pragma unroll
        for (int tj = 0; tj < 4; tj++) {
            int cc = n0 + wn * 32 + tj * 8 + tig * 2;
            *(float2*)(C + (size_t)r0 * Ntot + cc)       = make_float2(acc[ti][tj][0], acc[ti][tj][1]);
            *(float2*)(C + (size_t)(r0 + 8) * Ntot + cc) = make_float2(acc[ti][tj][2], acc[ti][tj][3]);
        }
    }
}

__global__ __launch_bounds__(256)
void gemm1() { gemm_body<K1>(g_A1, g_B1, g_C1, N1); }

__global__ __launch_bounds__(256)
void gemm2(float* __restrict__ out) { gemm_body<K2>(g_A2, g_B2, out, N2); }

// ---------------- prep kernels ----------------------------------------------
__device__ __forceinline__ void split_bf16(float v, __nv_bfloat16& hi, __nv_bfloat16& lo) {
    hi = __float2bfloat16(v);
    lo = __float2bfloat16(v - __bfloat162float(hi));
}

__global__ __launch_bounds__(256) void prep_a1(const float* __restrict__ x) {
    int gid = blockIdx.x * 256 + threadIdx.x;          // BT*1024
    int m = gid >> 10, k = gid & 1023;
    __nv_bfloat16 hi, lo; split_bf16(x[gid], hi, lo);
    __nv_bfloat16* a = g_A1 + (size_t)m * K1 + k;
    a[0] = hi; a[1024] = hi; a[2048] = lo;
}

__global__ void prep_b1(const float* __restrict__ Wq, const float* __restrict__ Wk,
                        const float* __restrict__ Wv, const float* __restrict__ Ws,
                        const float* __restrict__ Wd)
{
    __shared__ float tile[32][33];
    int k0 = blockIdx.x * 32;
    int n0 = blockIdx.y * 32;
    int tx = threadIdx.x, ty = threadIdx.y;   // (32,8)
#pragma unroll
    for (int yy = 0; yy < 32; yy += 8) {
        int k = k0 + ty + yy, n = n0 + tx;
        float w;
        if      (n < 512)  w = Wq[(size_t)k * 512  + n];
        else if (n < 1024) w = Wk[(size_t)k * 512  + n - 512];
        else if (n < 3584) w = Wv[(size_t)k * 2560 + n - 1024];
        else if (n < 3624) w = Ws[(size_t)k * 40   + n - 3584];
        else if (n < 3664) w = Wd[(size_t)k * 40   + n - 3624];
        else               w = 0.f;
        tile[ty + yy][tx] = w;
    }
    __syncthreads();
#pragma unroll
    for (int yy = 0; yy < 32; yy += 8) {
        int n = n0 + ty + yy, k = k0 + tx;
        __nv_bfloat16 hi, lo; split_bf16(tile[tx][ty + yy], hi, lo);
        __nv_bfloat16* b = g_B1 + (size_t)n * K1 + k;
        b[0] = hi; b[1024] = lo; b[2048] = hi;
    }
}

__global__ __launch_bounds__(256) void prep_b2(const float* __restrict__ Wo) {
    int gid = blockIdx.x * 256 + threadIdx.x;          // 40*1024*64
    int he = gid >> 16;
    int d  = (gid >> 6) & 1023;
    int c  = gid & 63;
    __nv_bfloat16 hi, lo; split_bf16(Wo[gid], hi, lo);
    __nv_bfloat16* b = g_B2 + (size_t)d * K2 + he * 64 + c;
    b[0] = hi; b[V2] = lo; b[2 * V2] = hi;
}

// ---------------- routing gates + expert V mix (from g_C1) ------------------
__global__ __launch_bounds__(256) void route_mix() {
    int gid = blockIdx.x * 256 + threadIdx.x;          // BT*H*64
    int d   = gid & 63;
    int bth = gid >> 6;
    int h   = bth & 7;
    int bt  = bth >> 3;

    const float* row = g_C1 + (size_t)bt * N1;
    const float* sl = row + 3584 + h * Ee;
    float s[Ee];
#pragma unroll
    for (int e = 0; e < Ee; e++) s[e] = sl[e];

    float acc = 0.f;
#pragma unroll
    for (int e = 0; e < Ee; e++) {
        int rank = 0;
#pragma unroll
        for (int j = 0; j < Ee; j++)
            rank += (s[j] > s[e]) || (s[j] == s[e] && j < e);
        float gate = (rank < KK) ? 1.0f / (1.0f + expf(-s[e])) : 0.f;
        acc = fmaf(gate, row[1024 + (h * Ee + e) * 64 + d], acc);
    }
    g_Vm[(size_t)bt * HS + h * 64 + d] = acc;

    if (d < Ee) {
        const float* dl = row + 3624 + h * Ee;
        float t[Ee];
#pragma unroll
        for (int e = 0; e < Ee; e++) t[e] = dl[e];
        int e = d, rank = 0;
#pragma unroll
        for (int j = 0; j < Ee; j++)
            rank += (t[j] > t[e]) || (t[j] == t[e] && j < e);
        g_sdg[bt * HE + h * Ee + e] = (rank < KK) ? 1.f : 0.f;
    }
}

// ---------------- causal flash attention (fp32, 64x64 tiles) ----------------
#define ATTN_SMEM ((4096 + 64*68 + 4096) * 4)

__global__ __launch_bounds__(256) void attn_kernel() {
    extern __shared__ float smx[];
    float* Qs = smx;
    float* KP = smx + 4096;
    float* Vs = smx + 4096 + 64 * 68;

    const int qt = blockIdx.x;
    const int bh = blockIdx.y;
    const int b = bh >> 3, h = bh & 7;
    const int tid = threadIdx.x;
    const int ty = tid >> 4, tx = tid & 15;

    const float* Qb = g_C1 + (size_t)b * Tt * N1 + h * 64;
    const float* Kb = g_C1 + (size_t)b * Tt * N1 + 512 + h * 64;
    const float* Vb = g_Vm + (size_t)b * Tt * HS + h * 64;

    {
        int r  = tid >> 2;
        int c0 = (tid & 3) * 16;
        const float* src = Qb + (size_t)(qt * 64 + r) * N1 + c0;
#pragma unroll
        for (int u = 0; u < 4; u++) {
            float4 v = *(const float4*)(src + u * 4);
            v.x *= QSCALE; v.y *= QSCALE; v.z *= QSCALE; v.w *= QSCALE;
            *(float4*)(Qs + r * 64 + c0 + u * 4) = v;
        }
    }

    float m[4], l[4], o[4][4];
#pragma unroll
    for (int i = 0; i < 4; i++) {
        m[i] = -1e30f; l[i] = 0.f;
#pragma unroll
        for (int j = 0; j < 4; j++) o[i][j] = 0.f;
    }

    for (int kt = 0; kt <= qt; kt++) {
        __syncthreads();
#pragma unroll
        for (int cc = 0; cc < 4; cc++) {
            int idx = cc * 256 + tid;
            int j   = idx >> 4;
            int d4  = (idx & 15) << 2;
            float4 kv = *(const float4*)(Kb + (size_t)(kt * 64 + j) * N1 + d4);
            KP[(d4 + 0) * 68 + j] = kv.x;
            KP[(d4 + 1) * 68 + j] = kv.y;
            KP[(d4 + 2) * 68 + j] = kv.z;
            KP[(d4 + 3) * 68 + j] = kv.w;
            *(float4*)(Vs + j * 64 + d4) = *(const float4*)(Vb + (size_t)(kt * 64 + j) * HS + d4);
        }
        __syncthreads();

        float s[4][4];
#pragma unroll
        for (int i = 0; i < 4; i++)
#pragma unroll
            for (int j = 0; j < 4; j++) s[i][j] = 0.f;

#pragma unroll 16
        for (int kk = 0; kk < 64; kk++) {
            float4 bq = *(float4*)(KP + kk * 68 + tx * 4);
            float a0 = Qs[(ty * 4 + 0) * 64 + kk];
            float a1 = Qs[(ty * 4 + 1) * 64 + kk];
            float a2 = Qs[(ty * 4 + 2) * 64 + kk];
            float a3 = Qs[(ty * 4 + 3) * 64 + kk];
            s[0][0]=fmaf(a0,bq.x,s[0][0]); s[0][1]=fmaf(a0,bq.y,s[0][1]); s[0][2]=fmaf(a0,bq.z,s[0][2]); s[0][3]=fmaf(a0,bq.w,s[0][3]);
            s[1][0]=fmaf(a1,bq.x,s[1][0]); s[1][1]=fmaf(a1,bq.y,s[1][1]); s[1][2]=fmaf(a1,bq.z,s[1][2]); s[1][3]=fmaf(a1,bq.w,s[1][3]);
            s[2][0]=fmaf(a2,bq.x,s[2][0]); s[2][1]=fmaf(a2,bq.y,s[2][1]); s[2][2]=fmaf(a2,bq.z,s[2][2]); s[2][3]=fmaf(a2,bq.w,s[2][3]);
            s[3][0]=fmaf(a3,bq.x,s[3][0]); s[3][1]=fmaf(a3,bq.y,s[3][1]); s[3][2]=fmaf(a3,bq.z,s[3][2]); s[3][3]=fmaf(a3,bq.w,s[3][3]);
        }

        if (kt == qt) {
#pragma unroll
            for (int i = 0; i < 4; i++)
#pragma unroll
                for (int j = 0; j < 4; j++)
                    if (tx * 4 + j > ty * 4 + i) s[i][j] = -1e9f;
        }

#pragma unroll
        for (int i = 0; i < 4; i++) {
            float mx = fmaxf(fmaxf(s[i][0], s[i][1]), fmaxf(s[i][2], s[i][3]));
#pragma unroll
            for (int off = 1; off < 16; off <<= 1)
                mx = fmaxf(mx, __shfl_xor_sync(0xffffffffu, mx, off));
            float mnew = fmaxf(m[i], mx);
            float corr = __expf(m[i] - mnew);
            float rs = 0.f;
#pragma unroll
            for (int j = 0; j < 4; j++) { s[i][j] = __expf(s[i][j] - mnew); rs += s[i][j]; }
#pragma unroll
            for (int off = 1; off < 16; off <<= 1)
                rs += __shfl_xor_sync(0xffffffffu, rs, off);
            l[i] = l[i] * corr + rs;
            m[i] = mnew;
#pragma unroll
            for (int j = 0; j < 4; j++) o[i][j] *= corr;
        }

        __syncthreads();
#pragma unroll
        for (int i = 0; i < 4; i++)
            *(float4*)(KP + (ty * 4 + i) * 68 + tx * 4) =
                make_float4(s[i][0], s[i][1], s[i][2], s[i][3]);
        __syncthreads();

#pragma unroll 16
        for (int c = 0; c < 64; c++) {
            float4 vv = *(float4*)(Vs + c * 64 + tx * 4);
            float p0 = KP[(ty * 4 + 0) * 68 + c];
            float p1 = KP[(ty * 4 + 1) * 68 + c];
            float p2 = KP[(ty * 4 + 2) * 68 + c];
            float p3 = KP[(ty * 4 + 3) * 68 + c];
            o[0][0]=fmaf(p0,vv.x,o[0][0]); o[0][1]=fmaf(p0,vv.y,o[0][1]); o[0][2]=fmaf(p0,vv.z,o[0][2]); o[0][3]=fmaf(p0,vv.w,o[0][3]);
            o[1][0]=fmaf(p1,vv.x,o[1][0]); o[1][1]=fmaf(p1,vv.y,o[1][1]); o[1][2]=fmaf(p1,vv.z,o[1][2]); o[1][3]=fmaf(p1,vv.w,o[1][3]);
            o[2][0]=fmaf(p2,vv.x,o[2][0]); o[2][1]=fmaf(p2,vv.y,o[2][1]); o[2][2]=fmaf(p2,vv.z,o[2][2]); o[2][3]=fmaf(p2,vv.w,o[2][3]);
            o[3][0]=fmaf(p3,vv.x,o[3][0]); o[3][1]=fmaf(p3,vv.y,o[3][1]); o[3][2]=fmaf(p3,vv.z,o[3][2]); o[3][3]=fmaf(p3,vv.w,o[3][3]);
        }
    }

#pragma unroll
    for (int i = 0; i < 4; i++) {
        float inv = 1.0f / l[i];
        int t = qt * 64 + ty * 4 + i;
        *(float4*)(g_O + ((size_t)b * Tt + t) * HS + h * 64 + tx * 4) =
            make_float4(o[i][0]*inv, o[i][1]*inv, o[i][2]*inv, o[i][3]*inv);
    }
}

// ---------------- A2 = split(sd * o) -----------------------------------------
__global__ __launch_bounds__(256) void build_a2() {
    int gid = blockIdx.x * 256 + threadIdx.x;          // BT*2560
    int col = gid % V2;
    int bt  = gid / V2;
    int he  = col >> 6;
    int c   = col & 63;
    int h   = he / Ee;
    float a = g_sdg[bt * HE + he] * g_O[(size_t)bt * HS + h * 64 + c];
    __nv_bfloat16 hi, lo; split_bf16(a, hi, lo);
    __nv_bfloat16* p = g_A2 + (size_t)bt * K2 + col;
    p[0] = hi; p[V2] = hi; p[2 * V2] = lo;
}

// ---------------- launch ------------------------------------------------------
extern "C" void kernel_launch(void* const* d_in, const int* in_sizes, int n_in,
                              void* d_out, int out_size)
{
    const float* x  = (const float*)d_in[0];
    const float* Wq = (const float*)d_in[1];
    const float* Wk = (const float*)d_in[2];
    const float* Wv = (const float*)d_in[3];
    const float* Ws = (const float*)d_in[4];
    const float* Wd = (const float*)d_in[5];
    const float* Wo = (const float*)d_in[6];
    float* out = (float*)d_out;

    cudaFuncSetAttribute(attn_kernel, cudaFuncAttributeMaxDynamicSharedMemorySize, ATTN_SMEM);
    cudaFuncSetAttribute(gemm1, cudaFuncAttributeMaxDynamicSharedMemorySize, GEMM_SMEM);
    cudaFuncSetAttribute(gemm2, cudaFuncAttributeMaxDynamicSharedMemorySize, GEMM_SMEM);

    prep_a1    <<<BT * DIMD / 256, 256>>>(x);
    prep_b1    <<<dim3(32, 120), dim3(32, 8)>>>(Wq, Wk, Wv, Ws, Wd);
    gemm1      <<<dim3(N1 / 128, BT / 128), 256, GEMM_SMEM>>>();
    route_mix  <<<BT * Hh * 64 / 256, 256>>>();
    attn_kernel<<<dim3(16, 16), 256, ATTN_SMEM>>>();
    prep_b2    <<<HE * DIMD * 64 / 256, 256>>>(Wo);
    build_a2   <<<BT * V2 / 256, 256>>>();
    gemm2      <<<dim3(N2 / 128, BT / 128), 256, GEMM_SMEM>>>(out);
}

// round 4
// speedup vs baseline: 1.8918x; 1.1529x over previous
#include <cuda_runtime.h>
#include <cuda_bf16.h>
#include <cstdint>

#define Tt   1024
#define DIMD 1024
#define Hh   8
#define Ee   5
#define KK   3
#define BT   2048
#define HS   512
#define HE   40
#define QSCALE 0.125f

#define N1 3840      // fused projection width (Q512|K512|V2560|Ss40|Sd40|pad48)
#define K1 3072      // 3*1024 split-K (hi,hi,lo x hi,lo,hi)
#define N2 1024
#define K2 7680      // 3*2560 split-K
#define V2 2560

// ---------------- scratch ----------------------------------------------------
__device__ float          g_C1 [BT * N1];
__device__ __nv_bfloat16  g_A1 [BT * K1];
__device__ __nv_bfloat16  g_B1 [N1 * K1];
__device__ __nv_bfloat16  g_A2 [(size_t)BT * K2];
__device__ __nv_bfloat16  g_B2 [(size_t)N2 * K2];
__device__ float          g_Vm [BT * HS];
__device__ float          g_O  [BT * HS];
__device__ float          g_sdg[BT * HE];
// attention operands, packed bf16x2 pairs
__device__ uint32_t g_Qh[16 * 1024 * 32];   // [bh][t][dhpair]
__device__ uint32_t g_Ql[16 * 1024 * 32];
__device__ uint32_t g_Kh[16 * 32 * 1024];   // [bh][dhpair][t]
__device__ uint32_t g_Kl[16 * 32 * 1024];
__device__ uint32_t g_Vh[16 * 512 * 64];    // [bh][keypair][d]
__device__ uint32_t g_Vl[16 * 512 * 64];

// ---------------- helpers -----------------------------------------------------
__device__ __forceinline__ uint32_t smem_u32(const void* p) {
    uint32_t a;
    asm("{ .reg .u64 t; cvta.to.shared.u64 t, %1; cvt.u32.u64 %0, t; }" : "=r"(a) : "l"(p));
    return a;
}
__device__ __forceinline__ void cpasync16(uint32_t dst, const void* src) {
    asm volatile("cp.async.cg.shared.global [%0], [%1], 16;\n" :: "r"(dst), "l"(src));
}
__device__ __forceinline__ void cp_commit() { asm volatile("cp.async.commit_group;\n"); }
template<int N> __device__ __forceinline__ void cp_wait() { asm volatile("cp.async.wait_group %0;\n" :: "n"(N)); }

__device__ __forceinline__ void mma16816(float* c, const uint32_t* a, const uint32_t* b) {
    asm volatile(
        "mma.sync.aligned.m16n8k16.row.col.f32.bf16.bf16.f32 "
        "{%0,%1,%2,%3}, {%4,%5,%6,%7}, {%8,%9}, {%0,%1,%2,%3};"
        : "+f"(c[0]), "+f"(c[1]), "+f"(c[2]), "+f"(c[3])
        : "r"(a[0]), "r"(a[1]), "r"(a[2]), "r"(a[3]), "r"(b[0]), "r"(b[1]));
}
// pack two fp32 -> bf16x2 (lo = first arg)
__device__ __forceinline__ uint32_t packbf(float lo, float hi) {
    uint32_t r;
    asm("cvt.rn.bf16x2.f32 %0, %1, %2;" : "=r"(r) : "f"(hi), "f"(lo));
    return r;
}
// residual pair: (lo - bf16(lo), hi - bf16(hi)) given the rounded pair p
__device__ __forceinline__ uint32_t packres(uint32_t p, float lo, float hi) {
    float plo = __uint_as_float(p << 16);
    float phi = __uint_as_float(p & 0xffff0000u);
    return packbf(lo - plo, hi - phi);
}

// ---------------- bf16 mma.sync SGEMM: 128x128 tile, BK=32, 3 stages ---------
#define BKs   32
#define SSTR  40
#define STAGE_B (2 * 128 * SSTR * 2)
#define GEMM_SMEM (3 * STAGE_B)

template<int KTOT>
__device__ __forceinline__ void gemm_body(const __nv_bfloat16* __restrict__ A,
                                          const __nv_bfloat16* __restrict__ Bm,
                                          float* __restrict__ C, int Ntot)
{
    extern __shared__ char sm_raw[];
    const uint32_t sbase = smem_u32(sm_raw);
    constexpr int NSTEP = KTOT / BKs;

    const int tid  = threadIdx.x;
    const int wid  = tid >> 5;
    const int lane = tid & 31;
    const int g    = lane >> 2;
    const int tig  = lane & 3;
    const int wm   = wid & 1;
    const int wn   = wid >> 1;

    const int m0 = blockIdx.y * 128;
    const int n0 = blockIdx.x * 128;

    const char* Ab = (const char*)(A  + (size_t)m0 * KTOT);
    const char* Bb = (const char*)(Bm + (size_t)n0 * KTOT);

    const int c0r = (tid * 2) >> 2,       c0o = ((tid * 2) & 3) * 16;
    const int c1r = (tid * 2 + 1) >> 2,   c1o = ((tid * 2 + 1) & 3) * 16;

    auto issue_stage = [&](int kt, int slot) {
        uint32_t as = sbase + slot * STAGE_B;
        uint32_t bs = as + 128 * SSTR * 2;
        const char* ag = Ab + (size_t)kt * (BKs * 2);
        const char* bg = Bb + (size_t)kt * (BKs * 2);
        cpasync16(as + c0r * (SSTR*2) + c0o, ag + (size_t)c0r * (KTOT*2) + c0o);
        cpasync16(as + c1r * (SSTR*2) + c1o, ag + (size_t)c1r * (KTOT*2) + c1o);
        cpasync16(bs + c0r * (SSTR*2) + c0o, bg + (size_t)c0r * (KTOT*2) + c0o);
        cpasync16(bs + c1r * (SSTR*2) + c1o, bg + (size_t)c1r * (KTOT*2) + c1o);
    };

    float acc[4][4][4];
#pragma unroll
    for (int i = 0; i < 4; i++)
#pragma unroll
        for (int j = 0; j < 4; j++)
#pragma unroll
            for (int q = 0; q < 4; q++) acc[i][j][q] = 0.f;

    issue_stage(0, 0); cp_commit();
    issue_stage(1, 1); cp_commit();

    for (int kt = 0; kt < NSTEP; kt++) {
        if (kt + 2 < NSTEP) issue_stage(kt + 2, (kt + 2) % 3);
        cp_commit();
        cp_wait<2>();
        __syncthreads();

        uint32_t as = sbase + (kt % 3) * STAGE_B;
        uint32_t bs = as + 128 * SSTR * 2;

#pragma unroll
        for (int ks = 0; ks < 2; ks++) {
            uint32_t afr[4][4];
#pragma unroll
            for (int ti = 0; ti < 4; ti++) {
                uint32_t r0 = as + (wm * 64 + ti * 16 + g) * (SSTR*2) + (ks * 16 + tig * 2) * 2;
                uint32_t r1 = r0 + 8 * (SSTR*2);
                asm volatile("ld.shared.b32 %0, [%1];" : "=r"(afr[ti][0]) : "r"(r0));
                asm volatile("ld.shared.b32 %0, [%1];" : "=r"(afr[ti][1]) : "r"(r1));
                asm volatile("ld.shared.b32 %0, [%1];" : "=r"(afr[ti][2]) : "r"(r0 + 16));
                asm volatile("ld.shared.b32 %0, [%1];" : "=r"(afr[ti][3]) : "r"(r1 + 16));
            }
            uint32_t bfr[4][2];
#pragma unroll
            for (int tj = 0; tj < 4; tj++) {
                uint32_t r0 = bs + (wn * 32 + tj * 8 + g) * (SSTR*2) + (ks * 16 + tig * 2) * 2;
                asm volatile("ld.shared.b32 %0, [%1];" : "=r"(bfr[tj][0]) : "r"(r0));
                asm volatile("ld.shared.b32 %0, [%1];" : "=r"(bfr[tj][1]) : "r"(r0 + 16));
            }
#pragma unroll
            for (int ti = 0; ti < 4; ti++)
#pragma unroll
                for (int tj = 0; tj < 4; tj++)
                    mma16816(acc[ti][tj], afr[ti], bfr[tj]);
        }
        __syncthreads();
    }

#pragma unroll
    for (int ti = 0; ti < 4; ti++) {
        int r0 = m0 + wm * 64 + ti * 16 + g;
#pragma unroll
        for (int tj = 0; tj < 4; tj++) {
            int cc = n0 + wn * 32 + tj * 8 + tig * 2;
            *(float2*)(C + (size_t)r0 * Ntot + cc)       = make_float2(acc[ti][tj][0], acc[ti][tj][1]);
            *(float2*)(C + (size_t)(r0 + 8) * Ntot + cc) = make_float2(acc[ti][tj][2], acc[ti][tj][3]);
        }
    }
}

__global__ __launch_bounds__(256)
void gemm1() { gemm_body<K1>(g_A1, g_B1, g_C1, N1); }

__global__ __launch_bounds__(256)
void gemm2(float* __restrict__ out) { gemm_body<K2>(g_A2, g_B2, out, N2); }

// ---------------- prep kernels ----------------------------------------------
__device__ __forceinline__ void split_bf16(float v, __nv_bfloat16& hi, __nv_bfloat16& lo) {
    hi = __float2bfloat16(v);
    lo = __float2bfloat16(v - __bfloat162float(hi));
}

__global__ __launch_bounds__(256) void prep_a1(const float* __restrict__ x) {
    int gid = blockIdx.x * 256 + threadIdx.x;
    int m = gid >> 10, k = gid & 1023;
    __nv_bfloat16 hi, lo; split_bf16(x[gid], hi, lo);
    __nv_bfloat16* a = g_A1 + (size_t)m * K1 + k;
    a[0] = hi; a[1024] = hi; a[2048] = lo;
}

__global__ void prep_b1(const float* __restrict__ Wq, const float* __restrict__ Wk,
                        const float* __restrict__ Wv, const float* __restrict__ Ws,
                        const float* __restrict__ Wd)
{
    __shared__ float tile[32][33];
    int k0 = blockIdx.x * 32;
    int n0 = blockIdx.y * 32;
    int tx = threadIdx.x, ty = threadIdx.y;
#pragma unroll
    for (int yy = 0; yy < 32; yy += 8) {
        int k = k0 + ty + yy, n = n0 + tx;
        float w;
        if      (n < 512)  w = Wq[(size_t)k * 512  + n];
        else if (n < 1024) w = Wk[(size_t)k * 512  + n - 512];
        else if (n < 3584) w = Wv[(size_t)k * 2560 + n - 1024];
        else if (n < 3624) w = Ws[(size_t)k * 40   + n - 3584];
        else if (n < 3664) w = Wd[(size_t)k * 40   + n - 3624];
        else               w = 0.f;
        tile[ty + yy][tx] = w;
    }
    __syncthreads();
#pragma unroll
    for (int yy = 0; yy < 32; yy += 8) {
        int n = n0 + ty + yy, k = k0 + tx;
        __nv_bfloat16 hi, lo; split_bf16(tile[tx][ty + yy], hi, lo);
        __nv_bfloat16* b = g_B1 + (size_t)n * K1 + k;
        b[0] = hi; b[1024] = lo; b[2048] = hi;
    }
}

__global__ __launch_bounds__(256) void prep_b2(const float* __restrict__ Wo) {
    int gid = blockIdx.x * 256 + threadIdx.x;
    int he = gid >> 16;
    int d  = (gid >> 6) & 1023;
    int c  = gid & 63;
    __nv_bfloat16 hi, lo; split_bf16(Wo[gid], hi, lo);
    __nv_bfloat16* b = g_B2 + (size_t)d * K2 + he * 64 + c;
    b[0] = hi; b[V2] = lo; b[2 * V2] = hi;
}

// ---------------- routing gates + expert V mix -------------------------------
__global__ __launch_bounds__(256) void route_mix() {
    int gid = blockIdx.x * 256 + threadIdx.x;
    int d   = gid & 63;
    int bth = gid >> 6;
    int h   = bth & 7;
    int bt  = bth >> 3;

    const float* row = g_C1 + (size_t)bt * N1;
    const float* sl = row + 3584 + h * Ee;
    float s[Ee];
#pragma unroll
    for (int e = 0; e < Ee; e++) s[e] = sl[e];

    float acc = 0.f;
#pragma unroll
    for (int e = 0; e < Ee; e++) {
        int rank = 0;
#pragma unroll
        for (int j = 0; j < Ee; j++)
            rank += (s[j] > s[e]) || (s[j] == s[e] && j < e);
        float gate = (rank < KK) ? 1.0f / (1.0f + expf(-s[e])) : 0.f;
        acc = fmaf(gate, row[1024 + (h * Ee + e) * 64 + d], acc);
    }
    g_Vm[(size_t)bt * HS + h * 64 + d] = acc;

    if (d < Ee) {
        const float* dl = row + 3624 + h * Ee;
        float t[Ee];
#pragma unroll
        for (int e = 0; e < Ee; e++) t[e] = dl[e];
        int e = d, rank = 0;
#pragma unroll
        for (int j = 0; j < Ee; j++)
            rank += (t[j] > t[e]) || (t[j] == t[e] && j < e);
        g_sdg[bt * HE + h * Ee + e] = (rank < KK) ? 1.f : 0.f;
    }
}

// ---------------- attention operand prep --------------------------------------
__global__ __launch_bounds__(256) void prep_qk() {
    int gid = blockIdx.x * 256 + threadIdx.x;   // 16*1024*32
    int p  = gid & 31;
    int t  = (gid >> 5) & 1023;
    int bh = gid >> 15;
    int b = bh >> 3, h = bh & 7;
    const float* row = g_C1 + (size_t)(b * 1024 + t) * N1;

    float q0 = row[h * 64 + 2 * p]     * QSCALE;
    float q1 = row[h * 64 + 2 * p + 1] * QSCALE;
    uint32_t qh = packbf(q0, q1);
    g_Qh[gid] = qh;
    g_Ql[gid] = packres(qh, q0, q1);

    float k0 = row[512 + h * 64 + 2 * p];
    float k1 = row[512 + h * 64 + 2 * p + 1];
    uint32_t kh = packbf(k0, k1);
    int kidx = (bh * 32 + p) * 1024 + t;
    g_Kh[kidx] = kh;
    g_Kl[kidx] = packres(kh, k0, k1);
}

__global__ __launch_bounds__(256) void prep_v() {
    int gid = blockIdx.x * 256 + threadIdx.x;   // 16*512*64
    int d  = gid & 63;
    int kp = (gid >> 6) & 511;
    int bh = gid >> 15;
    int b = bh >> 3, h = bh & 7;
    float v0 = g_Vm[(size_t)(b * 1024 + 2 * kp)     * HS + h * 64 + d];
    float v1 = g_Vm[(size_t)(b * 1024 + 2 * kp + 1) * HS + h * 64 + d];
    uint32_t vh = packbf(v0, v1);
    g_Vh[gid] = vh;
    g_Vl[gid] = packres(vh, v0, v1);
}

// ---------------- tensor-core causal flash attention -------------------------
// 64 q-rows / CTA (4 warps x m16), 64-key tiles, 2-stage cp.async pipeline.
// smem (u32): Qh[64][36], Ql[64][36], then 2 stages of {Kh,Kl,Vh,Vl}[32][72].
#define TSTR   72
#define TILE_U (32 * TSTR)            // 2304 u32 per array tile
#define STG_U  (4 * TILE_U)           // 9216 u32 per stage
#define QS_U   (64 * 36)              // 2304 u32 per Q array
#define SB_U   (2 * QS_U)             // stages start (4608)
#define ATTN_SMEM ((SB_U + 2 * STG_U) * 4)   // 92160 B

__global__ __launch_bounds__(128) void attn_tc() {
    extern __shared__ uint32_t sm[];
    const int qt  = blockIdx.x;     // 0..15
    const int bh  = blockIdx.y;     // 0..15
    const int b   = bh >> 3, h = bh & 7;
    const int tid = threadIdx.x;
    const int w   = tid >> 5;
    const int lane = tid & 31;
    const int g   = lane >> 2;
    const int tig = lane & 3;
    const uint32_t sbase_b = smem_u32(sm);

    // ---- load Q tile (pairs) into smem ----
    {
        const uint32_t* qhsrc = g_Qh + ((size_t)(bh << 10) + qt * 64) * 32;
        const uint32_t* qlsrc = g_Ql + ((size_t)(bh << 10) + qt * 64) * 32;
#pragma unroll
        for (int j = 0; j < 4; j++) {
            int idx = tid + j * 128;          // 0..511
            int row = idx >> 3, po = (idx & 7) * 4;
            *(uint4*)&sm[row * 36 + po]        = *(const uint4*)(qhsrc + row * 32 + po);
            *(uint4*)&sm[QS_U + row * 36 + po] = *(const uint4*)(qlsrc + row * 32 + po);
        }
    }

    // ---- issue stage 0 ----
    auto issue = [&](int kt, int s) {
#pragma unroll
        for (int i = 0; i < 16; i++) {
            int a = i >> 2;
            int r = (i & 3) * 8 + (tid >> 4);
            int p = tid & 15;
            uint32_t dst = sbase_b + (SB_U + s * STG_U + a * TILE_U + r * TSTR) * 4 + p * 16;
            const uint32_t* srcb;
            if      (a == 0) srcb = g_Kh + (size_t)(bh * 32 + r) * 1024 + kt * 64;
            else if (a == 1) srcb = g_Kl + (size_t)(bh * 32 + r) * 1024 + kt * 64;
            else if (a == 2) srcb = g_Vh + (size_t)(bh * 512 + kt * 32 + r) * 64;
            else             srcb = g_Vl + (size_t)(bh * 512 + kt * 32 + r) * 64;
            cpasync16(dst, (const char*)srcb + p * 16);
        }
    };
    issue(0, 0); cp_commit();
    __syncthreads();   // Q smem visible

    // ---- Q fragments (register-resident) ----
    uint32_t qa[2][4][4];
#pragma unroll
    for (int hl = 0; hl < 2; hl++) {
        int qb = hl * QS_U;
#pragma unroll
        for (int kb = 0; kb < 4; kb++) {
            qa[hl][kb][0] = sm[qb + (w * 16 + g)     * 36 + kb * 8 + tig];
            qa[hl][kb][1] = sm[qb + (w * 16 + g + 8) * 36 + kb * 8 + tig];
            qa[hl][kb][2] = sm[qb + (w * 16 + g)     * 36 + kb * 8 + 4 + tig];
            qa[hl][kb][3] = sm[qb + (w * 16 + g + 8) * 36 + kb * 8 + 4 + tig];
        }
    }

    float o[8][4];
#pragma unroll
    for (int a = 0; a < 8; a++)
#pragma unroll
        for (int q = 0; q < 4; q++) o[a][q] = 0.f;
    float m[2] = {-1e30f, -1e30f}, l[2] = {0.f, 0.f};

    for (int kt = 0; kt <= qt; kt++) {
        if (kt < qt) { issue(kt + 1, (kt + 1) & 1); cp_commit(); cp_wait<1>(); }
        else         { cp_wait<0>(); }
        __syncthreads();

        const int su = SB_U + (kt & 1) * STG_U;
        const int Kh = su, Kl = su + TILE_U, Vh = su + 2 * TILE_U, Vl = su + 3 * TILE_U;

        // ---- S = Qh·Kh + Qh·Kl + Ql·Kh ----
        float s[8][4];
#pragma unroll
        for (int a = 0; a < 8; a++)
#pragma unroll
            for (int q = 0; q < 4; q++) s[a][q] = 0.f;

#pragma unroll
        for (int kb = 0; kb < 4; kb++) {
            uint32_t bfr[8][2];
#pragma unroll
            for (int na = 0; na < 8; na++) {
                bfr[na][0] = sm[Kh + (8 * kb + tig)     * TSTR + na * 8 + g];
                bfr[na][1] = sm[Kh + (8 * kb + 4 + tig) * TSTR + na * 8 + g];
            }
#pragma unroll
            for (int na = 0; na < 8; na++) mma16816(s[na], qa[0][kb], bfr[na]);
#pragma unroll
            for (int na = 0; na < 8; na++) mma16816(s[na], qa[1][kb], bfr[na]);
#pragma unroll
            for (int na = 0; na < 8; na++) {
                bfr[na][0] = sm[Kl + (8 * kb + tig)     * TSTR + na * 8 + g];
                bfr[na][1] = sm[Kl + (8 * kb + 4 + tig) * TSTR + na * 8 + g];
            }
#pragma unroll
            for (int na = 0; na < 8; na++) mma16816(s[na], qa[0][kb], bfr[na]);
        }

        // ---- causal mask on diagonal tile ----
        if (kt == qt) {
            int r0 = w * 16 + g;
#pragma unroll
            for (int na = 0; na < 8; na++) {
                int c0 = na * 8 + 2 * tig;
                if (c0     > r0)     s[na][0] = -1e9f;
                if (c0 + 1 > r0)     s[na][1] = -1e9f;
                if (c0     > r0 + 8) s[na][2] = -1e9f;
                if (c0 + 1 > r0 + 8) s[na][3] = -1e9f;
            }
        }

        // ---- online softmax (rows g, g+8) ----
#pragma unroll
        for (int ri = 0; ri < 2; ri++) {
            float mx = -1e30f;
#pragma unroll
            for (int a = 0; a < 8; a++)
                mx = fmaxf(mx, fmaxf(s[a][2 * ri], s[a][2 * ri + 1]));
            mx = fmaxf(mx, __shfl_xor_sync(0xffffffffu, mx, 1));
            mx = fmaxf(mx, __shfl_xor_sync(0xffffffffu, mx, 2));
            float mnew = fmaxf(m[ri], mx);
            float corr = __expf(m[ri] - mnew);
            float rs = 0.f;
#pragma unroll
            for (int a = 0; a < 8; a++) {
                float p0 = __expf(s[a][2 * ri]     - mnew);
                float p1 = __expf(s[a][2 * ri + 1] - mnew);
                s[a][2 * ri] = p0; s[a][2 * ri + 1] = p1;
                rs += p0 + p1;
            }
            rs += __shfl_xor_sync(0xffffffffu, rs, 1);
            rs += __shfl_xor_sync(0xffffffffu, rs, 2);
            l[ri] = l[ri] * corr + rs;
            m[ri] = mnew;
#pragma unroll
            for (int a = 0; a < 8; a++) { o[a][2 * ri] *= corr; o[a][2 * ri + 1] *= corr; }
        }

        // ---- O += Ph·Vh + Pl·Vh + Ph·Vl ----
#pragma unroll
        for (int kb = 0; kb < 4; kb++) {
            uint32_t ph[4], pl[4];
            ph[0] = packbf(s[2*kb][0],   s[2*kb][1]);
            ph[1] = packbf(s[2*kb][2],   s[2*kb][3]);
            ph[2] = packbf(s[2*kb+1][0], s[2*kb+1][1]);
            ph[3] = packbf(s[2*kb+1][2], s[2*kb+1][3]);
            pl[0] = packres(ph[0], s[2*kb][0],   s[2*kb][1]);
            pl[1] = packres(ph[1], s[2*kb][2],   s[2*kb][3]);
            pl[2] = packres(ph[2], s[2*kb+1][0], s[2*kb+1][1]);
            pl[3] = packres(ph[3], s[2*kb+1][2], s[2*kb+1][3]);

            uint32_t bfr[8][2];
#pragma unroll
            for (int na = 0; na < 8; na++) {
                bfr[na][0] = sm[Vh + (8 * kb + tig)     * TSTR + na * 8 + g];
                bfr[na][1] = sm[Vh + (8 * kb + 4 + tig) * TSTR + na * 8 + g];
            }
#pragma unroll
            for (int na = 0; na < 8; na++) mma16816(o[na], ph, bfr[na]);
#pragma unroll
            for (int na = 0; na < 8; na++) mma16816(o[na], pl, bfr[na]);
#pragma unroll
            for (int na = 0; na < 8; na++) {
                bfr[na][0] = sm[Vl + (8 * kb + tig)     * TSTR + na * 8 + g];
                bfr[na][1] = sm[Vl + (8 * kb + 4 + tig) * TSTR + na * 8 + g];
            }
#pragma unroll
            for (int na = 0; na < 8; na++) mma16816(o[na], ph, bfr[na]);
        }
        __syncthreads();
    }

    // ---- epilogue ----
    float inv0 = 1.0f / l[0], inv1 = 1.0f / l[1];
    int row0 = qt * 64 + w * 16 + g;
#pragma unroll
    for (int na = 0; na < 8; na++) {
        int col = h * 64 + na * 8 + 2 * tig;
        *(float2*)(g_O + (size_t)(b * 1024 + row0)     * HS + col) = make_float2(o[na][0] * inv0, o[na][1] * inv0);
        *(float2*)(g_O + (size_t)(b * 1024 + row0 + 8) * HS + col) = make_float2(o[na][2] * inv1, o[na][3] * inv1);
    }
}

// ---------------- A2 = split(sd * o) -----------------------------------------
__global__ __launch_bounds__(256) void build_a2() {
    int gid = blockIdx.x * 256 + threadIdx.x;
    int col = gid % V2;
    int bt  = gid / V2;
    int he  = col >> 6;
    int c   = col & 63;
    int h   = he / Ee;
    float a = g_sdg[bt * HE + he] * g_O[(size_t)bt * HS + h * 64 + c];
    __nv_bfloat16 hi, lo; split_bf16(a, hi, lo);
    __nv_bfloat16* p = g_A2 + (size_t)bt * K2 + col;
    p[0] = hi; p[V2] = hi; p[2 * V2] = lo;
}

// ---------------- launch ------------------------------------------------------
extern "C" void kernel_launch(void* const* d_in, const int* in_sizes, int n_in,
                              void* d_out, int out_size)
{
    const float* x  = (const float*)d_in[0];
    const float* Wq = (const float*)d_in[1];
    const float* Wk = (const float*)d_in[2];
    const float* Wv = (const float*)d_in[3];
    const float* Ws = (const float*)d_in[4];
    const float* Wd = (const float*)d_in[5];
    const float* Wo = (const float*)d_in[6];
    float* out = (float*)d_out;

    cudaFuncSetAttribute(gemm1,   cudaFuncAttributeMaxDynamicSharedMemorySize, GEMM_SMEM);
    cudaFuncSetAttribute(gemm2,   cudaFuncAttributeMaxDynamicSharedMemorySize, GEMM_SMEM);
    cudaFuncSetAttribute(attn_tc, cudaFuncAttributeMaxDynamicSharedMemorySize, ATTN_SMEM);

    prep_a1  <<<BT * DIMD / 256, 256>>>(x);
    prep_b1  <<<dim3(32, 120), dim3(32, 8)>>>(Wq, Wk, Wv, Ws, Wd);
    gemm1    <<<dim3(N1 / 128, BT / 128), 256, GEMM_SMEM>>>();
    route_mix<<<BT * Hh * 64 / 256, 256>>>();
    prep_qk  <<<16 * 1024 * 32 / 256, 256>>>();
    prep_v   <<<16 * 512 * 64 / 256, 256>>>();
    attn_tc  <<<dim3(16, 16), 128, ATTN_SMEM>>>();
    prep_b2  <<<HE * DIMD * 64 / 256, 256>>>(Wo);
    build_a2 <<<BT * V2 / 256, 256>>>();
    gemm2    <<<dim3(N2 / 128, BT / 128), 256, GEMM_SMEM>>>(out);
}

// round 5
// speedup vs baseline: 2.8752x; 1.5198x over previous
#include <cuda_runtime.h>
#include <cuda_bf16.h>
#include <cstdint>

#define Tt   1024
#define DIMD 1024
#define Hh   8
#define Ee   5
#define KK   3
#define BT   2048
#define HS   512
#define HE   40
#define QSCALE 0.125f

#define N1 3840      // fused projection width (Q512|K512|V2560|Ss40|Sd40|pad48)
#define K1 3072      // 3*1024 split-K (hi,hi,lo x hi,lo,hi)
#define N2 1024
#define K2 7680      // 3*2560 split-K
#define V2 2560

// ---------------- scratch ----------------------------------------------------
__device__ float          g_C1 [BT * N1];
__device__ __nv_bfloat16  g_A1 [BT * K1];
__device__ __nv_bfloat16  g_B1 [N1 * K1];
__device__ __nv_bfloat16  g_A2 [(size_t)BT * K2];
__device__ __nv_bfloat16  g_B2 [(size_t)N2 * K2];
__device__ float          g_O  [BT * HS];
__device__ float          g_sdg[BT * HE];
// attention operands, packed bf16x2 pairs
__device__ uint32_t g_Qh[16 * 1024 * 32];   // [bh][t][dhpair]
__device__ uint32_t g_Ql[16 * 1024 * 32];
__device__ uint32_t g_Kh[16 * 32 * 1024];   // [bh][dhpair][t]
__device__ uint32_t g_Kl[16 * 32 * 1024];
__device__ uint32_t g_Vh[16 * 512 * 64];    // [bh][keypair][d]
__device__ uint32_t g_Vl[16 * 512 * 64];

// ---------------- helpers -----------------------------------------------------
__device__ __forceinline__ uint32_t smem_u32(const void* p) {
    uint32_t a;
    asm("{ .reg .u64 t; cvta.to.shared.u64 t, %1; cvt.u32.u64 %0, t; }" : "=r"(a) : "l"(p));
    return a;
}
__device__ __forceinline__ void cpasync16(uint32_t dst, const void* src) {
    asm volatile("cp.async.cg.shared.global [%0], [%1], 16;\n" :: "r"(dst), "l"(src));
}
__device__ __forceinline__ void cp_commit() { asm volatile("cp.async.commit_group;\n"); }
template<int N> __device__ __forceinline__ void cp_wait() { asm volatile("cp.async.wait_group %0;\n" :: "n"(N)); }

__device__ __forceinline__ void mma16816(float* c, const uint32_t* a, const uint32_t* b) {
    asm volatile(
        "mma.sync.aligned.m16n8k16.row.col.f32.bf16.bf16.f32 "
        "{%0,%1,%2,%3}, {%4,%5,%6,%7}, {%8,%9}, {%0,%1,%2,%3};"
        : "+f"(c[0]), "+f"(c[1]), "+f"(c[2]), "+f"(c[3])
        : "r"(a[0]), "r"(a[1]), "r"(a[2]), "r"(a[3]), "r"(b[0]), "r"(b[1]));
}
__device__ __forceinline__ void ldm_x4(uint32_t* r, uint32_t addr) {
    asm volatile("ldmatrix.sync.aligned.m8n8.x4.shared.b16 {%0,%1,%2,%3}, [%4];"
        : "=r"(r[0]), "=r"(r[1]), "=r"(r[2]), "=r"(r[3]) : "r"(addr));
}
__device__ __forceinline__ uint32_t packbf(float lo, float hi) {
    uint32_t r;
    asm("cvt.rn.bf16x2.f32 %0, %1, %2;" : "=r"(r) : "f"(hi), "f"(lo));
    return r;
}
__device__ __forceinline__ uint32_t packres(uint32_t p, float lo, float hi) {
    float plo = __uint_as_float(p << 16);
    float phi = __uint_as_float(p & 0xffff0000u);
    return packbf(lo - plo, hi - phi);
}

// ---------------- bf16 mma.sync GEMM: 128 x NT tile, BK=64, ldmatrix ---------
// A [Mtot, KTOT] row-major bf16, Bm [Ntot, KTOT] row-major bf16 (= W^T),
// C [Mtot, Ntot] fp32.  C = A @ Bm^T.
// smem: 3 stages x (128 + NT) rows x 128 B, SW128 swizzle per 8-row atom.
template<int NT, int KTOT>
__device__ __forceinline__ void gemm_body(const __nv_bfloat16* __restrict__ A,
                                          const __nv_bfloat16* __restrict__ Bm,
                                          float* __restrict__ C, int Ntot)
{
    constexpr int ROWS  = 128 + NT;
    constexpr int STAGE = ROWS * 128;
    constexpr int NSTEP = KTOT / 64;
    constexpr int NTW   = (NT == 128) ? 64 : 32;   // warp n-tile
    constexpr int NPAIR = NTW / 16;                // ldmatrix.x4 pairs for B
    constexpr int NA    = NTW / 8;                 // n8 atoms per warp

    extern __shared__ char sm_raw[];
    const uint32_t sb = smem_u32(sm_raw);

    const int tid  = threadIdx.x;
    const int wid  = tid >> 5;
    const int lane = tid & 31;
    const int wm   = wid & 3;        // 4 m-warps of 32 rows
    const int wn   = wid >> 2;       // 2 n-warps of NTW cols
    const int m0   = blockIdx.y * 128;
    const int n0   = blockIdx.x * NT;

    const char* Ag = (const char*)(A  + (size_t)m0 * KTOT);
    const char* Bg = (const char*)(Bm + (size_t)n0 * KTOT);

    // cp.async assignment: thread covers rows tid>>3 + 32*i, 16B chunk tid&7
    const int ld_r   = tid >> 3;
    const int ld_c   = (tid & 7) * 16;
    const int ld_cs  = ld_c ^ ((ld_r & 7) * 16);   // swizzled chunk offset

    auto issue = [&](int kt, int slot) {
        uint32_t st = sb + slot * STAGE;
        const char* agk = Ag + kt * 128;
        const char* bgk = Bg + kt * 128;
#pragma unroll
        for (int i = 0; i < ROWS / 32; i++) {
            int rr = ld_r + i * 32;
            uint32_t dst = st + rr * 128 + ld_cs;
            const char* src = (i < 4) ? agk + (size_t)rr * (KTOT * 2) + ld_c
                                      : bgk + (size_t)(rr - 128) * (KTOT * 2) + ld_c;
            cpasync16(dst, src);
        }
    };

    // ldmatrix per-thread static offsets
    const uint32_t xorv = (lane & 7) * 16;
    const uint32_t ahi  = (lane >> 4) * 16;
    const uint32_t bhi  = ((lane >> 3) & 1) * 16;
    uint32_t arow[2], brow[NPAIR];
#pragma unroll
    for (int mi = 0; mi < 2; mi++)
        arow[mi] = (wm * 32 + mi * 16 + (lane & 15)) * 128;
#pragma unroll
    for (int pj = 0; pj < NPAIR; pj++)
        brow[pj] = (128 + wn * NTW + pj * 16 + ((lane >> 4) << 3) + (lane & 7)) * 128;

    float acc[2][NA][4];
#pragma unroll
    for (int mi = 0; mi < 2; mi++)
#pragma unroll
        for (int na = 0; na < NA; na++)
#pragma unroll
            for (int q = 0; q < 4; q++) acc[mi][na][q] = 0.f;

    issue(0, 0); cp_commit();
    issue(1, 1); cp_commit();

    for (int kt = 0; kt < NSTEP; kt++) {
        if (kt + 2 < NSTEP) issue(kt + 2, (kt + 2) % 3);
        cp_commit();
        cp_wait<2>();
        __syncthreads();

        uint32_t stg = sb + (kt % 3) * STAGE;
#pragma unroll
        for (int ks = 0; ks < 4; ks++) {
            uint32_t a[2][4];
            ldm_x4(a[0], stg + arow[0] + (((uint32_t)ks * 32 + ahi) ^ xorv));
            ldm_x4(a[1], stg + arow[1] + (((uint32_t)ks * 32 + ahi) ^ xorv));
            uint32_t b[NPAIR][4];
#pragma unroll
            for (int pj = 0; pj < NPAIR; pj++)
                ldm_x4(b[pj], stg + brow[pj] + (((uint32_t)ks * 32 + bhi) ^ xorv));
#pragma unroll
            for (int mi = 0; mi < 2; mi++)
#pragma unroll
                for (int pj = 0; pj < NPAIR; pj++) {
                    mma16816(acc[mi][2 * pj],     a[mi], &b[pj][0]);
                    mma16816(acc[mi][2 * pj + 1], a[mi], &b[pj][2]);
                }
        }
        __syncthreads();
    }

    // epilogue
    const int g   = lane >> 2;
    const int tg  = lane & 3;
#pragma unroll
    for (int mi = 0; mi < 2; mi++) {
        int r0 = m0 + wm * 32 + mi * 16 + g;
#pragma unroll
        for (int na = 0; na < NA; na++) {
            int cc = n0 + wn * NTW + na * 8 + tg * 2;
            *(float2*)(C + (size_t)r0 * Ntot + cc)       = make_float2(acc[mi][na][0], acc[mi][na][1]);
            *(float2*)(C + (size_t)(r0 + 8) * Ntot + cc) = make_float2(acc[mi][na][2], acc[mi][na][3]);
        }
    }
}

#define GEMM1_SMEM (3 * 256 * 128)   // 98304
#define GEMM2_SMEM (3 * 192 * 128)   // 73728

__global__ __launch_bounds__(256, 2)
void gemm1() { gemm_body<128, K1>(g_A1, g_B1, g_C1, N1); }

__global__ __launch_bounds__(256, 2)
void gemm2(float* __restrict__ out) { gemm_body<64, K2>(g_A2, g_B2, out, N2); }

// ---------------- prep kernels ----------------------------------------------
__device__ __forceinline__ void split_bf16(float v, __nv_bfloat16& hi, __nv_bfloat16& lo) {
    hi = __float2bfloat16(v);
    lo = __float2bfloat16(v - __bfloat162float(hi));
}

__global__ __launch_bounds__(256) void prep_a1(const float* __restrict__ x) {
    int gid = blockIdx.x * 256 + threadIdx.x;
    int m = gid >> 10, k = gid & 1023;
    __nv_bfloat16 hi, lo; split_bf16(x[gid], hi, lo);
    __nv_bfloat16* a = g_A1 + (size_t)m * K1 + k;
    a[0] = hi; a[1024] = hi; a[2048] = lo;
}

__global__ void prep_b1(const float* __restrict__ Wq, const float* __restrict__ Wk,
                        const float* __restrict__ Wv, const float* __restrict__ Ws,
                        const float* __restrict__ Wd)
{
    __shared__ float tile[32][33];
    int k0 = blockIdx.x * 32;
    int n0 = blockIdx.y * 32;
    int tx = threadIdx.x, ty = threadIdx.y;
#pragma unroll
    for (int yy = 0; yy < 32; yy += 8) {
        int k = k0 + ty + yy, n = n0 + tx;
        float w;
        if      (n < 512)  w = Wq[(size_t)k * 512  + n];
        else if (n < 1024) w = Wk[(size_t)k * 512  + n - 512];
        else if (n < 3584) w = Wv[(size_t)k * 2560 + n - 1024];
        else if (n < 3624) w = Ws[(size_t)k * 40   + n - 3584];
        else if (n < 3664) w = Wd[(size_t)k * 40   + n - 3624];
        else               w = 0.f;
        tile[ty + yy][tx] = w;
    }
    __syncthreads();
#pragma unroll
    for (int yy = 0; yy < 32; yy += 8) {
        int n = n0 + ty + yy, k = k0 + tx;
        __nv_bfloat16 hi, lo; split_bf16(tile[tx][ty + yy], hi, lo);
        __nv_bfloat16* b = g_B1 + (size_t)n * K1 + k;
        b[0] = hi; b[1024] = lo; b[2048] = hi;
    }
}

__global__ __launch_bounds__(256) void prep_b2(const float* __restrict__ Wo) {
    int gid = blockIdx.x * 256 + threadIdx.x;
    int he = gid >> 16;
    int d  = (gid >> 6) & 1023;
    int c  = gid & 63;
    __nv_bfloat16 hi, lo; split_bf16(Wo[gid], hi, lo);
    __nv_bfloat16* b = g_B2 + (size_t)d * K2 + he * 64 + c;
    b[0] = hi; b[V2] = lo; b[2 * V2] = hi;
}

// ---------------- fused routing gates + expert V mix + split-pack ------------
__global__ __launch_bounds__(256) void route_pack() {
    int gid = blockIdx.x * 256 + threadIdx.x;   // 16*512*64
    int d  = gid & 63;
    int kp = (gid >> 6) & 511;
    int bh = gid >> 15;
    int b = bh >> 3, h = bh & 7;

    float v[2];
#pragma unroll
    for (int u = 0; u < 2; u++) {
        int t = kp * 2 + u;
        const float* row = g_C1 + (size_t)(b * 1024 + t) * N1;
        const float* sl = row + 3584 + h * Ee;
        float s[Ee];
#pragma unroll
        for (int e = 0; e < Ee; e++) s[e] = sl[e];
        float acc = 0.f;
#pragma unroll
        for (int e = 0; e < Ee; e++) {
            int rank = 0;
#pragma unroll
            for (int j = 0; j < Ee; j++)
                rank += (s[j] > s[e]) || (s[j] == s[e] && j < e);
            float gate = (rank < KK) ? 1.0f / (1.0f + expf(-s[e])) : 0.f;
            acc = fmaf(gate, row[1024 + (h * Ee + e) * 64 + d], acc);
        }
        v[u] = acc;

        if (d < Ee) {
            const float* dl = row + 3624 + h * Ee;
            float tq[Ee];
#pragma unroll
            for (int e = 0; e < Ee; e++) tq[e] = dl[e];
            int e = d, rank = 0;
#pragma unroll
            for (int j = 0; j < Ee; j++)
                rank += (tq[j] > tq[e]) || (tq[j] == tq[e] && j < e);
            g_sdg[(b * 1024 + t) * HE + h * Ee + e] = (rank < KK) ? 1.f : 0.f;
        }
    }
    uint32_t vh = packbf(v[0], v[1]);
    g_Vh[gid] = vh;
    g_Vl[gid] = packres(vh, v[0], v[1]);
}

// ---------------- attention operand prep --------------------------------------
__global__ __launch_bounds__(256) void prep_qk() {
    int gid = blockIdx.x * 256 + threadIdx.x;   // 16*1024*32
    int p  = gid & 31;
    int t  = (gid >> 5) & 1023;
    int bh = gid >> 15;
    int b = bh >> 3, h = bh & 7;
    const float* row = g_C1 + (size_t)(b * 1024 + t) * N1;

    float q0 = row[h * 64 + 2 * p]     * QSCALE;
    float q1 = row[h * 64 + 2 * p + 1] * QSCALE;
    uint32_t qh = packbf(q0, q1);
    g_Qh[gid] = qh;
    g_Ql[gid] = packres(qh, q0, q1);

    float k0 = row[512 + h * 64 + 2 * p];
    float k1 = row[512 + h * 64 + 2 * p + 1];
    uint32_t kh = packbf(k0, k1);
    int kidx = (bh * 32 + p) * 1024 + t;
    g_Kh[kidx] = kh;
    g_Kl[kidx] = packres(kh, k0, k1);
}

// ---------------- tensor-core causal flash attention -------------------------
#define TSTR   72
#define TILE_U (32 * TSTR)
#define STG_U  (4 * TILE_U)
#define QS_U   (64 * 36)
#define SB_U   (2 * QS_U)
#define ATTN_SMEM ((SB_U + 2 * STG_U) * 4)

__global__ __launch_bounds__(128) void attn_tc() {
    extern __shared__ uint32_t sm[];
    const int qt  = blockIdx.x;
    const int bh  = blockIdx.y;
    const int b   = bh >> 3, h = bh & 7;
    const int tid = threadIdx.x;
    const int w   = tid >> 5;
    const int lane = tid & 31;
    const int g   = lane >> 2;
    const int tig = lane & 3;
    const uint32_t sbase_b = smem_u32(sm);

    {
        const uint32_t* qhsrc = g_Qh + ((size_t)(bh << 10) + qt * 64) * 32;
        const uint32_t* qlsrc = g_Ql + ((size_t)(bh << 10) + qt * 64) * 32;
#pragma unroll
        for (int j = 0; j < 4; j++) {
            int idx = tid + j * 128;
            int row = idx >> 3, po = (idx & 7) * 4;
            *(uint4*)&sm[row * 36 + po]        = *(const uint4*)(qhsrc + row * 32 + po);
            *(uint4*)&sm[QS_U + row * 36 + po] = *(const uint4*)(qlsrc + row * 32 + po);
        }
    }

    auto issue = [&](int kt, int s) {
#pragma unroll
        for (int i = 0; i < 16; i++) {
            int a = i >> 2;
            int r = (i & 3) * 8 + (tid >> 4);
            int p = tid & 15;
            uint32_t dst = sbase_b + (SB_U + s * STG_U + a * TILE_U + r * TSTR) * 4 + p * 16;
            const uint32_t* srcb;
            if      (a == 0) srcb = g_Kh + (size_t)(bh * 32 + r) * 1024 + kt * 64;
            else if (a == 1) srcb = g_Kl + (size_t)(bh * 32 + r) * 1024 + kt * 64;
            else if (a == 2) srcb = g_Vh + (size_t)(bh * 512 + kt * 32 + r) * 64;
            else             srcb = g_Vl + (size_t)(bh * 512 + kt * 32 + r) * 64;
            cpasync16(dst, (const char*)srcb + p * 16);
        }
    };
    issue(0, 0); cp_commit();
    __syncthreads();

    uint32_t qa[2][4][4];
#pragma unroll
    for (int hl = 0; hl < 2; hl++) {
        int qb = hl * QS_U;
#pragma unroll
        for (int kb = 0; kb < 4; kb++) {
            qa[hl][kb][0] = sm[qb + (w * 16 + g)     * 36 + kb * 8 + tig];
            qa[hl][kb][1] = sm[qb + (w * 16 + g + 8) * 36 + kb * 8 + tig];
            qa[hl][kb][2] = sm[qb + (w * 16 + g)     * 36 + kb * 8 + 4 + tig];
            qa[hl][kb][3] = sm[qb + (w * 16 + g + 8) * 36 + kb * 8 + 4 + tig];
        }
    }

    float o[8][4];
#pragma unroll
    for (int a = 0; a < 8; a++)
#pragma unroll
        for (int q = 0; q < 4; q++) o[a][q] = 0.f;
    float m[2] = {-1e30f, -1e30f}, l[2] = {0.f, 0.f};

    for (int kt = 0; kt <= qt; kt++) {
        if (kt < qt) { issue(kt + 1, (kt + 1) & 1); cp_commit(); cp_wait<1>(); }
        else         { cp_wait<0>(); }
        __syncthreads();

        const int su = SB_U + (kt & 1) * STG_U;
        const int Kh = su, Kl = su + TILE_U, Vh = su + 2 * TILE_U, Vl = su + 3 * TILE_U;

        float s[8][4];
#pragma unroll
        for (int a = 0; a < 8; a++)
#pragma unroll
            for (int q = 0; q < 4; q++) s[a][q] = 0.f;

#pragma unroll
        for (int kb = 0; kb < 4; kb++) {
            uint32_t bfr[8][2];
#pragma unroll
            for (int na = 0; na < 8; na++) {
                bfr[na][0] = sm[Kh + (8 * kb + tig)     * TSTR + na * 8 + g];
                bfr[na][1] = sm[Kh + (8 * kb + 4 + tig) * TSTR + na * 8 + g];
            }
#pragma unroll
            for (int na = 0; na < 8; na++) mma16816(s[na], qa[0][kb], bfr[na]);
#pragma unroll
            for (int na = 0; na < 8; na++) mma16816(s[na], qa[1][kb], bfr[na]);
#pragma unroll
            for (int na = 0; na < 8; na++) {
                bfr[na][0] = sm[Kl + (8 * kb + tig)     * TSTR + na * 8 + g];
                bfr[na][1] = sm[Kl + (8 * kb + 4 + tig) * TSTR + na * 8 + g];
            }
#pragma unroll
            for (int na = 0; na < 8; na++) mma16816(s[na], qa[0][kb], bfr[na]);
        }

        if (kt == qt) {
            int r0 = w * 16 + g;
#pragma unroll
            for (int na = 0; na < 8; na++) {
                int c0 = na * 8 + 2 * tig;
                if (c0     > r0)     s[na][0] = -1e9f;
                if (c0 + 1 > r0)     s[na][1] = -1e9f;
                if (c0     > r0 + 8) s[na][2] = -1e9f;
                if (c0 + 1 > r0 + 8) s[na][3] = -1e9f;
            }
        }

#pragma unroll
        for (int ri = 0; ri < 2; ri++) {
            float mx = -1e30f;
#pragma unroll
            for (int a = 0; a < 8; a++)
                mx = fmaxf(mx, fmaxf(s[a][2 * ri], s[a][2 * ri + 1]));
            mx = fmaxf(mx, __shfl_xor_sync(0xffffffffu, mx, 1));
            mx = fmaxf(mx, __shfl_xor_sync(0xffffffffu, mx, 2));
            float mnew = fmaxf(m[ri], mx);
            float corr = __expf(m[ri] - mnew);
            float rs = 0.f;
#pragma unroll
            for (int a = 0; a < 8; a++) {
                float p0 = __expf(s[a][2 * ri]     - mnew);
                float p1 = __expf(s[a][2 * ri + 1] - mnew);
                s[a][2 * ri] = p0; s[a][2 * ri + 1] = p1;
                rs += p0 + p1;
            }
            rs += __shfl_xor_sync(0xffffffffu, rs, 1);
            rs += __shfl_xor_sync(0xffffffffu, rs, 2);
            l[ri] = l[ri] * corr + rs;
            m[ri] = mnew;
#pragma unroll
            for (int a = 0; a < 8; a++) { o[a][2 * ri] *= corr; o[a][2 * ri + 1] *= corr; }
        }

#pragma unroll
        for (int kb = 0; kb < 4; kb++) {
            uint32_t ph[4], pl[4];
            ph[0] = packbf(s[2*kb][0],   s[2*kb][1]);
            ph[1] = packbf(s[2*kb][2],   s[2*kb][3]);
            ph[2] = packbf(s[2*kb+1][0], s[2*kb+1][1]);
            ph[3] = packbf(s[2*kb+1][2], s[2*kb+1][3]);
            pl[0] = packres(ph[0], s[2*kb][0],   s[2*kb][1]);
            pl[1] = packres(ph[1], s[2*kb][2],   s[2*kb][3]);
            pl[2] = packres(ph[2], s[2*kb+1][0], s[2*kb+1][1]);
            pl[3] = packres(ph[3], s[2*kb+1][2], s[2*kb+1][3]);

            uint32_t bfr[8][2];
#pragma unroll
            for (int na = 0; na < 8; na++) {
                bfr[na][0] = sm[Vh + (8 * kb + tig)     * TSTR + na * 8 + g];
                bfr[na][1] = sm[Vh + (8 * kb + 4 + tig) * TSTR + na * 8 + g];
            }
#pragma unroll
            for (int na = 0; na < 8; na++) mma16816(o[na], ph, bfr[na]);
#pragma unroll
            for (int na = 0; na < 8; na++) mma16816(o[na], pl, bfr[na]);
#pragma unroll
            for (int na = 0; na < 8; na++) {
                bfr[na][0] = sm[Vl + (8 * kb + tig)     * TSTR + na * 8 + g];
                bfr[na][1] = sm[Vl + (8 * kb + 4 + tig) * TSTR + na * 8 + g];
            }
#pragma unroll
            for (int na = 0; na < 8; na++) mma16816(o[na], ph, bfr[na]);
        }
        __syncthreads();
    }

    float inv0 = 1.0f / l[0], inv1 = 1.0f / l[1];
    int row0 = qt * 64 + w * 16 + g;
#pragma unroll
    for (int na = 0; na < 8; na++) {
        int col = h * 64 + na * 8 + 2 * tig;
        *(float2*)(g_O + (size_t)(b * 1024 + row0)     * HS + col) = make_float2(o[na][0] * inv0, o[na][1] * inv0);
        *(float2*)(g_O + (size_t)(b * 1024 + row0 + 8) * HS + col) = make_float2(o[na][2] * inv1, o[na][3] * inv1);
    }
}

// ---------------- A2 = split(sd * o) -----------------------------------------
__global__ __launch_bounds__(256) void build_a2() {
    int gid = blockIdx.x * 256 + threadIdx.x;
    int col = gid % V2;
    int bt  = gid / V2;
    int he  = col >> 6;
    int c   = col & 63;
    int h   = he / Ee;
    float a = g_sdg[bt * HE + he] * g_O[(size_t)bt * HS + h * 64 + c];
    __nv_bfloat16 hi, lo; split_bf16(a, hi, lo);
    __nv_bfloat16* p = g_A2 + (size_t)bt * K2 + col;
    p[0] = hi; p[V2] = hi; p[2 * V2] = lo;
}

// ---------------- launch ------------------------------------------------------
extern "C" void kernel_launch(void* const* d_in, const int* in_sizes, int n_in,
                              void* d_out, int out_size)
{
    const float* x  = (const float*)d_in[0];
    const float* Wq = (const float*)d_in[1];
    const float* Wk = (const float*)d_in[2];
    const float* Wv = (const float*)d_in[3];
    const float* Ws = (const float*)d_in[4];
    const float* Wd = (const float*)d_in[5];
    const float* Wo = (const float*)d_in[6];
    float* out = (float*)d_out;

    cudaFuncSetAttribute(gemm1,   cudaFuncAttributeMaxDynamicSharedMemorySize, GEMM1_SMEM);
    cudaFuncSetAttribute(gemm2,   cudaFuncAttributeMaxDynamicSharedMemorySize, GEMM2_SMEM);
    cudaFuncSetAttribute(attn_tc, cudaFuncAttributeMaxDynamicSharedMemorySize, ATTN_SMEM);

    prep_a1   <<<BT * DIMD / 256, 256>>>(x);
    prep_b1   <<<dim3(32, 120), dim3(32, 8)>>>(Wq, Wk, Wv, Ws, Wd);
    prep_b2   <<<HE * DIMD * 64 / 256, 256>>>(Wo);
    gemm1     <<<dim3(N1 / 128, BT / 128), 256, GEMM1_SMEM>>>();
    route_pack<<<16 * 512 * 64 / 256, 256>>>();
    prep_qk   <<<16 * 1024 * 32 / 256, 256>>>();
    attn_tc   <<<dim3(16, 16), 128, ATTN_SMEM>>>();
    build_a2  <<<BT * V2 / 256, 256>>>();
    gemm2     <<<dim3(N2 / 64, BT / 128), 256, GEMM2_SMEM>>>(out);
}

// round 6
// speedup vs baseline: 3.0494x; 1.0606x over previous
#include <cuda_runtime.h>
#include <cuda_bf16.h>
#include <cstdint>

#define Tt   1024
#define DIMD 1024
#define Hh   8
#define Ee   5
#define KK   3
#define BT   2048
#define HS   512
#define HE   40
#define QSCALE 0.125f

#define N1 3840      // fused projection width (Q512|K512|V2560|Ss40|Sd40|pad48)
#define K1 3072      // 3*1024 split-K (hi,hi,lo x hi,lo,hi)
#define N2 1024
#define K2 7680      // 3*2560 split-K
#define V2 2560

// ---------------- scratch ----------------------------------------------------
__device__ float          g_C1 [BT * N1];
__device__ __nv_bfloat16  g_A1 [BT * K1];
__device__ __nv_bfloat16  g_B1 [N1 * K1];
__device__ __nv_bfloat16  g_A2 [(size_t)BT * K2];
__device__ __nv_bfloat16  g_B2 [(size_t)N2 * K2];
__device__ float          g_O  [BT * HS];
__device__ float          g_sdg[BT * HE];
// attention operands, packed bf16x2 pairs
__device__ uint32_t g_Qh[16 * 1024 * 32];   // [bh][t][dpair]
__device__ uint32_t g_Ql[16 * 1024 * 32];
__device__ uint32_t g_Kh[16 * 1024 * 32];   // [bh][t][dpair]   (Q-style layout)
__device__ uint32_t g_Kl[16 * 1024 * 32];
__device__ uint32_t g_Vh[16 * 64 * 512];    // [bh][d][tpair]   (transposed)
__device__ uint32_t g_Vl[16 * 64 * 512];

// ---------------- helpers -----------------------------------------------------
__device__ __forceinline__ uint32_t smem_u32(const void* p) {
    uint32_t a;
    asm("{ .reg .u64 t; cvta.to.shared.u64 t, %1; cvt.u32.u64 %0, t; }" : "=r"(a) : "l"(p));
    return a;
}
__device__ __forceinline__ void cpasync16(uint32_t dst, const void* src) {
    asm volatile("cp.async.cg.shared.global [%0], [%1], 16;\n" :: "r"(dst), "l"(src));
}
__device__ __forceinline__ void cp_commit() { asm volatile("cp.async.commit_group;\n"); }
template<int N> __device__ __forceinline__ void cp_wait() { asm volatile("cp.async.wait_group %0;\n" :: "n"(N)); }

__device__ __forceinline__ void mma16816(float* c, const uint32_t* a, const uint32_t* b) {
    asm volatile(
        "mma.sync.aligned.m16n8k16.row.col.f32.bf16.bf16.f32 "
        "{%0,%1,%2,%3}, {%4,%5,%6,%7}, {%8,%9}, {%0,%1,%2,%3};"
        : "+f"(c[0]), "+f"(c[1]), "+f"(c[2]), "+f"(c[3])
        : "r"(a[0]), "r"(a[1]), "r"(a[2]), "r"(a[3]), "r"(b[0]), "r"(b[1]));
}
__device__ __forceinline__ void ldm_x4(uint32_t* r, uint32_t addr) {
    asm volatile("ldmatrix.sync.aligned.m8n8.x4.shared.b16 {%0,%1,%2,%3}, [%4];"
        : "=r"(r[0]), "=r"(r[1]), "=r"(r[2]), "=r"(r[3]) : "r"(addr));
}
__device__ __forceinline__ uint32_t packbf(float lo, float hi) {
    uint32_t r;
    asm("cvt.rn.bf16x2.f32 %0, %1, %2;" : "=r"(r) : "f"(hi), "f"(lo));
    return r;
}
__device__ __forceinline__ uint32_t packres(uint32_t p, float lo, float hi) {
    float plo = __uint_as_float(p << 16);
    float phi = __uint_as_float(p & 0xffff0000u);
    return packbf(lo - plo, hi - phi);
}
#define WGBAR(id) asm volatile("bar.sync %0, 128;" :: "r"((id) + 1) : "memory")

// ---------------- bf16 mma.sync GEMM: 128 x NT tile, BK=64, ldmatrix ---------
template<int NT, int KTOT>
__device__ __forceinline__ void gemm_body(const __nv_bfloat16* __restrict__ A,
                                          const __nv_bfloat16* __restrict__ Bm,
                                          float* __restrict__ C, int Ntot)
{
    constexpr int ROWS  = 128 + NT;
    constexpr int STAGE = ROWS * 128;
    constexpr int NSTEP = KTOT / 64;
    constexpr int NTW   = (NT == 128) ? 64 : 32;
    constexpr int NPAIR = NTW / 16;
    constexpr int NA    = NTW / 8;

    extern __shared__ char sm_raw[];
    const uint32_t sb = smem_u32(sm_raw);

    const int tid  = threadIdx.x;
    const int wid  = tid >> 5;
    const int lane = tid & 31;
    const int wm   = wid & 3;
    const int wn   = wid >> 2;
    const int m0   = blockIdx.y * 128;
    const int n0   = blockIdx.x * NT;

    const char* Ag = (const char*)(A  + (size_t)m0 * KTOT);
    const char* Bg = (const char*)(Bm + (size_t)n0 * KTOT);

    const int ld_r   = tid >> 3;
    const int ld_c   = (tid & 7) * 16;
    const int ld_cs  = ld_c ^ ((ld_r & 7) * 16);

    auto issue = [&](int kt, int slot) {
        uint32_t st = sb + slot * STAGE;
        const char* agk = Ag + kt * 128;
        const char* bgk = Bg + kt * 128;
#pragma unroll
        for (int i = 0; i < ROWS / 32; i++) {
            int rr = ld_r + i * 32;
            uint32_t dst = st + rr * 128 + ld_cs;
            const char* src = (i < 4) ? agk + (size_t)rr * (KTOT * 2) + ld_c
                                      : bgk + (size_t)(rr - 128) * (KTOT * 2) + ld_c;
            cpasync16(dst, src);
        }
    };

    const uint32_t xorv = (lane & 7) * 16;
    const uint32_t ahi  = (lane >> 4) * 16;
    const uint32_t bhi  = ((lane >> 3) & 1) * 16;
    uint32_t arow[2], brow[NPAIR];
#pragma unroll
    for (int mi = 0; mi < 2; mi++)
        arow[mi] = (wm * 32 + mi * 16 + (lane & 15)) * 128;
#pragma unroll
    for (int pj = 0; pj < NPAIR; pj++)
        brow[pj] = (128 + wn * NTW + pj * 16 + ((lane >> 4) << 3) + (lane & 7)) * 128;

    float acc[2][NA][4];
#pragma unroll
    for (int mi = 0; mi < 2; mi++)
#pragma unroll
        for (int na = 0; na < NA; na++)
#pragma unroll
            for (int q = 0; q < 4; q++) acc[mi][na][q] = 0.f;

    issue(0, 0); cp_commit();
    issue(1, 1); cp_commit();

    for (int kt = 0; kt < NSTEP; kt++) {
        if (kt + 1 < NSTEP) cp_wait<1>(); else cp_wait<0>();
        __syncthreads();
        if (kt + 2 < NSTEP) { issue(kt + 2, (kt + 2) % 3); cp_commit(); }

        uint32_t stg = sb + (kt % 3) * STAGE;
        // A fragments double-buffered across ks
        uint32_t afr[2][2][4];
        ldm_x4(afr[0][0], stg + arow[0] + (ahi ^ xorv));
        ldm_x4(afr[0][1], stg + arow[1] + (ahi ^ xorv));
#pragma unroll
        for (int ks = 0; ks < 4; ks++) {
            const int cur = ks & 1;
            if (ks < 3) {
                ldm_x4(afr[cur ^ 1][0], stg + arow[0] + (((uint32_t)(ks + 1) * 32 + ahi) ^ xorv));
                ldm_x4(afr[cur ^ 1][1], stg + arow[1] + (((uint32_t)(ks + 1) * 32 + ahi) ^ xorv));
            }
            uint32_t b[NPAIR][4];
#pragma unroll
            for (int pj = 0; pj < NPAIR; pj++)
                ldm_x4(b[pj], stg + brow[pj] + (((uint32_t)ks * 32 + bhi) ^ xorv));
#pragma unroll
            for (int mi = 0; mi < 2; mi++)
#pragma unroll
                for (int pj = 0; pj < NPAIR; pj++) {
                    mma16816(acc[mi][2 * pj],     afr[cur][mi], &b[pj][0]);
                    mma16816(acc[mi][2 * pj + 1], afr[cur][mi], &b[pj][2]);
                }
        }
    }

    __syncthreads();   // all reads done before CTA exit (safety for last stage reuse: none) 
    const int g   = lane >> 2;
    const int tg  = lane & 3;
#pragma unroll
    for (int mi = 0; mi < 2; mi++) {
        int r0 = m0 + wm * 32 + mi * 16 + g;
#pragma unroll
        for (int na = 0; na < NA; na++) {
            int cc = n0 + wn * NTW + na * 8 + tg * 2;
            *(float2*)(C + (size_t)r0 * Ntot + cc)       = make_float2(acc[mi][na][0], acc[mi][na][1]);
            *(float2*)(C + (size_t)(r0 + 8) * Ntot + cc) = make_float2(acc[mi][na][2], acc[mi][na][3]);
        }
    }
}

#define GEMM1_SMEM (3 * 256 * 128)
#define GEMM2_SMEM (3 * 192 * 128)

__global__ __launch_bounds__(256, 2)
void gemm1() { gemm_body<128, K1>(g_A1, g_B1, g_C1, N1); }

__global__ __launch_bounds__(256, 2)
void gemm2(float* __restrict__ out) { gemm_body<64, K2>(g_A2, g_B2, out, N2); }

// ---------------- prep kernels ----------------------------------------------
__device__ __forceinline__ void split_bf16(float v, __nv_bfloat16& hi, __nv_bfloat16& lo) {
    hi = __float2bfloat16(v);
    lo = __float2bfloat16(v - __bfloat162float(hi));
}

__global__ __launch_bounds__(256) void prep_a1(const float* __restrict__ x) {
    int gid = blockIdx.x * 256 + threadIdx.x;
    int m = gid >> 10, k = gid & 1023;
    __nv_bfloat16 hi, lo; split_bf16(x[gid], hi, lo);
    __nv_bfloat16* a = g_A1 + (size_t)m * K1 + k;
    a[0] = hi; a[1024] = hi; a[2048] = lo;
}

__global__ void prep_b1(const float* __restrict__ Wq, const float* __restrict__ Wk,
                        const float* __restrict__ Wv, const float* __restrict__ Ws,
                        const float* __restrict__ Wd)
{
    __shared__ float tile[32][33];
    int k0 = blockIdx.x * 32;
    int n0 = blockIdx.y * 32;
    int tx = threadIdx.x, ty = threadIdx.y;
#pragma unroll
    for (int yy = 0; yy < 32; yy += 8) {
        int k = k0 + ty + yy, n = n0 + tx;
        float w;
        if      (n < 512)  w = Wq[(size_t)k * 512  + n];
        else if (n < 1024) w = Wk[(size_t)k * 512  + n - 512];
        else if (n < 3584) w = Wv[(size_t)k * 2560 + n - 1024];
        else if (n < 3624) w = Ws[(size_t)k * 40   + n - 3584];
        else if (n < 3664) w = Wd[(size_t)k * 40   + n - 3624];
        else               w = 0.f;
        tile[ty + yy][tx] = w;
    }
    __syncthreads();
#pragma unroll
    for (int yy = 0; yy < 32; yy += 8) {
        int n = n0 + ty + yy, k = k0 + tx;
        __nv_bfloat16 hi, lo; split_bf16(tile[tx][ty + yy], hi, lo);
        __nv_bfloat16* b = g_B1 + (size_t)n * K1 + k;
        b[0] = hi; b[1024] = lo; b[2048] = hi;
    }
}

__global__ __launch_bounds__(256) void prep_b2(const float* __restrict__ Wo) {
    int gid = blockIdx.x * 256 + threadIdx.x;
    int he = gid >> 16;
    int d  = (gid >> 6) & 1023;
    int c  = gid & 63;
    __nv_bfloat16 hi, lo; split_bf16(Wo[gid], hi, lo);
    __nv_bfloat16* b = g_B2 + (size_t)d * K2 + he * 64 + c;
    b[0] = hi; b[V2] = lo; b[2 * V2] = hi;
}

// ---------------- fused routing gates + expert V mix + transposed pack -------
__global__ __launch_bounds__(256) void route_pack() {
    __shared__ uint32_t tvh[4][65], tvl[4][65];
    int gid = blockIdx.x * 256 + threadIdx.x;   // 16*512*64, d fastest
    int d  = gid & 63;
    int kp = (gid >> 6) & 511;
    int bh = gid >> 15;
    int b = bh >> 3, h = bh & 7;

    float v[2];
#pragma unroll
    for (int u = 0; u < 2; u++) {
        int t = kp * 2 + u;
        const float* row = g_C1 + (size_t)(b * 1024 + t) * N1;
        const float* sl = row + 3584 + h * Ee;
        float s[Ee];
#pragma unroll
        for (int e = 0; e < Ee; e++) s[e] = sl[e];
        float acc = 0.f;
#pragma unroll
        for (int e = 0; e < Ee; e++) {
            int rank = 0;
#pragma unroll
            for (int j = 0; j < Ee; j++)
                rank += (s[j] > s[e]) || (s[j] == s[e] && j < e);
            float gate = (rank < KK) ? 1.0f / (1.0f + expf(-s[e])) : 0.f;
            acc = fmaf(gate, row[1024 + (h * Ee + e) * 64 + d], acc);
        }
        v[u] = acc;

        if (d < Ee) {
            const float* dl = row + 3624 + h * Ee;
            float tq[Ee];
#pragma unroll
            for (int e = 0; e < Ee; e++) tq[e] = dl[e];
            int e = d, rank = 0;
#pragma unroll
            for (int j = 0; j < Ee; j++)
                rank += (tq[j] > tq[e]) || (tq[j] == tq[e] && j < e);
            g_sdg[(b * 1024 + t) * HE + h * Ee + e] = (rank < KK) ? 1.f : 0.f;
        }
    }
    uint32_t vh = packbf(v[0], v[1]);
    tvh[kp & 3][d] = vh;
    tvl[kp & 3][d] = packres(vh, v[0], v[1]);
    __syncthreads();
    // transposed coalesced write: 4 consecutive threads = 4 consecutive tpairs
    int td  = threadIdx.x >> 2;
    int tk4 = threadIdx.x & 3;
    int kp0 = (blockIdx.x * 4) & 511;
    size_t oidx = ((size_t)bh * 64 + td) * 512 + kp0 + tk4;
    g_Vh[oidx] = tvh[tk4][td];
    g_Vl[oidx] = tvl[tk4][td];
}

// ---------------- attention operand prep --------------------------------------
__global__ __launch_bounds__(256) void prep_qk() {
    int gid = blockIdx.x * 256 + threadIdx.x;   // 16*1024*32
    int p  = gid & 31;
    int t  = (gid >> 5) & 1023;
    int bh = gid >> 15;
    int b = bh >> 3, h = bh & 7;
    const float* row = g_C1 + (size_t)(b * 1024 + t) * N1;

    float q0 = row[h * 64 + 2 * p]     * QSCALE;
    float q1 = row[h * 64 + 2 * p + 1] * QSCALE;
    uint32_t qh = packbf(q0, q1);
    g_Qh[gid] = qh;
    g_Ql[gid] = packres(qh, q0, q1);

    float k0 = row[512 + h * 64 + 2 * p];
    float k1 = row[512 + h * 64 + 2 * p + 1];
    uint32_t kh = packbf(k0, k1);
    g_Kh[gid] = kh;
    g_Kl[gid] = packres(kh, k0, k1);
}

// ---------------- tensor-core causal flash attention, paired q-tiles ---------
// CTA = 256 thr = 2 independent 128-thr warp-groups; wg0: qt=bx, wg1: qt=15-bx.
// Per wg smem (u32): Qh[64][36], Ql[64][36], 2 stages x {Kh,Kl,Vh,Vl}[64 rows][36].
#define AQS   (64 * 36)                 // 2304 u32 per Q array
#define ATL   (64 * 36)                 // 2304 u32 per KV array
#define ASTG  (4 * ATL)                 // 9216 u32 per stage
#define AWG_U (2 * AQS + 2 * ASTG)      // 23040 u32 per warp-group
#define ATTN_SMEM (2 * AWG_U * 4)       // 184320 B

__global__ __launch_bounds__(256) void attn_tc() {
    extern __shared__ uint32_t sm[];
    const int bh   = blockIdx.y;
    const int b    = bh >> 3, h = bh & 7;
    const int wg   = threadIdx.x >> 7;
    const int qt   = wg ? (15 - blockIdx.x) : blockIdx.x;
    const int tid  = threadIdx.x & 127;
    const int w    = tid >> 5;
    const int lane = tid & 31;
    const int g    = lane >> 2;
    const int tig  = lane & 3;
    uint32_t* smg  = sm + wg * AWG_U;
    const uint32_t sb = smem_u32(smg);

    auto issue = [&](int kt, int s) {
#pragma unroll
        for (int i = 0; i < 16; i++) {
            int a = i >> 2;
            int r = (i & 3) * 16 + (tid >> 3);
            int c = tid & 7;
            uint32_t dst = sb + (2 * AQS + s * ASTG + a * ATL + r * 36) * 4 + c * 16;
            const uint32_t* srcb;
            if      (a == 0) srcb = g_Kh + ((size_t)(bh << 10) + kt * 64 + r) * 32;
            else if (a == 1) srcb = g_Kl + ((size_t)(bh << 10) + kt * 64 + r) * 32;
            else if (a == 2) srcb = g_Vh + ((size_t)bh * 64 + r) * 512 + kt * 32;
            else             srcb = g_Vl + ((size_t)bh * 64 + r) * 512 + kt * 32;
            cpasync16(dst, (const char*)srcb + c * 16);
        }
    };
    issue(0, 0); cp_commit();

    {   // Q tiles into smem
        const uint32_t* qhsrc = g_Qh + ((size_t)(bh << 10) + qt * 64) * 32;
        const uint32_t* qlsrc = g_Ql + ((size_t)(bh << 10) + qt * 64) * 32;
#pragma unroll
        for (int j = 0; j < 4; j++) {
            int idx = tid + j * 128;
            int row = idx >> 3, po = (idx & 7) * 4;
            *(uint4*)&smg[row * 36 + po]       = *(const uint4*)(qhsrc + row * 32 + po);
            *(uint4*)&smg[AQS + row * 36 + po] = *(const uint4*)(qlsrc + row * 32 + po);
        }
    }
    WGBAR(wg);

    uint32_t qa[2][4][4];
#pragma unroll
    for (int hl = 0; hl < 2; hl++) {
        int qb = hl * AQS;
#pragma unroll
        for (int kb = 0; kb < 4; kb++) {
            qa[hl][kb][0] = smg[qb + (w * 16 + g)     * 36 + kb * 8 + tig];
            qa[hl][kb][1] = smg[qb + (w * 16 + g + 8) * 36 + kb * 8 + tig];
            qa[hl][kb][2] = smg[qb + (w * 16 + g)     * 36 + kb * 8 + 4 + tig];
            qa[hl][kb][3] = smg[qb + (w * 16 + g + 8) * 36 + kb * 8 + 4 + tig];
        }
    }

    // ldmatrix per-lane base: instr j loads mats (na=2j,h0),(2j,h1),(2j+1,h0),(2j+1,h1)
    const int li   = lane >> 3;
    const uint32_t lbase = (((li >> 1) * 8 + (lane & 7)) * 36 + (li & 1) * 4) * 4;

    float o[8][4];
#pragma unroll
    for (int a = 0; a < 8; a++)
#pragma unroll
        for (int q = 0; q < 4; q++) o[a][q] = 0.f;
    float m[2] = {-1e30f, -1e30f}, l[2] = {0.f, 0.f};

    for (int kt = 0; kt <= qt; kt++) {
        if (kt < qt) { issue(kt + 1, (kt + 1) & 1); cp_commit(); cp_wait<1>(); }
        else         { cp_wait<0>(); }
        WGBAR(wg);

        const uint32_t su = sb + (2 * AQS + (kt & 1) * ASTG) * 4;
        const uint32_t Khb = su,             Klb = su + ATL * 4;
        const uint32_t Vhb = su + 2*ATL*4,   Vlb = su + 3 * ATL * 4;

        float s[8][4];
#pragma unroll
        for (int a = 0; a < 8; a++)
#pragma unroll
            for (int q = 0; q < 4; q++) s[a][q] = 0.f;

        // ---- S = Qh*Kh + Qh*Kl + Ql*Kh ----
#pragma unroll
        for (int kb = 0; kb < 4; kb++) {
            uint32_t bb[4][4];
#pragma unroll
            for (int j = 0; j < 4; j++)
                ldm_x4(bb[j], Khb + lbase + (j * 576 + kb * 8) * 4);
#pragma unroll
            for (int j = 0; j < 4; j++) {
                mma16816(s[2*j],   qa[0][kb], &bb[j][0]);
                mma16816(s[2*j+1], qa[0][kb], &bb[j][2]);
            }
#pragma unroll
            for (int j = 0; j < 4; j++) {
                mma16816(s[2*j],   qa[1][kb], &bb[j][0]);
                mma16816(s[2*j+1], qa[1][kb], &bb[j][2]);
            }
#pragma unroll
            for (int j = 0; j < 4; j++)
                ldm_x4(bb[j], Klb + lbase + (j * 576 + kb * 8) * 4);
#pragma unroll
            for (int j = 0; j < 4; j++) {
                mma16816(s[2*j],   qa[0][kb], &bb[j][0]);
                mma16816(s[2*j+1], qa[0][kb], &bb[j][2]);
            }
        }

        if (kt == qt) {
            int r0 = w * 16 + g;
#pragma unroll
            for (int na = 0; na < 8; na++) {
                int c0 = na * 8 + 2 * tig;
                if (c0     > r0)     s[na][0] = -1e9f;
                if (c0 + 1 > r0)     s[na][1] = -1e9f;
                if (c0     > r0 + 8) s[na][2] = -1e9f;
                if (c0 + 1 > r0 + 8) s[na][3] = -1e9f;
            }
        }

#pragma unroll
        for (int ri = 0; ri < 2; ri++) {
            float mx = -1e30f;
#pragma unroll
            for (int a = 0; a < 8; a++)
                mx = fmaxf(mx, fmaxf(s[a][2 * ri], s[a][2 * ri + 1]));
            mx = fmaxf(mx, __shfl_xor_sync(0xffffffffu, mx, 1));
            mx = fmaxf(mx, __shfl_xor_sync(0xffffffffu, mx, 2));
            float mnew = fmaxf(m[ri], mx);
            float corr = __expf(m[ri] - mnew);
            float rs = 0.f;
#pragma unroll
            for (int a = 0; a < 8; a++) {
                float p0 = __expf(s[a][2 * ri]     - mnew);
                float p1 = __expf(s[a][2 * ri + 1] - mnew);
                s[a][2 * ri] = p0; s[a][2 * ri + 1] = p1;
                rs += p0 + p1;
            }
            rs += __shfl_xor_sync(0xffffffffu, rs, 1);
            rs += __shfl_xor_sync(0xffffffffu, rs, 2);
            l[ri] = l[ri] * corr + rs;
            m[ri] = mnew;
#pragma unroll
            for (int a = 0; a < 8; a++) { o[a][2 * ri] *= corr; o[a][2 * ri + 1] *= corr; }
        }

        // ---- O += Ph*Vh + Pl*Vh + Ph*Vl ----
#pragma unroll
        for (int kb = 0; kb < 4; kb++) {
            uint32_t ph[4], pl[4];
            ph[0] = packbf(s[2*kb][0],   s[2*kb][1]);
            ph[1] = packbf(s[2*kb][2],   s[2*kb][3]);
            ph[2] = packbf(s[2*kb+1][0], s[2*kb+1][1]);
            ph[3] = packbf(s[2*kb+1][2], s[2*kb+1][3]);
            pl[0] = packres(ph[0], s[2*kb][0],   s[2*kb][1]);
            pl[1] = packres(ph[1], s[2*kb][2],   s[2*kb][3]);
            pl[2] = packres(ph[2], s[2*kb+1][0], s[2*kb+1][1]);
            pl[3] = packres(ph[3], s[2*kb+1][2], s[2*kb+1][3]);

            uint32_t bb[4][4];
#pragma unroll
            for (int j = 0; j < 4; j++)
                ldm_x4(bb[j], Vhb + lbase + (j * 576 + kb * 8) * 4);
#pragma unroll
            for (int j = 0; j < 4; j++) {
                mma16816(o[2*j],   ph, &bb[j][0]);
                mma16816(o[2*j+1], ph, &bb[j][2]);
            }
#pragma unroll
            for (int j = 0; j < 4; j++) {
                mma16816(o[2*j],   pl, &bb[j][0]);
                mma16816(o[2*j+1], pl, &bb[j][2]);
            }
#pragma unroll
            for (int j = 0; j < 4; j++)
                ldm_x4(bb[j], Vlb + lbase + (j * 576 + kb * 8) * 4);
#pragma unroll
            for (int j = 0; j < 4; j++) {
                mma16816(o[2*j],   ph, &bb[j][0]);
                mma16816(o[2*j+1], ph, &bb[j][2]);
            }
        }
        WGBAR(wg);
    }

    float inv0 = 1.0f / l[0], inv1 = 1.0f / l[1];
    int row0 = qt * 64 + w * 16 + g;
#pragma unroll
    for (int na = 0; na < 8; na++) {
        int col = h * 64 + na * 8 + 2 * tig;
        *(float2*)(g_O + (size_t)(b * 1024 + row0)     * HS + col) = make_float2(o[na][0] * inv0, o[na][1] * inv0);
        *(float2*)(g_O + (size_t)(b * 1024 + row0 + 8) * HS + col) = make_float2(o[na][2] * inv1, o[na][3] * inv1);
    }
}

// ---------------- A2 = split(sd * o) -----------------------------------------
__global__ __launch_bounds__(256) void build_a2() {
    int gid = blockIdx.x * 256 + threadIdx.x;
    int col = gid % V2;
    int bt  = gid / V2;
    int he  = col >> 6;
    int c   = col & 63;
    int h   = he / Ee;
    float a = g_sdg[bt * HE + he] * g_O[(size_t)bt * HS + h * 64 + c];
    __nv_bfloat16 hi, lo; split_bf16(a, hi, lo);
    __nv_bfloat16* p = g_A2 + (size_t)bt * K2 + col;
    p[0] = hi; p[V2] = hi; p[2 * V2] = lo;
}

// ---------------- launch ------------------------------------------------------
extern "C" void kernel_launch(void* const* d_in, const int* in_sizes, int n_in,
                              void* d_out, int out_size)
{
    const float* x  = (const float*)d_in[0];
    const float* Wq = (const float*)d_in[1];
    const float* Wk = (const float*)d_in[2];
    const float* Wv = (const float*)d_in[3];
    const float* Ws = (const float*)d_in[4];
    const float* Wd = (const float*)d_in[5];
    const float* Wo = (const float*)d_in[6];
    float* out = (float*)d_out;

    cudaFuncSetAttribute(gemm1,   cudaFuncAttributeMaxDynamicSharedMemorySize, GEMM1_SMEM);
    cudaFuncSetAttribute(gemm2,   cudaFuncAttributeMaxDynamicSharedMemorySize, GEMM2_SMEM);
    cudaFuncSetAttribute(attn_tc, cudaFuncAttributeMaxDynamicSharedMemorySize, ATTN_SMEM);

    prep_a1   <<<BT * DIMD / 256, 256>>>(x);
    prep_b1   <<<dim3(32, 120), dim3(32, 8)>>>(Wq, Wk, Wv, Ws, Wd);
    prep_b2   <<<HE * DIMD * 64 / 256, 256>>>(Wo);
    gemm1     <<<dim3(N1 / 128, BT / 128), 256, GEMM1_SMEM>>>();
    route_pack<<<16 * 512 * 64 / 256, 256>>>();
    prep_qk   <<<16 * 1024 * 32 / 256, 256>>>();
    attn_tc   <<<dim3(8, 16), 256, ATTN_SMEM>>>();
    build_a2  <<<BT * V2 / 256, 256>>>();
    gemm2     <<<dim3(N2 / 64, BT / 128), 256, GEMM2_SMEM>>>(out);
}

// round 7
// speedup vs baseline: 3.1395x; 1.0295x over previous
#include <cuda_runtime.h>
#include <cuda_bf16.h>
#include <cstdint>

#define Tt   1024
#define DIMD 1024
#define Hh   8
#define Ee   5
#define KK   3
#define BT   2048
#define HS   512
#define HE   40
#define QSCALE 0.125f

#define N1 3840      // fused projection width (Q512|K512|V2560|Ss40|Sd40|pad48)
#define N2 1024
#define V2 2560

// ---------------- scratch ----------------------------------------------------
__device__ float g_C1 [BT * N1];
// split operand blobs (element offsets within blob)
#define A1H 0
#define A1L (BT * 1024)
#define B1H (2 * BT * 1024)
#define B1L (2 * BT * 1024 + N1 * 1024)
__device__ __nv_bfloat16 g_W1[2 * BT * 1024 + 2 * N1 * 1024];
#define A2H 0
#define A2L (BT * V2)
#define B2H (2 * BT * V2)
#define B2L (2 * BT * V2 + N2 * V2)
__device__ __nv_bfloat16 g_W2[2 * BT * V2 + 2 * N2 * V2];

__device__ float g_O  [BT * HS];
__device__ float g_sdg[BT * HE];
// attention operands, packed bf16x2 pairs
__device__ uint32_t g_Qh[16 * 1024 * 32];   // [bh][t][dpair]
__device__ uint32_t g_Ql[16 * 1024 * 32];
__device__ uint32_t g_Kh[16 * 1024 * 32];   // [bh][t][dpair]
__device__ uint32_t g_Kl[16 * 1024 * 32];
__device__ uint32_t g_Vh[16 * 64 * 512];    // [bh][d][tpair]
__device__ uint32_t g_Vl[16 * 64 * 512];

// ---------------- helpers -----------------------------------------------------
__device__ __forceinline__ uint32_t smem_u32(const void* p) {
    uint32_t a;
    asm("{ .reg .u64 t; cvta.to.shared.u64 t, %1; cvt.u32.u64 %0, t; }" : "=r"(a) : "l"(p));
    return a;
}
__device__ __forceinline__ void cpasync16(uint32_t dst, const void* src) {
    asm volatile("cp.async.cg.shared.global [%0], [%1], 16;\n" :: "r"(dst), "l"(src));
}
__device__ __forceinline__ void cp_commit() { asm volatile("cp.async.commit_group;\n"); }
template<int N> __device__ __forceinline__ void cp_wait() { asm volatile("cp.async.wait_group %0;\n" :: "n"(N)); }

__device__ __forceinline__ void mma16816(float* c, const uint32_t* a, const uint32_t* b) {
    asm volatile(
        "mma.sync.aligned.m16n8k16.row.col.f32.bf16.bf16.f32 "
        "{%0,%1,%2,%3}, {%4,%5,%6,%7}, {%8,%9}, {%0,%1,%2,%3};"
        : "+f"(c[0]), "+f"(c[1]), "+f"(c[2]), "+f"(c[3])
        : "r"(a[0]), "r"(a[1]), "r"(a[2]), "r"(a[3]), "r"(b[0]), "r"(b[1]));
}
__device__ __forceinline__ void ldm_x4(uint32_t* r, uint32_t addr) {
    asm volatile("ldmatrix.sync.aligned.m8n8.x4.shared.b16 {%0,%1,%2,%3}, [%4];"
        : "=r"(r[0]), "=r"(r[1]), "=r"(r[2]), "=r"(r[3]) : "r"(addr));
}
__device__ __forceinline__ uint32_t packbf(float lo, float hi) {
    uint32_t r;
    asm("cvt.rn.bf16x2.f32 %0, %1, %2;" : "=r"(r) : "f"(hi), "f"(lo));
    return r;
}
__device__ __forceinline__ uint32_t packres(uint32_t p, float lo, float hi) {
    float plo = __uint_as_float(p << 16);
    float phi = __uint_as_float(p & 0xffff0000u);
    return packbf(lo - plo, hi - phi);
}
#define WGBAR(id) asm volatile("bar.sync %0, 128;" :: "r"((id) + 1) : "memory")

// ---------------- 3-term split GEMM with shared fragments --------------------
// C = Ah@Bh^T + Al@Bh^T + Ah@Bl^T  (fp32 acc). Arrays row-major [rows][KTOT] bf16.
// CTA tile 128 x NT, BK=32 (64B smem rows), swizzle: col16 ^= ((row>>1)&3)*16.
template<int NT, int KTOT>
__device__ __forceinline__ void gemm3_body(const char* __restrict__ W,
                                           uint32_t offAh, uint32_t offAl,
                                           uint32_t offBh, uint32_t offBl,
                                           float* __restrict__ C, int Ntot)
{
    constexpr int ROWS  = 256 + 2 * NT;     // Ah(128)|Al(128)|Bh(NT)|Bl(NT)
    constexpr int STAGE = ROWS * 64;
    constexpr int NSTEP = KTOT / 32;
    constexpr int NTW   = NT / 2;
    constexpr int NPAIR = NTW / 16;
    constexpr int NA    = NTW / 8;
    constexpr int CPT   = ROWS * 4 / 256;

    extern __shared__ char sm_raw[];
    const uint32_t sb = smem_u32(sm_raw);
    const int tid = threadIdx.x, wid = tid >> 5, lane = tid & 31;
    const int wm = wid & 3, wn = wid >> 2;
    const int m0 = blockIdx.y * 128, n0 = blockIdx.x * NT;

    uint32_t srcoff[CPT], dstoff[CPT];
#pragma unroll
    for (int i = 0; i < CPT; i++) {
        int cid = i * 256 + tid;
        int row = cid >> 2;
        int c   = (cid & 3) * 16;
        dstoff[i] = row * 64 + (c ^ (((row >> 1) & 3) * 16));
        uint32_t aoff; int gr;
        if      (row < 128)      { aoff = offAh; gr = m0 + row; }
        else if (row < 256)      { aoff = offAl; gr = m0 + row - 128; }
        else if (row < 256 + NT) { aoff = offBh; gr = n0 + row - 256; }
        else                     { aoff = offBl; gr = n0 + row - 256 - NT; }
        srcoff[i] = aoff + (uint32_t)gr * (KTOT * 2) + c;
    }

    const uint32_t ahi = (lane >> 4) * 16;
    const uint32_t bhi = ((lane >> 3) & 1) * 16;
    uint32_t aof[2], aswz[2], bof[NPAIR], bswz[NPAIR];
#pragma unroll
    for (int mi = 0; mi < 2; mi++) {
        int r = wm * 32 + mi * 16 + (lane & 15);
        aof[mi] = r * 64; aswz[mi] = ((r >> 1) & 3) * 16;
    }
#pragma unroll
    for (int pj = 0; pj < NPAIR; pj++) {
        int r = wn * NTW + pj * 16 + ((lane >> 4) << 3) + (lane & 7);
        bof[pj] = (256 + r) * 64; bswz[pj] = ((r >> 1) & 3) * 16;
    }

    float acc[2][NA][4];
#pragma unroll
    for (int mi = 0; mi < 2; mi++)
#pragma unroll
        for (int na = 0; na < NA; na++)
#pragma unroll
            for (int q = 0; q < 4; q++) acc[mi][na][q] = 0.f;

    auto issue = [&](int kt, int slot) {
        uint32_t st = sb + slot * STAGE;
        const char* gk = W + (size_t)kt * 64;
#pragma unroll
        for (int i = 0; i < CPT; i++)
            cpasync16(st + dstoff[i], gk + srcoff[i]);
    };

    issue(0, 0); cp_commit();
    issue(1, 1); cp_commit();

    for (int kt = 0; kt < NSTEP; kt++) {
        if (kt + 1 < NSTEP) cp_wait<1>(); else cp_wait<0>();
        __syncthreads();
        if (kt + 2 < NSTEP) { issue(kt + 2, (kt + 2) % 3); cp_commit(); }

        uint32_t stg = sb + (kt % 3) * STAGE;
#pragma unroll
        for (int ks = 0; ks < 2; ks++) {
            const uint32_t ca = (uint32_t)ks * 32 + ahi;
            const uint32_t cb = (uint32_t)ks * 32 + bhi;
            uint32_t ah[2][4], al[2][4], bb[NPAIR][4];
            ldm_x4(ah[0], stg + aof[0] + (ca ^ aswz[0]));
            ldm_x4(ah[1], stg + aof[1] + (ca ^ aswz[1]));
            ldm_x4(al[0], stg + 8192 + aof[0] + (ca ^ aswz[0]));
            ldm_x4(al[1], stg + 8192 + aof[1] + (ca ^ aswz[1]));
#pragma unroll
            for (int pj = 0; pj < NPAIR; pj++)
                ldm_x4(bb[pj], stg + bof[pj] + (cb ^ bswz[pj]));
            // term 1: Ah*Bh ; term 2: Al*Bh (share bb)
#pragma unroll
            for (int mi = 0; mi < 2; mi++)
#pragma unroll
                for (int pj = 0; pj < NPAIR; pj++) {
                    mma16816(acc[mi][2 * pj],     ah[mi], &bb[pj][0]);
                    mma16816(acc[mi][2 * pj + 1], ah[mi], &bb[pj][2]);
                }
#pragma unroll
            for (int mi = 0; mi < 2; mi++)
#pragma unroll
                for (int pj = 0; pj < NPAIR; pj++) {
                    mma16816(acc[mi][2 * pj],     al[mi], &bb[pj][0]);
                    mma16816(acc[mi][2 * pj + 1], al[mi], &bb[pj][2]);
                }
            // term 3: Ah*Bl (reload bb from Bl region)
#pragma unroll
            for (int pj = 0; pj < NPAIR; pj++)
                ldm_x4(bb[pj], stg + bof[pj] + NT * 64 + (cb ^ bswz[pj]));
#pragma unroll
            for (int mi = 0; mi < 2; mi++)
#pragma unroll
                for (int pj = 0; pj < NPAIR; pj++) {
                    mma16816(acc[mi][2 * pj],     ah[mi], &bb[pj][0]);
                    mma16816(acc[mi][2 * pj + 1], ah[mi], &bb[pj][2]);
                }
        }
    }

    const int g  = lane >> 2;
    const int tg = lane & 3;
#pragma unroll
    for (int mi = 0; mi < 2; mi++) {
        int r0 = m0 + wm * 32 + mi * 16 + g;
#pragma unroll
        for (int na = 0; na < NA; na++) {
            int cc = n0 + wn * NTW + na * 8 + tg * 2;
            *(float2*)(C + (size_t)r0 * Ntot + cc)       = make_float2(acc[mi][na][0], acc[mi][na][1]);
            *(float2*)(C + (size_t)(r0 + 8) * Ntot + cc) = make_float2(acc[mi][na][2], acc[mi][na][3]);
        }
    }
}

#define GEMM1_SMEM (3 * (256 + 256) * 64)   // 98304
#define GEMM2_SMEM (3 * (256 + 128) * 64)   // 73728

__global__ __launch_bounds__(256, 2)
void gemm1() {
    gemm3_body<128, 1024>((const char*)g_W1, A1H * 2, A1L * 2, B1H * 2, B1L * 2, g_C1, N1);
}
__global__ __launch_bounds__(256, 2)
void gemm2(float* __restrict__ out) {
    gemm3_body<64, 2560>((const char*)g_W2, A2H * 2, A2L * 2, B2H * 2, B2L * 2, out, N2);
}

// ---------------- prep kernels ----------------------------------------------
__device__ __forceinline__ void split_bf16(float v, __nv_bfloat16& hi, __nv_bfloat16& lo) {
    hi = __float2bfloat16(v);
    lo = __float2bfloat16(v - __bfloat162float(hi));
}

__global__ __launch_bounds__(256) void prep_a1(const float* __restrict__ x) {
    int gid = blockIdx.x * 256 + threadIdx.x;          // BT*1024
    __nv_bfloat16 hi, lo; split_bf16(x[gid], hi, lo);
    g_W1[A1H + gid] = hi;
    g_W1[A1L + gid] = lo;
}

__global__ void prep_b1(const float* __restrict__ Wq, const float* __restrict__ Wk,
                        const float* __restrict__ Wv, const float* __restrict__ Ws,
                        const float* __restrict__ Wd)
{
    __shared__ float tile[32][33];
    int k0 = blockIdx.x * 32;
    int n0 = blockIdx.y * 32;
    int tx = threadIdx.x, ty = threadIdx.y;
#pragma unroll
    for (int yy = 0; yy < 32; yy += 8) {
        int k = k0 + ty + yy, n = n0 + tx;
        float w;
        if      (n < 512)  w = Wq[(size_t)k * 512  + n];
        else if (n < 1024) w = Wk[(size_t)k * 512  + n - 512];
        else if (n < 3584) w = Wv[(size_t)k * 2560 + n - 1024];
        else if (n < 3624) w = Ws[(size_t)k * 40   + n - 3584];
        else if (n < 3664) w = Wd[(size_t)k * 40   + n - 3624];
        else               w = 0.f;
        tile[ty + yy][tx] = w;
    }
    __syncthreads();
#pragma unroll
    for (int yy = 0; yy < 32; yy += 8) {
        int n = n0 + ty + yy, k = k0 + tx;
        __nv_bfloat16 hi, lo; split_bf16(tile[tx][ty + yy], hi, lo);
        int idx = n * 1024 + k;
        g_W1[B1H + idx] = hi;
        g_W1[B1L + idx] = lo;
    }
}

__global__ __launch_bounds__(256) void prep_b2(const float* __restrict__ Wo) {
    int gid = blockIdx.x * 256 + threadIdx.x;          // 40*1024*64
    int he = gid >> 16;
    int d  = (gid >> 6) & 1023;
    int c  = gid & 63;
    __nv_bfloat16 hi, lo; split_bf16(Wo[gid], hi, lo);
    int idx = d * V2 + he * 64 + c;
    g_W2[B2H + idx] = hi;
    g_W2[B2L + idx] = lo;
}

// ---------------- fused routing gates + expert V mix + transposed pack -------
__global__ __launch_bounds__(256) void route_pack() {
    __shared__ uint32_t tvh[4][65], tvl[4][65];
    int gid = blockIdx.x * 256 + threadIdx.x;   // 16*512*64, d fastest
    int d  = gid & 63;
    int kp = (gid >> 6) & 511;
    int bh = gid >> 15;
    int b = bh >> 3, h = bh & 7;

    float v[2];
#pragma unroll
    for (int u = 0; u < 2; u++) {
        int t = kp * 2 + u;
        const float* row = g_C1 + (size_t)(b * 1024 + t) * N1;
        const float* sl = row + 3584 + h * Ee;
        float s[Ee];
#pragma unroll
        for (int e = 0; e < Ee; e++) s[e] = sl[e];
        float acc = 0.f;
#pragma unroll
        for (int e = 0; e < Ee; e++) {
            int rank = 0;
#pragma unroll
            for (int j = 0; j < Ee; j++)
                rank += (s[j] > s[e]) || (s[j] == s[e] && j < e);
            float gate = (rank < KK) ? 1.0f / (1.0f + expf(-s[e])) : 0.f;
            acc = fmaf(gate, row[1024 + (h * Ee + e) * 64 + d], acc);
        }
        v[u] = acc;

        if (d < Ee) {
            const float* dl = row + 3624 + h * Ee;
            float tq[Ee];
#pragma unroll
            for (int e = 0; e < Ee; e++) tq[e] = dl[e];
            int e = d, rank = 0;
#pragma unroll
            for (int j = 0; j < Ee; j++)
                rank += (tq[j] > tq[e]) || (tq[j] == tq[e] && j < e);
            g_sdg[(b * 1024 + t) * HE + h * Ee + e] = (rank < KK) ? 1.f : 0.f;
        }
    }
    uint32_t vh = packbf(v[0], v[1]);
    tvh[kp & 3][d] = vh;
    tvl[kp & 3][d] = packres(vh, v[0], v[1]);
    __syncthreads();
    int td  = threadIdx.x >> 2;
    int tk4 = threadIdx.x & 3;
    int kp0 = (blockIdx.x * 4) & 511;
    size_t oidx = ((size_t)bh * 64 + td) * 512 + kp0 + tk4;
    g_Vh[oidx] = tvh[tk4][td];
    g_Vl[oidx] = tvl[tk4][td];
}

// ---------------- attention operand prep --------------------------------------
__global__ __launch_bounds__(256) void prep_qk() {
    int gid = blockIdx.x * 256 + threadIdx.x;   // 16*1024*32
    int p  = gid & 31;
    int t  = (gid >> 5) & 1023;
    int bh = gid >> 15;
    int b = bh >> 3, h = bh & 7;
    const float* row = g_C1 + (size_t)(b * 1024 + t) * N1;

    float q0 = row[h * 64 + 2 * p]     * QSCALE;
    float q1 = row[h * 64 + 2 * p + 1] * QSCALE;
    uint32_t qh = packbf(q0, q1);
    g_Qh[gid] = qh;
    g_Ql[gid] = packres(qh, q0, q1);

    float k0 = row[512 + h * 64 + 2 * p];
    float k1 = row[512 + h * 64 + 2 * p + 1];
    uint32_t kh = packbf(k0, k1);
    g_Kh[gid] = kh;
    g_Kl[gid] = packres(kh, k0, k1);
}

// ---------------- tensor-core causal flash attention, paired q-tiles ---------
#define AQS   (64 * 36)
#define ATL   (64 * 36)
#define ASTG  (4 * ATL)
#define AWG_U (2 * AQS + 2 * ASTG)
#define ATTN_SMEM (2 * AWG_U * 4)

__global__ __launch_bounds__(256) void attn_tc() {
    extern __shared__ uint32_t sm[];
    const int bh   = blockIdx.y;
    const int b    = bh >> 3, h = bh & 7;
    const int wg   = threadIdx.x >> 7;
    const int qt   = wg ? (15 - blockIdx.x) : blockIdx.x;
    const int tid  = threadIdx.x & 127;
    const int w    = tid >> 5;
    const int lane = tid & 31;
    const int g    = lane >> 2;
    const int tig  = lane & 3;
    uint32_t* smg  = sm + wg * AWG_U;
    const uint32_t sb = smem_u32(smg);

    auto issue = [&](int kt, int s) {
#pragma unroll
        for (int i = 0; i < 16; i++) {
            int a = i >> 2;
            int r = (i & 3) * 16 + (tid >> 3);
            int c = tid & 7;
            uint32_t dst = sb + (2 * AQS + s * ASTG + a * ATL + r * 36) * 4 + c * 16;
            const uint32_t* srcb;
            if      (a == 0) srcb = g_Kh + ((size_t)(bh << 10) + kt * 64 + r) * 32;
            else if (a == 1) srcb = g_Kl + ((size_t)(bh << 10) + kt * 64 + r) * 32;
            else if (a == 2) srcb = g_Vh + ((size_t)bh * 64 + r) * 512 + kt * 32;
            else             srcb = g_Vl + ((size_t)bh * 64 + r) * 512 + kt * 32;
            cpasync16(dst, (const char*)srcb + c * 16);
        }
    };
    issue(0, 0); cp_commit();

    {
        const uint32_t* qhsrc = g_Qh + ((size_t)(bh << 10) + qt * 64) * 32;
        const uint32_t* qlsrc = g_Ql + ((size_t)(bh << 10) + qt * 64) * 32;
#pragma unroll
        for (int j = 0; j < 4; j++) {
            int idx = tid + j * 128;
            int row = idx >> 3, po = (idx & 7) * 4;
            *(uint4*)&smg[row * 36 + po]       = *(const uint4*)(qhsrc + row * 32 + po);
            *(uint4*)&smg[AQS + row * 36 + po] = *(const uint4*)(qlsrc + row * 32 + po);
        }
    }
    WGBAR(wg);

    uint32_t qa[2][4][4];
#pragma unroll
    for (int hl = 0; hl < 2; hl++) {
        int qb = hl * AQS;
#pragma unroll
        for (int kb = 0; kb < 4; kb++) {
            qa[hl][kb][0] = smg[qb + (w * 16 + g)     * 36 + kb * 8 + tig];
            qa[hl][kb][1] = smg[qb + (w * 16 + g + 8) * 36 + kb * 8 + tig];
            qa[hl][kb][2] = smg[qb + (w * 16 + g)     * 36 + kb * 8 + 4 + tig];
            qa[hl][kb][3] = smg[qb + (w * 16 + g + 8) * 36 + kb * 8 + 4 + tig];
        }
    }

    const int li   = lane >> 3;
    const uint32_t lbase = (((li >> 1) * 8 + (lane & 7)) * 36 + (li & 1) * 4) * 4;

    float o[8][4];
#pragma unroll
    for (int a = 0; a < 8; a++)
#pragma unroll
        for (int q = 0; q < 4; q++) o[a][q] = 0.f;
    float m[2] = {-1e30f, -1e30f}, l[2] = {0.f, 0.f};

    for (int kt = 0; kt <= qt; kt++) {
        if (kt < qt) { issue(kt + 1, (kt + 1) & 1); cp_commit(); cp_wait<1>(); }
        else         { cp_wait<0>(); }
        WGBAR(wg);

        const uint32_t su = sb + (2 * AQS + (kt & 1) * ASTG) * 4;
        const uint32_t Khb = su,              Klb = su + ATL * 4;
        const uint32_t Vhb = su + 2 * ATL * 4, Vlb = su + 3 * ATL * 4;

        float s[8][4];
#pragma unroll
        for (int a = 0; a < 8; a++)
#pragma unroll
            for (int q = 0; q < 4; q++) s[a][q] = 0.f;

#pragma unroll
        for (int kb = 0; kb < 4; kb++) {
            uint32_t bb[4][4];
#pragma unroll
            for (int j = 0; j < 4; j++)
                ldm_x4(bb[j], Khb + lbase + (j * 576 + kb * 8) * 4);
#pragma unroll
            for (int j = 0; j < 4; j++) {
                mma16816(s[2*j],   qa[0][kb], &bb[j][0]);
                mma16816(s[2*j+1], qa[0][kb], &bb[j][2]);
            }
#pragma unroll
            for (int j = 0; j < 4; j++) {
                mma16816(s[2*j],   qa[1][kb], &bb[j][0]);
                mma16816(s[2*j+1], qa[1][kb], &bb[j][2]);
            }
#pragma unroll
            for (int j = 0; j < 4; j++)
                ldm_x4(bb[j], Klb + lbase + (j * 576 + kb * 8) * 4);
#pragma unroll
            for (int j = 0; j < 4; j++) {
                mma16816(s[2*j],   qa[0][kb], &bb[j][0]);
                mma16816(s[2*j+1], qa[0][kb], &bb[j][2]);
            }
        }

        if (kt == qt) {
            int r0 = w * 16 + g;
#pragma unroll
            for (int na = 0; na < 8; na++) {
                int c0 = na * 8 + 2 * tig;
                if (c0     > r0)     s[na][0] = -1e9f;
                if (c0 + 1 > r0)     s[na][1] = -1e9f;
                if (c0     > r0 + 8) s[na][2] = -1e9f;
                if (c0 + 1 > r0 + 8) s[na][3] = -1e9f;
            }
        }

#pragma unroll
        for (int ri = 0; ri < 2; ri++) {
            float mx = -1e30f;
#pragma unroll
            for (int a = 0; a < 8; a++)
                mx = fmaxf(mx, fmaxf(s[a][2 * ri], s[a][2 * ri + 1]));
            mx = fmaxf(mx, __shfl_xor_sync(0xffffffffu, mx, 1));
            mx = fmaxf(mx, __shfl_xor_sync(0xffffffffu, mx, 2));
            float mnew = fmaxf(m[ri], mx);
            float corr = __expf(m[ri] - mnew);
            float rs = 0.f;
#pragma unroll
            for (int a = 0; a < 8; a++) {
                float p0 = __expf(s[a][2 * ri]     - mnew);
                float p1 = __expf(s[a][2 * ri + 1] - mnew);
                s[a][2 * ri] = p0; s[a][2 * ri + 1] = p1;
                rs += p0 + p1;
            }
            rs += __shfl_xor_sync(0xffffffffu, rs, 1);
            rs += __shfl_xor_sync(0xffffffffu, rs, 2);
            l[ri] = l[ri] * corr + rs;
            m[ri] = mnew;
#pragma unroll
            for (int a = 0; a < 8; a++) { o[a][2 * ri] *= corr; o[a][2 * ri + 1] *= corr; }
        }

#pragma unroll
        for (int kb = 0; kb < 4; kb++) {
            uint32_t ph[4], pl[4];
            ph[0] = packbf(s[2*kb][0],   s[2*kb][1]);
            ph[1] = packbf(s[2*kb][2],   s[2*kb][3]);
            ph[2] = packbf(s[2*kb+1][0], s[2*kb+1][1]);
            ph[3] = packbf(s[2*kb+1][2], s[2*kb+1][3]);
            pl[0] = packres(ph[0], s[2*kb][0],   s[2*kb][1]);
            pl[1] = packres(ph[1], s[2*kb][2],   s[2*kb][3]);
            pl[2] = packres(ph[2], s[2*kb+1][0], s[2*kb+1][1]);
            pl[3] = packres(ph[3], s[2*kb+1][2], s[2*kb+1][3]);

            uint32_t bb[4][4];
#pragma unroll
            for (int j = 0; j < 4; j++)
                ldm_x4(bb[j], Vhb + lbase + (j * 576 + kb * 8) * 4);
#pragma unroll
            for (int j = 0; j < 4; j++) {
                mma16816(o[2*j],   ph, &bb[j][0]);
                mma16816(o[2*j+1], ph, &bb[j][2]);
            }
#pragma unroll
            for (int j = 0; j < 4; j++) {
                mma16816(o[2*j],   pl, &bb[j][0]);
                mma16816(o[2*j+1], pl, &bb[j][2]);
            }
#pragma unroll
            for (int j = 0; j < 4; j++)
                ldm_x4(bb[j], Vlb + lbase + (j * 576 + kb * 8) * 4);
#pragma unroll
            for (int j = 0; j < 4; j++) {
                mma16816(o[2*j],   ph, &bb[j][0]);
                mma16816(o[2*j+1], ph, &bb[j][2]);
            }
        }
        WGBAR(wg);
    }

    float inv0 = 1.0f / l[0], inv1 = 1.0f / l[1];
    int row0 = qt * 64 + w * 16 + g;
#pragma unroll
    for (int na = 0; na < 8; na++) {
        int col = h * 64 + na * 8 + 2 * tig;
        *(float2*)(g_O + (size_t)(b * 1024 + row0)     * HS + col) = make_float2(o[na][0] * inv0, o[na][1] * inv0);
        *(float2*)(g_O + (size_t)(b * 1024 + row0 + 8) * HS + col) = make_float2(o[na][2] * inv1, o[na][3] * inv1);
    }
}

// ---------------- A2 = split(sd * o) -----------------------------------------
__global__ __launch_bounds__(256) void build_a2() {
    int gid = blockIdx.x * 256 + threadIdx.x;
    int col = gid % V2;
    int bt  = gid / V2;
    int he  = col >> 6;
    int c   = col & 63;
    int h   = he / Ee;
    float a = g_sdg[bt * HE + he] * g_O[(size_t)bt * HS + h * 64 + c];
    __nv_bfloat16 hi, lo; split_bf16(a, hi, lo);
    g_W2[A2H + gid] = hi;
    g_W2[A2L + gid] = lo;
}

// ---------------- launch ------------------------------------------------------
extern "C" void kernel_launch(void* const* d_in, const int* in_sizes, int n_in,
                              void* d_out, int out_size)
{
    const float* x  = (const float*)d_in[0];
    const float* Wq = (const float*)d_in[1];
    const float* Wk = (const float*)d_in[2];
    const float* Wv = (const float*)d_in[3];
    const float* Ws = (const float*)d_in[4];
    const float* Wd = (const float*)d_in[5];
    const float* Wo = (const float*)d_in[6];
    float* out = (float*)d_out;

    cudaFuncSetAttribute(gemm1,   cudaFuncAttributeMaxDynamicSharedMemorySize, GEMM1_SMEM);
    cudaFuncSetAttribute(gemm2,   cudaFuncAttributeMaxDynamicSharedMemorySize, GEMM2_SMEM);
    cudaFuncSetAttribute(attn_tc, cudaFuncAttributeMaxDynamicSharedMemorySize, ATTN_SMEM);

    prep_a1   <<<BT * DIMD / 256, 256>>>(x);
    prep_b1   <<<dim3(32, 120), dim3(32, 8)>>>(Wq, Wk, Wv, Ws, Wd);
    prep_b2   <<<HE * DIMD * 64 / 256, 256>>>(Wo);
    gemm1     <<<dim3(N1 / 128, BT / 128), 256, GEMM1_SMEM>>>();
    route_pack<<<16 * 512 * 64 / 256, 256>>>();
    prep_qk   <<<16 * 1024 * 32 / 256, 256>>>();
    attn_tc   <<<dim3(8, 16), 256, ATTN_SMEM>>>();
    build_a2  <<<BT * V2 / 256, 256>>>();
    gemm2     <<<dim3(N2 / 64, BT / 128), 256, GEMM2_SMEM>>>(out);
}

// round 8
// speedup vs baseline: 3.2000x; 1.0193x over previous
#include <cuda_runtime.h>
#include <cuda_bf16.h>
#include <cstdint>

#define Tt   1024
#define DIMD 1024
#define Hh   8
#define Ee   5
#define KK   3
#define BT   2048
#define HS   512
#define HE   40
#define QSCALE 0.125f

#define N1 3840
#define N2 1024
#define V2 2560

// ---------------- scratch ----------------------------------------------------
__device__ float g_C1 [BT * N1];
#define A1H 0
#define A1L (BT * 1024)
#define B1H (2 * BT * 1024)
#define B1L (2 * BT * 1024 + N1 * 1024)
__device__ __nv_bfloat16 g_W1[2 * BT * 1024 + 2 * N1 * 1024];
#define A2H 0
#define A2L (BT * V2)
#define B2H (2 * BT * V2)
#define B2L (2 * BT * V2 + N2 * V2)
__device__ __nv_bfloat16 g_W2[2 * BT * V2 + 2 * N2 * V2];

__device__ float g_sdg[BT * HE];
__device__ uint32_t g_Qh[16 * 1024 * 32];
__device__ uint32_t g_Ql[16 * 1024 * 32];
__device__ uint32_t g_Kh[16 * 1024 * 32];
__device__ uint32_t g_Kl[16 * 1024 * 32];
__device__ uint32_t g_Vh[16 * 64 * 512];
__device__ uint32_t g_Vl[16 * 64 * 512];

// ---------------- helpers -----------------------------------------------------
__device__ __forceinline__ uint32_t smem_u32(const void* p) {
    uint32_t a;
    asm("{ .reg .u64 t; cvta.to.shared.u64 t, %1; cvt.u32.u64 %0, t; }" : "=r"(a) : "l"(p));
    return a;
}
__device__ __forceinline__ void cpasync16(uint32_t dst, const void* src) {
    asm volatile("cp.async.cg.shared.global [%0], [%1], 16;\n" :: "r"(dst), "l"(src));
}
__device__ __forceinline__ void cp_commit() { asm volatile("cp.async.commit_group;\n"); }
template<int N> __device__ __forceinline__ void cp_wait() { asm volatile("cp.async.wait_group %0;\n" :: "n"(N)); }

__device__ __forceinline__ void mma16816(float* c, const uint32_t* a, const uint32_t* b) {
    asm volatile(
        "mma.sync.aligned.m16n8k16.row.col.f32.bf16.bf16.f32 "
        "{%0,%1,%2,%3}, {%4,%5,%6,%7}, {%8,%9}, {%0,%1,%2,%3};"
        : "+f"(c[0]), "+f"(c[1]), "+f"(c[2]), "+f"(c[3])
        : "r"(a[0]), "r"(a[1]), "r"(a[2]), "r"(a[3]), "r"(b[0]), "r"(b[1]));
}
__device__ __forceinline__ void ldm_x4(uint32_t* r, uint32_t addr) {
    asm volatile("ldmatrix.sync.aligned.m8n8.x4.shared.b16 {%0,%1,%2,%3}, [%4];"
        : "=r"(r[0]), "=r"(r[1]), "=r"(r[2]), "=r"(r[3]) : "r"(addr));
}
__device__ __forceinline__ uint32_t packbf(float lo, float hi) {
    uint32_t r;
    asm("cvt.rn.bf16x2.f32 %0, %1, %2;" : "=r"(r) : "f"(hi), "f"(lo));
    return r;
}
__device__ __forceinline__ uint32_t packres(uint32_t p, float lo, float hi) {
    float plo = __uint_as_float(p << 16);
    float phi = __uint_as_float(p & 0xffff0000u);
    return packbf(lo - plo, hi - phi);
}
#define WGBAR(id) asm volatile("bar.sync %0, 128;" :: "r"((id) + 1) : "memory")

// ---------------- 3-term split GEMM with shared fragments --------------------
// C = Ah@Bh^T + Al@Bh^T + Ah@Bl^T (fp32 acc). Row-major [rows][KTOT] bf16.
// CTA tile 128 x NT, BK=32 (64B rows), swizzle: col16 ^= ((row>>1)&3)*16.
template<int NT, int KTOT>
__device__ __forceinline__ void gemm3_body(const char* __restrict__ W,
                                           uint32_t offAh, uint32_t offAl,
                                           uint32_t offBh, uint32_t offBl,
                                           float* __restrict__ C, int Ntot)
{
    constexpr int ROWS  = 256 + 2 * NT;
    constexpr int STAGE = ROWS * 64;
    constexpr int NSTEP = KTOT / 32;
    constexpr int NTW   = NT / 2;
    constexpr int NPAIR = NTW / 16;
    constexpr int NA    = NTW / 8;
    constexpr int CPT   = ROWS / 64;
    constexpr int NB    = NT / 64;      // Bh chunk count
    constexpr size_t K2B = KTOT * 2;

    extern __shared__ char sm_raw[];
    const uint32_t sb = smem_u32(sm_raw);
    const int tid = threadIdx.x, wid = tid >> 5, lane = tid & 31;
    const int wm = wid & 3, wn = wid >> 2;
    const int m0 = blockIdx.y * 128, n0 = blockIdx.x * NT;

    // cp.async: region base pointers (no per-chunk arrays -> fewer regs)
    const int r0 = tid >> 2;                 // 0..63
    const int cc = (tid & 3) * 16;
    const uint32_t dst0 = r0 * 64 + (cc ^ (((r0 >> 1) & 3) * 16));
    const char* pAh = W + offAh + (size_t)(m0 + r0) * K2B + cc;
    const char* pAl = W + offAl + (size_t)(m0 + r0) * K2B + cc;
    const char* pBh = W + offBh + (size_t)(n0 + r0) * K2B + cc;
    const char* pBl = W + offBl + (size_t)(n0 + r0) * K2B + cc;

    auto issue = [&](int kt, int slot) {
        const uint32_t st = sb + slot * STAGE + dst0;
        const size_t gk = (size_t)kt * 64;
#pragma unroll
        for (int i = 0; i < CPT; i++) {
            const char* src;
            if      (i < 2)      src = pAh + (size_t)i * (64 * K2B);
            else if (i < 4)      src = pAl + (size_t)(i - 2) * (64 * K2B);
            else if (i < 4 + NB) src = pBh + (size_t)(i - 4) * (64 * K2B);
            else                 src = pBl + (size_t)(i - 4 - NB) * (64 * K2B);
            cpasync16(st + i * 4096, src + gk);
        }
    };

    const uint32_t ahi = (lane >> 4) * 16;
    const uint32_t bhi = ((lane >> 3) & 1) * 16;
    uint32_t aof[2], aswz[2], bof[NPAIR], bswz[NPAIR];
#pragma unroll
    for (int mi = 0; mi < 2; mi++) {
        int r = wm * 32 + mi * 16 + (lane & 15);
        aof[mi] = r * 64; aswz[mi] = ((r >> 1) & 3) * 16;
    }
#pragma unroll
    for (int pj = 0; pj < NPAIR; pj++) {
        int r = wn * NTW + pj * 16 + ((lane >> 4) << 3) + (lane & 7);
        bof[pj] = (256 + r) * 64; bswz[pj] = ((r >> 1) & 3) * 16;
    }

    float acc[2][NA][4];
#pragma unroll
    for (int mi = 0; mi < 2; mi++)
#pragma unroll
        for (int na = 0; na < NA; na++)
#pragma unroll
            for (int q = 0; q < 4; q++) acc[mi][na][q] = 0.f;

    issue(0, 0); cp_commit();
    issue(1, 1); cp_commit();

    for (int kt = 0; kt < NSTEP; kt++) {
        if (kt + 1 < NSTEP) cp_wait<1>(); else cp_wait<0>();
        __syncthreads();
        if (kt + 2 < NSTEP) { issue(kt + 2, (kt + 2) % 3); cp_commit(); }

        uint32_t stg = sb + (kt % 3) * STAGE;
#pragma unroll
        for (int ks = 0; ks < 2; ks++) {
            const uint32_t ca = (uint32_t)ks * 32 + ahi;
            const uint32_t cb = (uint32_t)ks * 32 + bhi;
            uint32_t ah[2][4], al[2][4], bb[NPAIR][4];
            ldm_x4(ah[0], stg + aof[0] + (ca ^ aswz[0]));
            ldm_x4(ah[1], stg + aof[1] + (ca ^ aswz[1]));
            ldm_x4(al[0], stg + 8192 + aof[0] + (ca ^ aswz[0]));
            ldm_x4(al[1], stg + 8192 + aof[1] + (ca ^ aswz[1]));
#pragma unroll
            for (int pj = 0; pj < NPAIR; pj++)
                ldm_x4(bb[pj], stg + bof[pj] + (cb ^ bswz[pj]));
#pragma unroll
            for (int mi = 0; mi < 2; mi++)
#pragma unroll
                for (int pj = 0; pj < NPAIR; pj++) {
                    mma16816(acc[mi][2 * pj],     ah[mi], &bb[pj][0]);
                    mma16816(acc[mi][2 * pj + 1], ah[mi], &bb[pj][2]);
                }
#pragma unroll
            for (int mi = 0; mi < 2; mi++)
#pragma unroll
                for (int pj = 0; pj < NPAIR; pj++) {
                    mma16816(acc[mi][2 * pj],     al[mi], &bb[pj][0]);
                    mma16816(acc[mi][2 * pj + 1], al[mi], &bb[pj][2]);
                }
#pragma unroll
            for (int pj = 0; pj < NPAIR; pj++)
                ldm_x4(bb[pj], stg + bof[pj] + NT * 64 + (cb ^ bswz[pj]));
#pragma unroll
            for (int mi = 0; mi < 2; mi++)
#pragma unroll
                for (int pj = 0; pj < NPAIR; pj++) {
                    mma16816(acc[mi][2 * pj],     ah[mi], &bb[pj][0]);
                    mma16816(acc[mi][2 * pj + 1], ah[mi], &bb[pj][2]);
                }
        }
    }

    const int g  = lane >> 2;
    const int tg = lane & 3;
#pragma unroll
    for (int mi = 0; mi < 2; mi++) {
        int r = m0 + wm * 32 + mi * 16 + g;
#pragma unroll
        for (int na = 0; na < NA; na++) {
            int ccc = n0 + wn * NTW + na * 8 + tg * 2;
            *(float2*)(C + (size_t)r * Ntot + ccc)       = make_float2(acc[mi][na][0], acc[mi][na][1]);
            *(float2*)(C + (size_t)(r + 8) * Ntot + ccc) = make_float2(acc[mi][na][2], acc[mi][na][3]);
        }
    }
}

#define GEMM1_SMEM (3 * (256 + 256) * 64)   // 98304
#define GEMM2_SMEM (3 * (256 + 128) * 64)   // 73728

__global__ __launch_bounds__(256, 2)
void gemm1() {
    gemm3_body<128, 1024>((const char*)g_W1, A1H * 2, A1L * 2, B1H * 2, B1L * 2, g_C1, N1);
}
__global__ __launch_bounds__(256, 3)
void gemm2(float* __restrict__ out) {
    gemm3_body<64, 2560>((const char*)g_W2, A2H * 2, A2L * 2, B2H * 2, B2L * 2, out, N2);
}

// ---------------- prep kernels ----------------------------------------------
__device__ __forceinline__ void split_bf16(float v, __nv_bfloat16& hi, __nv_bfloat16& lo) {
    hi = __float2bfloat16(v);
    lo = __float2bfloat16(v - __bfloat162float(hi));
}

__global__ __launch_bounds__(256) void prep_a1(const float* __restrict__ x) {
    int gid = blockIdx.x * 256 + threadIdx.x;
    __nv_bfloat16 hi, lo; split_bf16(x[gid], hi, lo);
    g_W1[A1H + gid] = hi;
    g_W1[A1L + gid] = lo;
}

__global__ void prep_b1(const float* __restrict__ Wq, const float* __restrict__ Wk,
                        const float* __restrict__ Wv, const float* __restrict__ Ws,
                        const float* __restrict__ Wd)
{
    __shared__ float tile[32][33];
    int k0 = blockIdx.x * 32;
    int n0 = blockIdx.y * 32;
    int tx = threadIdx.x, ty = threadIdx.y;
#pragma unroll
    for (int yy = 0; yy < 32; yy += 8) {
        int k = k0 + ty + yy, n = n0 + tx;
        float w;
        if      (n < 512)  w = Wq[(size_t)k * 512  + n];
        else if (n < 1024) w = Wk[(size_t)k * 512  + n - 512];
        else if (n < 3584) w = Wv[(size_t)k * 2560 + n - 1024];
        else if (n < 3624) w = Ws[(size_t)k * 40   + n - 3584];
        else if (n < 3664) w = Wd[(size_t)k * 40   + n - 3624];
        else               w = 0.f;
        tile[ty + yy][tx] = w;
    }
    __syncthreads();
#pragma unroll
    for (int yy = 0; yy < 32; yy += 8) {
        int n = n0 + ty + yy, k = k0 + tx;
        __nv_bfloat16 hi, lo; split_bf16(tile[tx][ty + yy], hi, lo);
        int idx = n * 1024 + k;
        g_W1[B1H + idx] = hi;
        g_W1[B1L + idx] = lo;
    }
}

__global__ __launch_bounds__(256) void prep_b2(const float* __restrict__ Wo) {
    int gid = blockIdx.x * 256 + threadIdx.x;
    int he = gid >> 16;
    int d  = (gid >> 6) & 1023;
    int c  = gid & 63;
    __nv_bfloat16 hi, lo; split_bf16(Wo[gid], hi, lo);
    int idx = d * V2 + he * 64 + c;
    g_W2[B2H + idx] = hi;
    g_W2[B2L + idx] = lo;
}

// ---------------- fused routing gates + expert V mix + transposed pack -------
__global__ __launch_bounds__(256) void route_pack() {
    __shared__ uint32_t tvh[4][65], tvl[4][65];
    int gid = blockIdx.x * 256 + threadIdx.x;
    int d  = gid & 63;
    int kp = (gid >> 6) & 511;
    int bh = gid >> 15;
    int b = bh >> 3, h = bh & 7;

    float v[2];
#pragma unroll
    for (int u = 0; u < 2; u++) {
        int t = kp * 2 + u;
        const float* row = g_C1 + (size_t)(b * 1024 + t) * N1;
        const float* sl = row + 3584 + h * Ee;
        float s[Ee];
#pragma unroll
        for (int e = 0; e < Ee; e++) s[e] = sl[e];
        float acc = 0.f;
#pragma unroll
        for (int e = 0; e < Ee; e++) {
            int rank = 0;
#pragma unroll
            for (int j = 0; j < Ee; j++)
                rank += (s[j] > s[e]) || (s[j] == s[e] && j < e);
            float gate = (rank < KK) ? 1.0f / (1.0f + expf(-s[e])) : 0.f;
            acc = fmaf(gate, row[1024 + (h * Ee + e) * 64 + d], acc);
        }
        v[u] = acc;

        if (d < Ee) {
            const float* dl = row + 3624 + h * Ee;
            float tq[Ee];
#pragma unroll
            for (int e = 0; e < Ee; e++) tq[e] = dl[e];
            int e = d, rank = 0;
#pragma unroll
            for (int j = 0; j < Ee; j++)
                rank += (tq[j] > tq[e]) || (tq[j] == tq[e] && j < e);
            g_sdg[(b * 1024 + t) * HE + h * Ee + e] = (rank < KK) ? 1.f : 0.f;
        }
    }
    uint32_t vh = packbf(v[0], v[1]);
    tvh[kp & 3][d] = vh;
    tvl[kp & 3][d] = packres(vh, v[0], v[1]);
    __syncthreads();
    int td  = threadIdx.x >> 2;
    int tk4 = threadIdx.x & 3;
    int kp0 = (blockIdx.x * 4) & 511;
    size_t oidx = ((size_t)bh * 64 + td) * 512 + kp0 + tk4;
    g_Vh[oidx] = tvh[tk4][td];
    g_Vl[oidx] = tvl[tk4][td];
}

// ---------------- attention operand prep --------------------------------------
__global__ __launch_bounds__(256) void prep_qk() {
    int gid = blockIdx.x * 256 + threadIdx.x;
    int p  = gid & 31;
    int t  = (gid >> 5) & 1023;
    int bh = gid >> 15;
    int b = bh >> 3, h = bh & 7;
    const float* row = g_C1 + (size_t)(b * 1024 + t) * N1;

    float q0 = row[h * 64 + 2 * p]     * QSCALE;
    float q1 = row[h * 64 + 2 * p + 1] * QSCALE;
    uint32_t qh = packbf(q0, q1);
    g_Qh[gid] = qh;
    g_Ql[gid] = packres(qh, q0, q1);

    float k0 = row[512 + h * 64 + 2 * p];
    float k1 = row[512 + h * 64 + 2 * p + 1];
    uint32_t kh = packbf(k0, k1);
    g_Kh[gid] = kh;
    g_Kl[gid] = packres(kh, k0, k1);
}

// ---------------- tensor-core causal flash attention, paired q-tiles ---------
// Epilogue writes sd-gated bf16 split of O directly into A2 (all 5 experts).
#define AQS   (64 * 36)
#define ATL   (64 * 36)
#define ASTG  (4 * ATL)
#define AWG_U (2 * AQS + 2 * ASTG)
#define ATTN_SMEM (2 * AWG_U * 4)

__global__ __launch_bounds__(256) void attn_tc() {
    extern __shared__ uint32_t sm[];
    const int bh   = blockIdx.y;
    const int b    = bh >> 3, h = bh & 7;
    const int wg   = threadIdx.x >> 7;
    const int qt   = wg ? (15 - blockIdx.x) : blockIdx.x;
    const int tid  = threadIdx.x & 127;
    const int w    = tid >> 5;
    const int lane = tid & 31;
    const int g    = lane >> 2;
    const int tig  = lane & 3;
    uint32_t* smg  = sm + wg * AWG_U;
    const uint32_t sb = smem_u32(smg);

    auto issue = [&](int kt, int s) {
#pragma unroll
        for (int i = 0; i < 16; i++) {
            int a = i >> 2;
            int r = (i & 3) * 16 + (tid >> 3);
            int c = tid & 7;
            uint32_t dst = sb + (2 * AQS + s * ASTG + a * ATL + r * 36) * 4 + c * 16;
            const uint32_t* srcb;
            if      (a == 0) srcb = g_Kh + ((size_t)(bh << 10) + kt * 64 + r) * 32;
            else if (a == 1) srcb = g_Kl + ((size_t)(bh << 10) + kt * 64 + r) * 32;
            else if (a == 2) srcb = g_Vh + ((size_t)bh * 64 + r) * 512 + kt * 32;
            else             srcb = g_Vl + ((size_t)bh * 64 + r) * 512 + kt * 32;
            cpasync16(dst, (const char*)srcb + c * 16);
        }
    };
    issue(0, 0); cp_commit();

    {
        const uint32_t* qhsrc = g_Qh + ((size_t)(bh << 10) + qt * 64) * 32;
        const uint32_t* qlsrc = g_Ql + ((size_t)(bh << 10) + qt * 64) * 32;
#pragma unroll
        for (int j = 0; j < 4; j++) {
            int idx = tid + j * 128;
            int row = idx >> 3, po = (idx & 7) * 4;
            *(uint4*)&smg[row * 36 + po]       = *(const uint4*)(qhsrc + row * 32 + po);
            *(uint4*)&smg[AQS + row * 36 + po] = *(const uint4*)(qlsrc + row * 32 + po);
        }
    }
    WGBAR(wg);

    uint32_t qa[2][4][4];
#pragma unroll
    for (int hl = 0; hl < 2; hl++) {
        int qb = hl * AQS;
#pragma unroll
        for (int kb = 0; kb < 4; kb++) {
            qa[hl][kb][0] = smg[qb + (w * 16 + g)     * 36 + kb * 8 + tig];
            qa[hl][kb][1] = smg[qb + (w * 16 + g + 8) * 36 + kb * 8 + tig];
            qa[hl][kb][2] = smg[qb + (w * 16 + g)     * 36 + kb * 8 + 4 + tig];
            qa[hl][kb][3] = smg[qb + (w * 16 + g + 8) * 36 + kb * 8 + 4 + tig];
        }
    }

    const int li   = lane >> 3;
    const uint32_t lbase = (((li >> 1) * 8 + (lane & 7)) * 36 + (li & 1) * 4) * 4;

    float o[8][4];
#pragma unroll
    for (int a = 0; a < 8; a++)
#pragma unroll
        for (int q = 0; q < 4; q++) o[a][q] = 0.f;
    float m[2] = {-1e30f, -1e30f}, l[2] = {0.f, 0.f};

    for (int kt = 0; kt <= qt; kt++) {
        if (kt < qt) { issue(kt + 1, (kt + 1) & 1); cp_commit(); cp_wait<1>(); }
        else         { cp_wait<0>(); }
        WGBAR(wg);

        const uint32_t su = sb + (2 * AQS + (kt & 1) * ASTG) * 4;
        const uint32_t Khb = su,               Klb = su + ATL * 4;
        const uint32_t Vhb = su + 2 * ATL * 4, Vlb = su + 3 * ATL * 4;

        float s[8][4];
#pragma unroll
        for (int a = 0; a < 8; a++)
#pragma unroll
            for (int q = 0; q < 4; q++) s[a][q] = 0.f;

#pragma unroll
        for (int kb = 0; kb < 4; kb++) {
            uint32_t bb[4][4];
#pragma unroll
            for (int j = 0; j < 4; j++)
                ldm_x4(bb[j], Khb + lbase + (j * 576 + kb * 8) * 4);
#pragma unroll
            for (int j = 0; j < 4; j++) {
                mma16816(s[2*j],   qa[0][kb], &bb[j][0]);
                mma16816(s[2*j+1], qa[0][kb], &bb[j][2]);
            }
#pragma unroll
            for (int j = 0; j < 4; j++) {
                mma16816(s[2*j],   qa[1][kb], &bb[j][0]);
                mma16816(s[2*j+1], qa[1][kb], &bb[j][2]);
            }
#pragma unroll
            for (int j = 0; j < 4; j++)
                ldm_x4(bb[j], Klb + lbase + (j * 576 + kb * 8) * 4);
#pragma unroll
            for (int j = 0; j < 4; j++) {
                mma16816(s[2*j],   qa[0][kb], &bb[j][0]);
                mma16816(s[2*j+1], qa[0][kb], &bb[j][2]);
            }
        }

        if (kt == qt) {
            int r0 = w * 16 + g;
#pragma unroll
            for (int na = 0; na < 8; na++) {
                int c0 = na * 8 + 2 * tig;
                if (c0     > r0)     s[na][0] = -1e9f;
                if (c0 + 1 > r0)     s[na][1] = -1e9f;
                if (c0     > r0 + 8) s[na][2] = -1e9f;
                if (c0 + 1 > r0 + 8) s[na][3] = -1e9f;
            }
        }

#pragma unroll
        for (int ri = 0; ri < 2; ri++) {
            float mx = -1e30f;
#pragma unroll
            for (int a = 0; a < 8; a++)
                mx = fmaxf(mx, fmaxf(s[a][2 * ri], s[a][2 * ri + 1]));
            mx = fmaxf(mx, __shfl_xor_sync(0xffffffffu, mx, 1));
            mx = fmaxf(mx, __shfl_xor_sync(0xffffffffu, mx, 2));
            float mnew = fmaxf(m[ri], mx);
            float corr = __expf(m[ri] - mnew);
            float rs = 0.f;
#pragma unroll
            for (int a = 0; a < 8; a++) {
                float p0 = __expf(s[a][2 * ri]     - mnew);
                float p1 = __expf(s[a][2 * ri + 1] - mnew);
                s[a][2 * ri] = p0; s[a][2 * ri + 1] = p1;
                rs += p0 + p1;
            }
            rs += __shfl_xor_sync(0xffffffffu, rs, 1);
            rs += __shfl_xor_sync(0xffffffffu, rs, 2);
            l[ri] = l[ri] * corr + rs;
            m[ri] = mnew;
#pragma unroll
            for (int a = 0; a < 8; a++) { o[a][2 * ri] *= corr; o[a][2 * ri + 1] *= corr; }
        }

#pragma unroll
        for (int kb = 0; kb < 4; kb++) {
            uint32_t ph[4], pl[4];
            ph[0] = packbf(s[2*kb][0],   s[2*kb][1]);
            ph[1] = packbf(s[2*kb][2],   s[2*kb][3]);
            ph[2] = packbf(s[2*kb+1][0], s[2*kb+1][1]);
            ph[3] = packbf(s[2*kb+1][2], s[2*kb+1][3]);
            pl[0] = packres(ph[0], s[2*kb][0],   s[2*kb][1]);
            pl[1] = packres(ph[1], s[2*kb][2],   s[2*kb][3]);
            pl[2] = packres(ph[2], s[2*kb+1][0], s[2*kb+1][1]);
            pl[3] = packres(ph[3], s[2*kb+1][2], s[2*kb+1][3]);

            uint32_t bb[4][4];
#pragma unroll
            for (int j = 0; j < 4; j++)
                ldm_x4(bb[j], Vhb + lbase + (j * 576 + kb * 8) * 4);
#pragma unroll
            for (int j = 0; j < 4; j++) {
                mma16816(o[2*j],   ph, &bb[j][0]);
                mma16816(o[2*j+1], ph, &bb[j][2]);
            }
#pragma unroll
            for (int j = 0; j < 4; j++) {
                mma16816(o[2*j],   pl, &bb[j][0]);
                mma16816(o[2*j+1], pl, &bb[j][2]);
            }
#pragma unroll
            for (int j = 0; j < 4; j++)
                ldm_x4(bb[j], Vlb + lbase + (j * 576 + kb * 8) * 4);
#pragma unroll
            for (int j = 0; j < 4; j++) {
                mma16816(o[2*j],   ph, &bb[j][0]);
                mma16816(o[2*j+1], ph, &bb[j][2]);
            }
        }
        WGBAR(wg);
    }

    // ---- fused epilogue: A2 = split(sd * O) for all 5 experts ----
    float inv0 = 1.0f / l[0], inv1 = 1.0f / l[1];
    int row0 = qt * 64 + w * 16 + g;
    int bt0  = b * 1024 + row0;

    float g0[Ee], g1[Ee];
#pragma unroll
    for (int e = 0; e < Ee; e++) {
        g0[e] = g_sdg[bt0 * HE + h * Ee + e];
        g1[e] = g_sdg[(bt0 + 8) * HE + h * Ee + e];
    }
    uint32_t* a2h0 = (uint32_t*)(g_W2 + A2H + (size_t)bt0 * V2);
    uint32_t* a2l0 = (uint32_t*)(g_W2 + A2L + (size_t)bt0 * V2);
    uint32_t* a2h1 = (uint32_t*)(g_W2 + A2H + (size_t)(bt0 + 8) * V2);
    uint32_t* a2l1 = (uint32_t*)(g_W2 + A2L + (size_t)(bt0 + 8) * V2);

#pragma unroll
    for (int na = 0; na < 8; na++) {
        int c0 = na * 8 + 2 * tig;                   // within-head col (even)
        float v00 = o[na][0] * inv0, v01 = o[na][1] * inv0;
        float v10 = o[na][2] * inv1, v11 = o[na][3] * inv1;
        uint32_t h0 = packbf(v00, v01), l0p = packres(h0, v00, v01);
        uint32_t h1 = packbf(v10, v11), l1p = packres(h1, v10, v11);
#pragma unroll
        for (int e = 0; e < Ee; e++) {
            int cw = ((h * Ee + e) * 64 + c0) >> 1;  // u32 index
            a2h0[cw] = (g0[e] != 0.f) ? h0  : 0u;
            a2l0[cw] = (g0[e] != 0.f) ? l0p : 0u;
            a2h1[cw] = (g1[e] != 0.f) ? h1  : 0u;
            a2l1[cw] = (g1[e] != 0.f) ? l1p : 0u;
        }
    }
}

// ---------------- launch ------------------------------------------------------
extern "C" void kernel_launch(void* const* d_in, const int* in_sizes, int n_in,
                              void* d_out, int out_size)
{
    const float* x  = (const float*)d_in[0];
    const float* Wq = (const float*)d_in[1];
    const float* Wk = (const float*)d_in[2];
    const float* Wv = (const float*)d_in[3];
    const float* Ws = (const float*)d_in[4];
    const float* Wd = (const float*)d_in[5];
    const float* Wo = (const float*)d_in[6];
    float* out = (float*)d_out;

    cudaFuncSetAttribute(gemm1,   cudaFuncAttributeMaxDynamicSharedMemorySize, GEMM1_SMEM);
    cudaFuncSetAttribute(gemm2,   cudaFuncAttributeMaxDynamicSharedMemorySize, GEMM2_SMEM);
    cudaFuncSetAttribute(attn_tc, cudaFuncAttributeMaxDynamicSharedMemorySize, ATTN_SMEM);

    prep_a1   <<<BT * DIMD / 256, 256>>>(x);
    prep_b1   <<<dim3(32, 120), dim3(32, 8)>>>(Wq, Wk, Wv, Ws, Wd);
    prep_b2   <<<HE * DIMD * 64 / 256, 256>>>(Wo);
    gemm1     <<<dim3(N1 / 128, BT / 128), 256, GEMM1_SMEM>>>();
    route_pack<<<16 * 512 * 64 / 256, 256>>>();
    prep_qk   <<<16 * 1024 * 32 / 256, 256>>>();
    attn_tc   <<<dim3(8, 16), 256, ATTN_SMEM>>>();
    gemm2     <<<dim3(N2 / 64, BT / 128), 256, GEMM2_SMEM>>>(out);
}

// round 9
// speedup vs baseline: 3.3925x; 1.0601x over previous
#include <cuda_runtime.h>
#include <cuda_bf16.h>
#include <cstdint>

#define Tt   1024
#define DIMD 1024
#define Hh   8
#define Ee   5
#define KK   3
#define BT   2048
#define HS   512
#define HE   40
#define QSCALE 0.125f

#define N1 3840
#define N2 1024
#define V2 2560

// ---------------- scratch ----------------------------------------------------
__device__ float g_C1 [BT * N1];
#define A1H 0
#define A1L (BT * 1024)
#define B1H (2 * BT * 1024)
#define B1L (2 * BT * 1024 + N1 * 1024)
__device__ __nv_bfloat16 g_W1[2 * BT * 1024 + 2 * N1 * 1024];
#define A2H 0
#define A2L (BT * V2)
#define B2H (2 * BT * V2)
#define B2L (2 * BT * V2 + N2 * V2)
__device__ __nv_bfloat16 g_W2[2 * BT * V2 + 2 * N2 * V2];

__device__ float g_sdg[BT * HE];
__device__ uint32_t g_Qh[16 * 1024 * 32];
__device__ uint32_t g_Ql[16 * 1024 * 32];
__device__ uint32_t g_Kh[16 * 1024 * 32];
__device__ uint32_t g_Kl[16 * 1024 * 32];
__device__ uint32_t g_Vh[16 * 64 * 512];
__device__ uint32_t g_Vl[16 * 64 * 512];

// ---------------- helpers -----------------------------------------------------
__device__ __forceinline__ uint32_t smem_u32(const void* p) {
    uint32_t a;
    asm("{ .reg .u64 t; cvta.to.shared.u64 t, %1; cvt.u32.u64 %0, t; }" : "=r"(a) : "l"(p));
    return a;
}
__device__ __forceinline__ void cpasync16(uint32_t dst, const void* src) {
    asm volatile("cp.async.cg.shared.global [%0], [%1], 16;\n" :: "r"(dst), "l"(src));
}
__device__ __forceinline__ void cp_commit() { asm volatile("cp.async.commit_group;\n"); }
template<int N> __device__ __forceinline__ void cp_wait() { asm volatile("cp.async.wait_group %0;\n" :: "n"(N)); }

__device__ __forceinline__ void mma16816(float* c, const uint32_t* a, const uint32_t* b) {
    asm volatile(
        "mma.sync.aligned.m16n8k16.row.col.f32.bf16.bf16.f32 "
        "{%0,%1,%2,%3}, {%4,%5,%6,%7}, {%8,%9}, {%0,%1,%2,%3};"
        : "+f"(c[0]), "+f"(c[1]), "+f"(c[2]), "+f"(c[3])
        : "r"(a[0]), "r"(a[1]), "r"(a[2]), "r"(a[3]), "r"(b[0]), "r"(b[1]));
}
__device__ __forceinline__ void ldm_x4(uint32_t* r, uint32_t addr) {
    asm volatile("ldmatrix.sync.aligned.m8n8.x4.shared.b16 {%0,%1,%2,%3}, [%4];"
        : "=r"(r[0]), "=r"(r[1]), "=r"(r[2]), "=r"(r[3]) : "r"(addr));
}
__device__ __forceinline__ uint32_t packbf(float lo, float hi) {
    uint32_t r;
    asm("cvt.rn.bf16x2.f32 %0, %1, %2;" : "=r"(r) : "f"(hi), "f"(lo));
    return r;
}
__device__ __forceinline__ uint32_t packres(uint32_t p, float lo, float hi) {
    float plo = __uint_as_float(p << 16);
    float phi = __uint_as_float(p & 0xffff0000u);
    return packbf(lo - plo, hi - phi);
}
#define WGBAR(id) asm volatile("bar.sync %0, 128;" :: "r"((id) + 1) : "memory")

// ---------------- 3-term split GEMM with shared fragments --------------------
// C = Ah@Bh^T + Al@Bh^T + Ah@Bl^T (fp32 acc). Row-major [rows][KTOT] bf16.
// CTA tile 128 x NT, BK=32 (64B rows), swizzle: col16 ^= ((row>>1)&3)*16.
// FUSEQK: tiles with n0<1024 write scaled/split Q,K pair arrays instead of C.
template<int NT, int KTOT, bool FUSEQK>
__device__ __forceinline__ void gemm3_body(const char* __restrict__ W,
                                           uint32_t offAh, uint32_t offAl,
                                           uint32_t offBh, uint32_t offBl,
                                           float* __restrict__ C, int Ntot)
{
    constexpr int ROWS  = 256 + 2 * NT;
    constexpr int STAGE = ROWS * 64;
    constexpr int NSTEP = KTOT / 32;
    constexpr int NTW   = NT / 2;
    constexpr int NPAIR = NTW / 16;
    constexpr int NA    = NTW / 8;
    constexpr int CPT   = ROWS / 64;
    constexpr int NB    = NT / 64;
    constexpr size_t K2B = KTOT * 2;

    extern __shared__ char sm_raw[];
    const uint32_t sb = smem_u32(sm_raw);
    const int tid = threadIdx.x, wid = tid >> 5, lane = tid & 31;
    const int wm = wid & 3, wn = wid >> 2;
    const int m0 = blockIdx.y * 128, n0 = blockIdx.x * NT;

    const int r0 = tid >> 2;
    const int cc = (tid & 3) * 16;
    const uint32_t dst0 = r0 * 64 + (cc ^ (((r0 >> 1) & 3) * 16));
    const char* pAh = W + offAh + (size_t)(m0 + r0) * K2B + cc;
    const char* pAl = W + offAl + (size_t)(m0 + r0) * K2B + cc;
    const char* pBh = W + offBh + (size_t)(n0 + r0) * K2B + cc;
    const char* pBl = W + offBl + (size_t)(n0 + r0) * K2B + cc;

    auto issue = [&](int kt, int slot) {
        const uint32_t st = sb + slot * STAGE + dst0;
        const size_t gk = (size_t)kt * 64;
#pragma unroll
        for (int i = 0; i < CPT; i++) {
            const char* src;
            if      (i < 2)      src = pAh + (size_t)i * (64 * K2B);
            else if (i < 4)      src = pAl + (size_t)(i - 2) * (64 * K2B);
            else if (i < 4 + NB) src = pBh + (size_t)(i - 4) * (64 * K2B);
            else                 src = pBl + (size_t)(i - 4 - NB) * (64 * K2B);
            cpasync16(st + i * 4096, src + gk);
        }
    };

    const uint32_t ahi = (lane >> 4) * 16;
    const uint32_t bhi = ((lane >> 3) & 1) * 16;
    uint32_t aof[2], aswz[2], bof[NPAIR], bswz[NPAIR];
#pragma unroll
    for (int mi = 0; mi < 2; mi++) {
        int r = wm * 32 + mi * 16 + (lane & 15);
        aof[mi] = r * 64; aswz[mi] = ((r >> 1) & 3) * 16;
    }
#pragma unroll
    for (int pj = 0; pj < NPAIR; pj++) {
        int r = wn * NTW + pj * 16 + ((lane >> 4) << 3) + (lane & 7);
        bof[pj] = (256 + r) * 64; bswz[pj] = ((r >> 1) & 3) * 16;
    }

    float acc[2][NA][4];
#pragma unroll
    for (int mi = 0; mi < 2; mi++)
#pragma unroll
        for (int na = 0; na < NA; na++)
#pragma unroll
            for (int q = 0; q < 4; q++) acc[mi][na][q] = 0.f;

    issue(0, 0); cp_commit();
    issue(1, 1); cp_commit();

    for (int kt = 0; kt < NSTEP; kt++) {
        if (kt + 1 < NSTEP) cp_wait<1>(); else cp_wait<0>();
        __syncthreads();
        if (kt + 2 < NSTEP) { issue(kt + 2, (kt + 2) % 3); cp_commit(); }

        uint32_t stg = sb + (kt % 3) * STAGE;
#pragma unroll
        for (int ks = 0; ks < 2; ks++) {
            const uint32_t ca = (uint32_t)ks * 32 + ahi;
            const uint32_t cb = (uint32_t)ks * 32 + bhi;
            uint32_t ah[2][4], al[2][4], bb[NPAIR][4];
            ldm_x4(ah[0], stg + aof[0] + (ca ^ aswz[0]));
            ldm_x4(ah[1], stg + aof[1] + (ca ^ aswz[1]));
            ldm_x4(al[0], stg + 8192 + aof[0] + (ca ^ aswz[0]));
            ldm_x4(al[1], stg + 8192 + aof[1] + (ca ^ aswz[1]));
#pragma unroll
            for (int pj = 0; pj < NPAIR; pj++)
                ldm_x4(bb[pj], stg + bof[pj] + (cb ^ bswz[pj]));
#pragma unroll
            for (int mi = 0; mi < 2; mi++)
#pragma unroll
                for (int pj = 0; pj < NPAIR; pj++) {
                    mma16816(acc[mi][2 * pj],     ah[mi], &bb[pj][0]);
                    mma16816(acc[mi][2 * pj + 1], ah[mi], &bb[pj][2]);
                }
#pragma unroll
            for (int mi = 0; mi < 2; mi++)
#pragma unroll
                for (int pj = 0; pj < NPAIR; pj++) {
                    mma16816(acc[mi][2 * pj],     al[mi], &bb[pj][0]);
                    mma16816(acc[mi][2 * pj + 1], al[mi], &bb[pj][2]);
                }
#pragma unroll
            for (int pj = 0; pj < NPAIR; pj++)
                ldm_x4(bb[pj], stg + bof[pj] + NT * 64 + (cb ^ bswz[pj]));
#pragma unroll
            for (int mi = 0; mi < 2; mi++)
#pragma unroll
                for (int pj = 0; pj < NPAIR; pj++) {
                    mma16816(acc[mi][2 * pj],     ah[mi], &bb[pj][0]);
                    mma16816(acc[mi][2 * pj + 1], ah[mi], &bb[pj][2]);
                }
        }
    }

    const int g  = lane >> 2;
    const int tg = lane & 3;

    if (FUSEQK && n0 < 1024) {
        // Q tile (n0<512) or K tile: write split bf16x2 pair arrays directly
        const bool isQ = (n0 < 512);
        const float sc = isQ ? QSCALE : 1.0f;
        uint32_t* dh = isQ ? g_Qh : g_Kh;
        uint32_t* dl = isQ ? g_Ql : g_Kl;
#pragma unroll
        for (int mi = 0; mi < 2; mi++) {
            int r = m0 + wm * 32 + mi * 16 + g;
            int b_ = r >> 10, t = r & 1023;
#pragma unroll
            for (int na = 0; na < NA; na++) {
                int ccc = n0 + wn * NTW + na * 8 + tg * 2;
                int h = (ccc >> 6) & 7;
                int p = (ccc & 63) >> 1;
                size_t base = (((size_t)(b_ * 8 + h) << 10) + t) * 32 + p;
                float v0 = acc[mi][na][0] * sc, v1 = acc[mi][na][1] * sc;
                uint32_t h0 = packbf(v0, v1);
                dh[base] = h0; dl[base] = packres(h0, v0, v1);
                float w0 = acc[mi][na][2] * sc, w1 = acc[mi][na][3] * sc;
                uint32_t h1 = packbf(w0, w1);
                dh[base + 8 * 32] = h1; dl[base + 8 * 32] = packres(h1, w0, w1);
            }
        }
    } else {
#pragma unroll
        for (int mi = 0; mi < 2; mi++) {
            int r = m0 + wm * 32 + mi * 16 + g;
#pragma unroll
            for (int na = 0; na < NA; na++) {
                int ccc = n0 + wn * NTW + na * 8 + tg * 2;
                *(float2*)(C + (size_t)r * Ntot + ccc)       = make_float2(acc[mi][na][0], acc[mi][na][1]);
                *(float2*)(C + (size_t)(r + 8) * Ntot + ccc) = make_float2(acc[mi][na][2], acc[mi][na][3]);
            }
        }
    }
}

#define GEMM_SMEM3 (3 * (256 + 128) * 64)   // 73728 (NT=64, 3 stages)

__global__ __launch_bounds__(256, 3)
void gemm1() {
    gemm3_body<64, 1024, true>((const char*)g_W1, A1H * 2, A1L * 2, B1H * 2, B1L * 2, g_C1, N1);
}
__global__ __launch_bounds__(256, 3)
void gemm2(float* __restrict__ out) {
    gemm3_body<64, 2560, false>((const char*)g_W2, A2H * 2, A2L * 2, B2H * 2, B2L * 2, out, N2);
}

// ---------------- prep kernels ----------------------------------------------
__device__ __forceinline__ void split_bf16(float v, __nv_bfloat16& hi, __nv_bfloat16& lo) {
    hi = __float2bfloat16(v);
    lo = __float2bfloat16(v - __bfloat162float(hi));
}

__global__ __launch_bounds__(256) void prep_a1(const float* __restrict__ x) {
    int gid = blockIdx.x * 256 + threadIdx.x;
    __nv_bfloat16 hi, lo; split_bf16(x[gid], hi, lo);
    g_W1[A1H + gid] = hi;
    g_W1[A1L + gid] = lo;
}

__global__ void prep_b1(const float* __restrict__ Wq, const float* __restrict__ Wk,
                        const float* __restrict__ Wv, const float* __restrict__ Ws,
                        const float* __restrict__ Wd)
{
    __shared__ float tile[32][33];
    int k0 = blockIdx.x * 32;
    int n0 = blockIdx.y * 32;
    int tx = threadIdx.x, ty = threadIdx.y;
#pragma unroll
    for (int yy = 0; yy < 32; yy += 8) {
        int k = k0 + ty + yy, n = n0 + tx;
        float w;
        if      (n < 512)  w = Wq[(size_t)k * 512  + n];
        else if (n < 1024) w = Wk[(size_t)k * 512  + n - 512];
        else if (n < 3584) w = Wv[(size_t)k * 2560 + n - 1024];
        else if (n < 3624) w = Ws[(size_t)k * 40   + n - 3584];
        else if (n < 3664) w = Wd[(size_t)k * 40   + n - 3624];
        else               w = 0.f;
        tile[ty + yy][tx] = w;
    }
    __syncthreads();
#pragma unroll
    for (int yy = 0; yy < 32; yy += 8) {
        int n = n0 + ty + yy, k = k0 + tx;
        __nv_bfloat16 hi, lo; split_bf16(tile[tx][ty + yy], hi, lo);
        int idx = n * 1024 + k;
        g_W1[B1H + idx] = hi;
        g_W1[B1L + idx] = lo;
    }
}

__global__ __launch_bounds__(256) void prep_b2(const float* __restrict__ Wo) {
    int gid = blockIdx.x * 256 + threadIdx.x;
    int he = gid >> 16;
    int d  = (gid >> 6) & 1023;
    int c  = gid & 63;
    __nv_bfloat16 hi, lo; split_bf16(Wo[gid], hi, lo);
    int idx = d * V2 + he * 64 + c;
    g_W2[B2H + idx] = hi;
    g_W2[B2L + idx] = lo;
}

// ---------------- fused routing gates + expert V mix + transposed pack -------
__global__ __launch_bounds__(256) void route_pack() {
    __shared__ uint32_t tvh[4][65], tvl[4][65];
    int gid = blockIdx.x * 256 + threadIdx.x;
    int d  = gid & 63;
    int kp = (gid >> 6) & 511;
    int bh = gid >> 15;
    int b = bh >> 3, h = bh & 7;

    float v[2];
#pragma unroll
    for (int u = 0; u < 2; u++) {
        int t = kp * 2 + u;
        const float* row = g_C1 + (size_t)(b * 1024 + t) * N1;
        const float* sl = row + 3584 + h * Ee;
        float s[Ee];
#pragma unroll
        for (int e = 0; e < Ee; e++) s[e] = sl[e];
        float acc = 0.f;
#pragma unroll
        for (int e = 0; e < Ee; e++) {
            int rank = 0;
#pragma unroll
            for (int j = 0; j < Ee; j++)
                rank += (s[j] > s[e]) || (s[j] == s[e] && j < e);
            float gate = (rank < KK) ? 1.0f / (1.0f + expf(-s[e])) : 0.f;
            acc = fmaf(gate, row[1024 + (h * Ee + e) * 64 + d], acc);
        }
        v[u] = acc;

        if (d < Ee) {
            const float* dl = row + 3624 + h * Ee;
            float tq[Ee];
#pragma unroll
            for (int e = 0; e < Ee; e++) tq[e] = dl[e];
            int e = d, rank = 0;
#pragma unroll
            for (int j = 0; j < Ee; j++)
                rank += (tq[j] > tq[e]) || (tq[j] == tq[e] && j < e);
            g_sdg[(b * 1024 + t) * HE + h * Ee + e] = (rank < KK) ? 1.f : 0.f;
        }
    }
    uint32_t vh = packbf(v[0], v[1]);
    tvh[kp & 3][d] = vh;
    tvl[kp & 3][d] = packres(vh, v[0], v[1]);
    __syncthreads();
    int td  = threadIdx.x >> 2;
    int tk4 = threadIdx.x & 3;
    int kp0 = (blockIdx.x * 4) & 511;
    size_t oidx = ((size_t)bh * 64 + td) * 512 + kp0 + tk4;
    g_Vh[oidx] = tvh[tk4][td];
    g_Vl[oidx] = tvl[tk4][td];
}

// ---------------- tensor-core causal flash attention, paired q-tiles ---------
#define AQS   (64 * 36)
#define ATL   (64 * 36)
#define ASTG  (4 * ATL)
#define AWG_U (2 * AQS + 2 * ASTG)
#define ATTN_SMEM (2 * AWG_U * 4)

__global__ __launch_bounds__(256) void attn_tc() {
    extern __shared__ uint32_t sm[];
    const int bh   = blockIdx.y;
    const int b    = bh >> 3, h = bh & 7;
    const int wg   = threadIdx.x >> 7;
    const int qt   = wg ? (15 - blockIdx.x) : blockIdx.x;
    const int tid  = threadIdx.x & 127;
    const int w    = tid >> 5;
    const int lane = tid & 31;
    const int g    = lane >> 2;
    const int tig  = lane & 3;
    uint32_t* smg  = sm + wg * AWG_U;
    const uint32_t sb = smem_u32(smg);

    auto issue = [&](int kt, int s) {
#pragma unroll
        for (int i = 0; i < 16; i++) {
            int a = i >> 2;
            int r = (i & 3) * 16 + (tid >> 3);
            int c = tid & 7;
            uint32_t dst = sb + (2 * AQS + s * ASTG + a * ATL + r * 36) * 4 + c * 16;
            const uint32_t* srcb;
            if      (a == 0) srcb = g_Kh + ((size_t)(bh << 10) + kt * 64 + r) * 32;
            else if (a == 1) srcb = g_Kl + ((size_t)(bh << 10) + kt * 64 + r) * 32;
            else if (a == 2) srcb = g_Vh + ((size_t)bh * 64 + r) * 512 + kt * 32;
            else             srcb = g_Vl + ((size_t)bh * 64 + r) * 512 + kt * 32;
            cpasync16(dst, (const char*)srcb + c * 16);
        }
    };
    issue(0, 0); cp_commit();

    {
        const uint32_t* qhsrc = g_Qh + ((size_t)(bh << 10) + qt * 64) * 32;
        const uint32_t* qlsrc = g_Ql + ((size_t)(bh << 10) + qt * 64) * 32;
#pragma unroll
        for (int j = 0; j < 4; j++) {
            int idx = tid + j * 128;
            int row = idx >> 3, po = (idx & 7) * 4;
            *(uint4*)&smg[row * 36 + po]       = *(const uint4*)(qhsrc + row * 32 + po);
            *(uint4*)&smg[AQS + row * 36 + po] = *(const uint4*)(qlsrc + row * 32 + po);
        }
    }
    WGBAR(wg);

    uint32_t qa[2][4][4];
#pragma unroll
    for (int hl = 0; hl < 2; hl++) {
        int qb = hl * AQS;
#pragma unroll
        for (int kb = 0; kb < 4; kb++) {
            qa[hl][kb][0] = smg[qb + (w * 16 + g)     * 36 + kb * 8 + tig];
            qa[hl][kb][1] = smg[qb + (w * 16 + g + 8) * 36 + kb * 8 + tig];
            qa[hl][kb][2] = smg[qb + (w * 16 + g)     * 36 + kb * 8 + 4 + tig];
            qa[hl][kb][3] = smg[qb + (w * 16 + g + 8) * 36 + kb * 8 + 4 + tig];
        }
    }

    const int li   = lane >> 3;
    const uint32_t lbase = (((li >> 1) * 8 + (lane & 7)) * 36 + (li & 1) * 4) * 4;

    float o[8][4];
#pragma unroll
    for (int a = 0; a < 8; a++)
#pragma unroll
        for (int q = 0; q < 4; q++) o[a][q] = 0.f;
    float m[2] = {-1e30f, -1e30f}, l[2] = {0.f, 0.f};

    for (int kt = 0; kt <= qt; kt++) {
        if (kt < qt) { issue(kt + 1, (kt + 1) & 1); cp_commit(); cp_wait<1>(); }
        else         { cp_wait<0>(); }
        WGBAR(wg);

        const uint32_t su = sb + (2 * AQS + (kt & 1) * ASTG) * 4;
        const uint32_t Khb = su,               Klb = su + ATL * 4;
        const uint32_t Vhb = su + 2 * ATL * 4, Vlb = su + 3 * ATL * 4;

        float s[8][4];
#pragma unroll
        for (int a = 0; a < 8; a++)
#pragma unroll
            for (int q = 0; q < 4; q++) s[a][q] = 0.f;

#pragma unroll
        for (int kb = 0; kb < 4; kb++) {
            uint32_t bb[4][4];
#pragma unroll
            for (int j = 0; j < 4; j++)
                ldm_x4(bb[j], Khb + lbase + (j * 576 + kb * 8) * 4);
#pragma unroll
            for (int j = 0; j < 4; j++) {
                mma16816(s[2*j],   qa[0][kb], &bb[j][0]);
                mma16816(s[2*j+1], qa[0][kb], &bb[j][2]);
            }
#pragma unroll
            for (int j = 0; j < 4; j++) {
                mma16816(s[2*j],   qa[1][kb], &bb[j][0]);
                mma16816(s[2*j+1], qa[1][kb], &bb[j][2]);
            }
#pragma unroll
            for (int j = 0; j < 4; j++)
                ldm_x4(bb[j], Klb + lbase + (j * 576 + kb * 8) * 4);
#pragma unroll
            for (int j = 0; j < 4; j++) {
                mma16816(s[2*j],   qa[0][kb], &bb[j][0]);
                mma16816(s[2*j+1], qa[0][kb], &bb[j][2]);
            }
        }

        if (kt == qt) {
            int r0 = w * 16 + g;
#pragma unroll
            for (int na = 0; na < 8; na++) {
                int c0 = na * 8 + 2 * tig;
                if (c0     > r0)     s[na][0] = -1e9f;
                if (c0 + 1 > r0)     s[na][1] = -1e9f;
                if (c0     > r0 + 8) s[na][2] = -1e9f;
                if (c0 + 1 > r0 + 8) s[na][3] = -1e9f;
            }
        }

#pragma unroll
        for (int ri = 0; ri < 2; ri++) {
            float mx = -1e30f;
#pragma unroll
            for (int a = 0; a < 8; a++)
                mx = fmaxf(mx, fmaxf(s[a][2 * ri], s[a][2 * ri + 1]));
            mx = fmaxf(mx, __shfl_xor_sync(0xffffffffu, mx, 1));
            mx = fmaxf(mx, __shfl_xor_sync(0xffffffffu, mx, 2));
            float mnew = fmaxf(m[ri], mx);
            float corr = __expf(m[ri] - mnew);
            float rs = 0.f;
#pragma unroll
            for (int a = 0; a < 8; a++) {
                float p0 = __expf(s[a][2 * ri]     - mnew);
                float p1 = __expf(s[a][2 * ri + 1] - mnew);
                s[a][2 * ri] = p0; s[a][2 * ri + 1] = p1;
                rs += p0 + p1;
            }
            rs += __shfl_xor_sync(0xffffffffu, rs, 1);
            rs += __shfl_xor_sync(0xffffffffu, rs, 2);
            l[ri] = l[ri] * corr + rs;
            m[ri] = mnew;
#pragma unroll
            for (int a = 0; a < 8; a++) { o[a][2 * ri] *= corr; o[a][2 * ri + 1] *= corr; }
        }

#pragma unroll
        for (int kb = 0; kb < 4; kb++) {
            uint32_t ph[4], pl[4];
            ph[0] = packbf(s[2*kb][0],   s[2*kb][1]);
            ph[1] = packbf(s[2*kb][2],   s[2*kb][3]);
            ph[2] = packbf(s[2*kb+1][0], s[2*kb+1][1]);
            ph[3] = packbf(s[2*kb+1][2], s[2*kb+1][3]);
            pl[0] = packres(ph[0], s[2*kb][0],   s[2*kb][1]);
            pl[1] = packres(ph[1], s[2*kb][2],   s[2*kb][3]);
            pl[2] = packres(ph[2], s[2*kb+1][0], s[2*kb+1][1]);
            pl[3] = packres(ph[3], s[2*kb+1][2], s[2*kb+1][3]);

            uint32_t bb[4][4];
#pragma unroll
            for (int j = 0; j < 4; j++)
                ldm_x4(bb[j], Vhb + lbase + (j * 576 + kb * 8) * 4);
#pragma unroll
            for (int j = 0; j < 4; j++) {
                mma16816(o[2*j],   ph, &bb[j][0]);
                mma16816(o[2*j+1], ph, &bb[j][2]);
            }
#pragma unroll
            for (int j = 0; j < 4; j++) {
                mma16816(o[2*j],   pl, &bb[j][0]);
                mma16816(o[2*j+1], pl, &bb[j][2]);
            }
#pragma unroll
            for (int j = 0; j < 4; j++)
                ldm_x4(bb[j], Vlb + lbase + (j * 576 + kb * 8) * 4);
#pragma unroll
            for (int j = 0; j < 4; j++) {
                mma16816(o[2*j],   ph, &bb[j][0]);
                mma16816(o[2*j+1], ph, &bb[j][2]);
            }
        }
        WGBAR(wg);
    }

    // ---- fused epilogue: A2 = split(sd * O) for all 5 experts ----
    float inv0 = 1.0f / l[0], inv1 = 1.0f / l[1];
    int row0 = qt * 64 + w * 16 + g;
    int bt0  = b * 1024 + row0;

    float g0[Ee], g1[Ee];
#pragma unroll
    for (int e = 0; e < Ee; e++) {
        g0[e] = g_sdg[bt0 * HE + h * Ee + e];
        g1[e] = g_sdg[(bt0 + 8) * HE + h * Ee + e];
    }
    uint32_t* a2h0 = (uint32_t*)(g_W2 + A2H + (size_t)bt0 * V2);
    uint32_t* a2l0 = (uint32_t*)(g_W2 + A2L + (size_t)bt0 * V2);
    uint32_t* a2h1 = (uint32_t*)(g_W2 + A2H + (size_t)(bt0 + 8) * V2);
    uint32_t* a2l1 = (uint32_t*)(g_W2 + A2L + (size_t)(bt0 + 8) * V2);

#pragma unroll
    for (int na = 0; na < 8; na++) {
        int c0 = na * 8 + 2 * tig;
        float v00 = o[na][0] * inv0, v01 = o[na][1] * inv0;
        float v10 = o[na][2] * inv1, v11 = o[na][3] * inv1;
        uint32_t h0 = packbf(v00, v01), l0p = packres(h0, v00, v01);
        uint32_t h1 = packbf(v10, v11), l1p = packres(h1, v10, v11);
#pragma unroll
        for (int e = 0; e < Ee; e++) {
            int cw = ((h * Ee + e) * 64 + c0) >> 1;
            a2h0[cw] = (g0[e] != 0.f) ? h0  : 0u;
            a2l0[cw] = (g0[e] != 0.f) ? l0p : 0u;
            a2h1[cw] = (g1[e] != 0.f) ? h1  : 0u;
            a2l1[cw] = (g1[e] != 0.f) ? l1p : 0u;
        }
    }
}

// ---------------- launch ------------------------------------------------------
extern "C" void kernel_launch(void* const* d_in, const int* in_sizes, int n_in,
                              void* d_out, int out_size)
{
    const float* x  = (const float*)d_in[0];
    const float* Wq = (const float*)d_in[1];
    const float* Wk = (const float*)d_in[2];
    const float* Wv = (const float*)d_in[3];
    const float* Ws = (const float*)d_in[4];
    const float* Wd = (const float*)d_in[5];
    const float* Wo = (const float*)d_in[6];
    float* out = (float*)d_out;

    cudaFuncSetAttribute(gemm1,   cudaFuncAttributeMaxDynamicSharedMemorySize, GEMM_SMEM3);
    cudaFuncSetAttribute(gemm2,   cudaFuncAttributeMaxDynamicSharedMemorySize, GEMM_SMEM3);
    cudaFuncSetAttribute(attn_tc, cudaFuncAttributeMaxDynamicSharedMemorySize, ATTN_SMEM);

    prep_a1   <<<BT * DIMD / 256, 256>>>(x);
    prep_b1   <<<dim3(32, 120), dim3(32, 8)>>>(Wq, Wk, Wv, Ws, Wd);
    prep_b2   <<<HE * DIMD * 64 / 256, 256>>>(Wo);
    gemm1     <<<dim3(N1 / 64, BT / 128), 256, GEMM_SMEM3>>>();
    route_pack<<<16 * 512 * 64 / 256, 256>>>();
    attn_tc   <<<dim3(8, 16), 256, ATTN_SMEM>>>();
    gemm2     <<<dim3(N2 / 64, BT / 128), 256, GEMM_SMEM3>>>(out);
}

// round 10
// speedup vs baseline: 4.0580x; 1.1962x over previous
#include <cuda_runtime.h>
#include <cuda_bf16.h>
#include <cuda_fp16.h>
#include <cstdint>

#define Tt   1024
#define DIMD 1024
#define Hh   8
#define Ee   5
#define KK   3
#define BT   2048
#define HS   512
#define HE   40
#define QSCALE 0.125f

#define N1 3840
#define N2 1024
#define V2 2560

// ---------------- scratch ----------------------------------------------------
__device__ float g_C1 [BT * N1];
// bf16 blob for gemm1 (Q/K/SsSd path, 3-term)
#define A1H 0
#define A1L (BT * 1024)
#define B1H (2 * BT * 1024)
#define B1L (2 * BT * 1024 + N1 * 1024)
__device__ __nv_bfloat16 g_W1b[2 * BT * 1024 + 2 * N1 * 1024];
// fp16 blob for gemm1 V path (2-term)
#define A1Hf 0
#define A1Lf (BT * 1024)
#define B1Hf (2 * BT * 1024)
__device__ __half g_W1f[2 * BT * 1024 + N1 * 1024];
// fp16 blob for gemm2 (2-term)
#define A2H 0
#define A2L (BT * V2)
#define B2H (2 * BT * V2)
__device__ __half g_W2[2 * BT * V2 + N2 * V2];

__device__ float g_sdg[BT * HE];
__device__ uint32_t g_Qh[16 * 1024 * 32];
__device__ uint32_t g_Ql[16 * 1024 * 32];
__device__ uint32_t g_Kh[16 * 1024 * 32];
__device__ uint32_t g_Kl[16 * 1024 * 32];
__device__ uint32_t g_Vh[16 * 64 * 512];
__device__ uint32_t g_Vl[16 * 64 * 512];

// ---------------- helpers -----------------------------------------------------
__device__ __forceinline__ uint32_t smem_u32(const void* p) {
    uint32_t a;
    asm("{ .reg .u64 t; cvta.to.shared.u64 t, %1; cvt.u32.u64 %0, t; }" : "=r"(a) : "l"(p));
    return a;
}
__device__ __forceinline__ void cpasync16(uint32_t dst, const void* src) {
    asm volatile("cp.async.cg.shared.global [%0], [%1], 16;\n" :: "r"(dst), "l"(src));
}
__device__ __forceinline__ void cp_commit() { asm volatile("cp.async.commit_group;\n"); }
template<int N> __device__ __forceinline__ void cp_wait() { asm volatile("cp.async.wait_group %0;\n" :: "n"(N)); }

__device__ __forceinline__ void mma16816(float* c, const uint32_t* a, const uint32_t* b) {
    asm volatile(
        "mma.sync.aligned.m16n8k16.row.col.f32.bf16.bf16.f32 "
        "{%0,%1,%2,%3}, {%4,%5,%6,%7}, {%8,%9}, {%0,%1,%2,%3};"
        : "+f"(c[0]), "+f"(c[1]), "+f"(c[2]), "+f"(c[3])
        : "r"(a[0]), "r"(a[1]), "r"(a[2]), "r"(a[3]), "r"(b[0]), "r"(b[1]));
}
__device__ __forceinline__ void mma16816f(float* c, const uint32_t* a, const uint32_t* b) {
    asm volatile(
        "mma.sync.aligned.m16n8k16.row.col.f32.f16.f16.f32 "
        "{%0,%1,%2,%3}, {%4,%5,%6,%7}, {%8,%9}, {%0,%1,%2,%3};"
        : "+f"(c[0]), "+f"(c[1]), "+f"(c[2]), "+f"(c[3])
        : "r"(a[0]), "r"(a[1]), "r"(a[2]), "r"(a[3]), "r"(b[0]), "r"(b[1]));
}
__device__ __forceinline__ void ldm_x4(uint32_t* r, uint32_t addr) {
    asm volatile("ldmatrix.sync.aligned.m8n8.x4.shared.b16 {%0,%1,%2,%3}, [%4];"
        : "=r"(r[0]), "=r"(r[1]), "=r"(r[2]), "=r"(r[3]) : "r"(addr));
}
__device__ __forceinline__ uint32_t packbf(float lo, float hi) {
    uint32_t r;
    asm("cvt.rn.bf16x2.f32 %0, %1, %2;" : "=r"(r) : "f"(hi), "f"(lo));
    return r;
}
__device__ __forceinline__ uint32_t packres(uint32_t p, float lo, float hi) {
    float plo = __uint_as_float(p << 16);
    float phi = __uint_as_float(p & 0xffff0000u);
    return packbf(lo - plo, hi - phi);
}
#define WGBAR(id) asm volatile("bar.sync %0, 128;" :: "r"((id) + 1) : "memory")

// ---------------- bf16 3-term GEMM (shared fragments) ------------------------
// C = Ah@Bh^T + Al@Bh^T + Ah@Bl^T. FUSEQK: tiles n0<1024 write Q/K pair arrays.
template<int NT, int KTOT, bool FUSEQK>
__device__ __forceinline__ void gemm3_body(const char* __restrict__ W,
                                           uint32_t offAh, uint32_t offAl,
                                           uint32_t offBh, uint32_t offBl,
                                           float* __restrict__ C, int Ntot)
{
    constexpr int ROWS  = 256 + 2 * NT;
    constexpr int STAGE = ROWS * 64;
    constexpr int NSTEP = KTOT / 32;
    constexpr int NTW   = NT / 2;
    constexpr int NPAIR = NTW / 16;
    constexpr int NA    = NTW / 8;
    constexpr int CPT   = ROWS / 64;
    constexpr int NB    = NT / 64;
    constexpr size_t K2B = KTOT * 2;

    extern __shared__ char sm_raw[];
    const uint32_t sb = smem_u32(sm_raw);
    const int tid = threadIdx.x, wid = tid >> 5, lane = tid & 31;
    const int wm = wid & 3, wn = wid >> 2;
    const int m0 = blockIdx.y * 128, n0 = blockIdx.x * NT;

    const int r0 = tid >> 2;
    const int cc = (tid & 3) * 16;
    const uint32_t dst0 = r0 * 64 + (cc ^ (((r0 >> 1) & 3) * 16));
    const char* pAh = W + offAh + (size_t)(m0 + r0) * K2B + cc;
    const char* pAl = W + offAl + (size_t)(m0 + r0) * K2B + cc;
    const char* pBh = W + offBh + (size_t)(n0 + r0) * K2B + cc;
    const char* pBl = W + offBl + (size_t)(n0 + r0) * K2B + cc;

    auto issue = [&](int kt, int slot) {
        const uint32_t st = sb + slot * STAGE + dst0;
        const size_t gk = (size_t)kt * 64;
#pragma unroll
        for (int i = 0; i < CPT; i++) {
            const char* src;
            if      (i < 2)      src = pAh + (size_t)i * (64 * K2B);
            else if (i < 4)      src = pAl + (size_t)(i - 2) * (64 * K2B);
            else if (i < 4 + NB) src = pBh + (size_t)(i - 4) * (64 * K2B);
            else                 src = pBl + (size_t)(i - 4 - NB) * (64 * K2B);
            cpasync16(st + i * 4096, src + gk);
        }
    };

    const uint32_t ahi = (lane >> 4) * 16;
    const uint32_t bhi = ((lane >> 3) & 1) * 16;
    uint32_t aof[2], aswz[2], bof[NPAIR], bswz[NPAIR];
#pragma unroll
    for (int mi = 0; mi < 2; mi++) {
        int r = wm * 32 + mi * 16 + (lane & 15);
        aof[mi] = r * 64; aswz[mi] = ((r >> 1) & 3) * 16;
    }
#pragma unroll
    for (int pj = 0; pj < NPAIR; pj++) {
        int r = wn * NTW + pj * 16 + ((lane >> 4) << 3) + (lane & 7);
        bof[pj] = (256 + r) * 64; bswz[pj] = ((r >> 1) & 3) * 16;
    }

    float acc[2][NA][4];
#pragma unroll
    for (int mi = 0; mi < 2; mi++)
#pragma unroll
        for (int na = 0; na < NA; na++)
#pragma unroll
            for (int q = 0; q < 4; q++) acc[mi][na][q] = 0.f;

    issue(0, 0); cp_commit();
    issue(1, 1); cp_commit();

    for (int kt = 0; kt < NSTEP; kt++) {
        if (kt + 1 < NSTEP) cp_wait<1>(); else cp_wait<0>();
        __syncthreads();
        if (kt + 2 < NSTEP) { issue(kt + 2, (kt + 2) % 3); cp_commit(); }

        uint32_t stg = sb + (kt % 3) * STAGE;
#pragma unroll
        for (int ks = 0; ks < 2; ks++) {
            const uint32_t ca = (uint32_t)ks * 32 + ahi;
            const uint32_t cb = (uint32_t)ks * 32 + bhi;
            uint32_t ah[2][4], al[2][4], bb[NPAIR][4];
            ldm_x4(ah[0], stg + aof[0] + (ca ^ aswz[0]));
            ldm_x4(ah[1], stg + aof[1] + (ca ^ aswz[1]));
            ldm_x4(al[0], stg + 8192 + aof[0] + (ca ^ aswz[0]));
            ldm_x4(al[1], stg + 8192 + aof[1] + (ca ^ aswz[1]));
#pragma unroll
            for (int pj = 0; pj < NPAIR; pj++)
                ldm_x4(bb[pj], stg + bof[pj] + (cb ^ bswz[pj]));
#pragma unroll
            for (int mi = 0; mi < 2; mi++)
#pragma unroll
                for (int pj = 0; pj < NPAIR; pj++) {
                    mma16816(acc[mi][2 * pj],     ah[mi], &bb[pj][0]);
                    mma16816(acc[mi][2 * pj + 1], ah[mi], &bb[pj][2]);
                }
#pragma unroll
            for (int mi = 0; mi < 2; mi++)
#pragma unroll
                for (int pj = 0; pj < NPAIR; pj++) {
                    mma16816(acc[mi][2 * pj],     al[mi], &bb[pj][0]);
                    mma16816(acc[mi][2 * pj + 1], al[mi], &bb[pj][2]);
                }
#pragma unroll
            for (int pj = 0; pj < NPAIR; pj++)
                ldm_x4(bb[pj], stg + bof[pj] + NT * 64 + (cb ^ bswz[pj]));
#pragma unroll
            for (int mi = 0; mi < 2; mi++)
#pragma unroll
                for (int pj = 0; pj < NPAIR; pj++) {
                    mma16816(acc[mi][2 * pj],     ah[mi], &bb[pj][0]);
                    mma16816(acc[mi][2 * pj + 1], ah[mi], &bb[pj][2]);
                }
        }
    }

    const int g  = lane >> 2;
    const int tg = lane & 3;

    if (FUSEQK && n0 < 1024) {
        const bool isQ = (n0 < 512);
        const float sc = isQ ? QSCALE : 1.0f;
        uint32_t* dh = isQ ? g_Qh : g_Kh;
        uint32_t* dl = isQ ? g_Ql : g_Kl;
#pragma unroll
        for (int mi = 0; mi < 2; mi++) {
            int r = m0 + wm * 32 + mi * 16 + g;
            int b_ = r >> 10, t = r & 1023;
#pragma unroll
            for (int na = 0; na < NA; na++) {
                int ccc = n0 + wn * NTW + na * 8 + tg * 2;
                int h = (ccc >> 6) & 7;
                int p = (ccc & 63) >> 1;
                size_t base = (((size_t)(b_ * 8 + h) << 10) + t) * 32 + p;
                float v0 = acc[mi][na][0] * sc, v1 = acc[mi][na][1] * sc;
                uint32_t h0 = packbf(v0, v1);
                dh[base] = h0; dl[base] = packres(h0, v0, v1);
                float w0 = acc[mi][na][2] * sc, w1 = acc[mi][na][3] * sc;
                uint32_t h1 = packbf(w0, w1);
                dh[base + 8 * 32] = h1; dl[base + 8 * 32] = packres(h1, w0, w1);
            }
        }
    } else {
#pragma unroll
        for (int mi = 0; mi < 2; mi++) {
            int r = m0 + wm * 32 + mi * 16 + g;
#pragma unroll
            for (int na = 0; na < NA; na++) {
                int ccc = n0 + wn * NTW + na * 8 + tg * 2;
                *(float2*)(C + (size_t)r * Ntot + ccc)       = make_float2(acc[mi][na][0], acc[mi][na][1]);
                *(float2*)(C + (size_t)(r + 8) * Ntot + ccc) = make_float2(acc[mi][na][2], acc[mi][na][3]);
            }
        }
    }
}

// ---------------- fp16 2-term GEMM: C = Ah@Bh^T + Al@Bh^T --------------------
template<int NT, int KTOT>
__device__ __forceinline__ void gemm2f_body(const char* __restrict__ W,
                                            uint32_t offAh, uint32_t offAl,
                                            uint32_t offBh,
                                            float* __restrict__ C, int Ntot)
{
    constexpr int ROWS  = 256 + NT;     // Ah(128)|Al(128)|Bh(NT)
    constexpr int STAGE = ROWS * 64;
    constexpr int NSTEP = KTOT / 32;
    constexpr int NTW   = NT / 2;
    constexpr int NPAIR = NTW / 16;
    constexpr int NA    = NTW / 8;
    constexpr int CPT   = ROWS / 64;
    constexpr size_t K2B = KTOT * 2;

    extern __shared__ char sm_raw[];
    const uint32_t sb = smem_u32(sm_raw);
    const int tid = threadIdx.x, wid = tid >> 5, lane = tid & 31;
    const int wm = wid & 3, wn = wid >> 2;
    const int m0 = blockIdx.y * 128, n0 = blockIdx.x * NT;

    const int r0 = tid >> 2;
    const int cc = (tid & 3) * 16;
    const uint32_t dst0 = r0 * 64 + (cc ^ (((r0 >> 1) & 3) * 16));
    const char* pAh = W + offAh + (size_t)(m0 + r0) * K2B + cc;
    const char* pAl = W + offAl + (size_t)(m0 + r0) * K2B + cc;
    const char* pBh = W + offBh + (size_t)(n0 + r0) * K2B + cc;

    auto issue = [&](int kt, int slot) {
        const uint32_t st = sb + slot * STAGE + dst0;
        const size_t gk = (size_t)kt * 64;
#pragma unroll
        for (int i = 0; i < CPT; i++) {
            const char* src;
            if      (i < 2) src = pAh + (size_t)i * (64 * K2B);
            else if (i < 4) src = pAl + (size_t)(i - 2) * (64 * K2B);
            else            src = pBh + (size_t)(i - 4) * (64 * K2B);
            cpasync16(st + i * 4096, src + gk);
        }
    };

    const uint32_t ahi = (lane >> 4) * 16;
    const uint32_t bhi = ((lane >> 3) & 1) * 16;
    uint32_t aof[2], aswz[2], bof[NPAIR], bswz[NPAIR];
#pragma unroll
    for (int mi = 0; mi < 2; mi++) {
        int r = wm * 32 + mi * 16 + (lane & 15);
        aof[mi] = r * 64; aswz[mi] = ((r >> 1) & 3) * 16;
    }
#pragma unroll
    for (int pj = 0; pj < NPAIR; pj++) {
        int r = wn * NTW + pj * 16 + ((lane >> 4) << 3) + (lane & 7);
        bof[pj] = (256 + r) * 64; bswz[pj] = ((r >> 1) & 3) * 16;
    }

    float acc[2][NA][4];
#pragma unroll
    for (int mi = 0; mi < 2; mi++)
#pragma unroll
        for (int na = 0; na < NA; na++)
#pragma unroll
            for (int q = 0; q < 4; q++) acc[mi][na][q] = 0.f;

    issue(0, 0); cp_commit();
    issue(1, 1); cp_commit();

    for (int kt = 0; kt < NSTEP; kt++) {
        if (kt + 1 < NSTEP) cp_wait<1>(); else cp_wait<0>();
        __syncthreads();
        if (kt + 2 < NSTEP) { issue(kt + 2, (kt + 2) % 3); cp_commit(); }

        uint32_t stg = sb + (kt % 3) * STAGE;
#pragma unroll
        for (int ks = 0; ks < 2; ks++) {
            const uint32_t ca = (uint32_t)ks * 32 + ahi;
            const uint32_t cb = (uint32_t)ks * 32 + bhi;
            uint32_t ah[2][4], al[2][4], bb[NPAIR][4];
            ldm_x4(ah[0], stg + aof[0] + (ca ^ aswz[0]));
            ldm_x4(ah[1], stg + aof[1] + (ca ^ aswz[1]));
            ldm_x4(al[0], stg + 8192 + aof[0] + (ca ^ aswz[0]));
            ldm_x4(al[1], stg + 8192 + aof[1] + (ca ^ aswz[1]));
#pragma unroll
            for (int pj = 0; pj < NPAIR; pj++)
                ldm_x4(bb[pj], stg + bof[pj] + (cb ^ bswz[pj]));
#pragma unroll
            for (int mi = 0; mi < 2; mi++)
#pragma unroll
                for (int pj = 0; pj < NPAIR; pj++) {
                    mma16816f(acc[mi][2 * pj],     ah[mi], &bb[pj][0]);
                    mma16816f(acc[mi][2 * pj + 1], ah[mi], &bb[pj][2]);
                }
#pragma unroll
            for (int mi = 0; mi < 2; mi++)
#pragma unroll
                for (int pj = 0; pj < NPAIR; pj++) {
                    mma16816f(acc[mi][2 * pj],     al[mi], &bb[pj][0]);
                    mma16816f(acc[mi][2 * pj + 1], al[mi], &bb[pj][2]);
                }
        }
    }

    const int g  = lane >> 2;
    const int tg = lane & 3;
#pragma unroll
    for (int mi = 0; mi < 2; mi++) {
        int r = m0 + wm * 32 + mi * 16 + g;
#pragma unroll
        for (int na = 0; na < NA; na++) {
            int ccc = n0 + wn * NTW + na * 8 + tg * 2;
            *(float2*)(C + (size_t)r * Ntot + ccc)       = make_float2(acc[mi][na][0], acc[mi][na][1]);
            *(float2*)(C + (size_t)(r + 8) * Ntot + ccc) = make_float2(acc[mi][na][2], acc[mi][na][3]);
        }
    }
}

#define GEMM_SMEM3 (3 * (256 + 128) * 64)   // 73728 (covers both bodies, NT=64)

__global__ __launch_bounds__(256, 3)
void gemm1() {
    if (blockIdx.x < 16 || blockIdx.x >= 56)
        gemm3_body<64, 1024, true>((const char*)g_W1b, A1H * 2, A1L * 2, B1H * 2, B1L * 2, g_C1, N1);
    else
        gemm2f_body<64, 1024>((const char*)g_W1f, A1Hf * 2, A1Lf * 2, B1Hf * 2, g_C1, N1);
}
__global__ __launch_bounds__(256, 3)
void gemm2(float* __restrict__ out) {
    gemm2f_body<64, 2560>((const char*)g_W2, A2H * 2, A2L * 2, B2H * 2, out, N2);
}

// ---------------- prep kernels ----------------------------------------------
__device__ __forceinline__ void split_bf16(float v, __nv_bfloat16& hi, __nv_bfloat16& lo) {
    hi = __float2bfloat16(v);
    lo = __float2bfloat16(v - __bfloat162float(hi));
}

__global__ __launch_bounds__(256) void prep_a1(const float* __restrict__ x) {
    int gid = blockIdx.x * 256 + threadIdx.x;
    float v = x[gid];
    __nv_bfloat16 hi, lo; split_bf16(v, hi, lo);
    g_W1b[A1H + gid] = hi;
    g_W1b[A1L + gid] = lo;
    __half fh = __float2half_rn(v);
    __half fl = __float2half_rn(v - __half2float(fh));
    g_W1f[A1Hf + gid] = fh;
    g_W1f[A1Lf + gid] = fl;
}

__global__ void prep_b1(const float* __restrict__ Wq, const float* __restrict__ Wk,
                        const float* __restrict__ Wv, const float* __restrict__ Ws,
                        const float* __restrict__ Wd)
{
    __shared__ float tile[32][33];
    int k0 = blockIdx.x * 32;
    int n0 = blockIdx.y * 32;
    int tx = threadIdx.x, ty = threadIdx.y;
#pragma unroll
    for (int yy = 0; yy < 32; yy += 8) {
        int k = k0 + ty + yy, n = n0 + tx;
        float w;
        if      (n < 512)  w = Wq[(size_t)k * 512  + n];
        else if (n < 1024) w = Wk[(size_t)k * 512  + n - 512];
        else if (n < 3584) w = Wv[(size_t)k * 2560 + n - 1024];
        else if (n < 3624) w = Ws[(size_t)k * 40   + n - 3584];
        else if (n < 3664) w = Wd[(size_t)k * 40   + n - 3624];
        else               w = 0.f;
        tile[ty + yy][tx] = w;
    }
    __syncthreads();
#pragma unroll
    for (int yy = 0; yy < 32; yy += 8) {
        int n = n0 + ty + yy, k = k0 + tx;
        float w = tile[tx][ty + yy];
        int idx = n * 1024 + k;
        if (n < 1024 || n >= 3584) {           // Q/K/SsSd: bf16 3-term
            __nv_bfloat16 hi, lo; split_bf16(w, hi, lo);
            g_W1b[B1H + idx] = hi;
            g_W1b[B1L + idx] = lo;
        } else {                                // V: fp16 2-term
            g_W1f[B1Hf + idx] = __float2half_rn(w);
        }
    }
}

__global__ __launch_bounds__(256) void prep_b2(const float* __restrict__ Wo) {
    int gid = blockIdx.x * 256 + threadIdx.x;
    int he = gid >> 16;
    int d  = (gid >> 6) & 1023;
    int c  = gid & 63;
    g_W2[B2H + d * V2 + he * 64 + c] = __float2half_rn(Wo[gid]);
}

// ---------------- fused routing gates + expert V mix + transposed pack -------
__global__ __launch_bounds__(256) void route_pack() {
    __shared__ uint32_t tvh[4][65], tvl[4][65];
    int gid = blockIdx.x * 256 + threadIdx.x;
    int d  = gid & 63;
    int kp = (gid >> 6) & 511;
    int bh = gid >> 15;
    int b = bh >> 3, h = bh & 7;

    float v[2];
#pragma unroll
    for (int u = 0; u < 2; u++) {
        int t = kp * 2 + u;
        const float* row = g_C1 + (size_t)(b * 1024 + t) * N1;
        const float* sl = row + 3584 + h * Ee;
        float s[Ee];
#pragma unroll
        for (int e = 0; e < Ee; e++) s[e] = sl[e];
        float acc = 0.f;
#pragma unroll
        for (int e = 0; e < Ee; e++) {
            int rank = 0;
#pragma unroll
            for (int j = 0; j < Ee; j++)
                rank += (s[j] > s[e]) || (s[j] == s[e] && j < e);
            float gate = (rank < KK) ? 1.0f / (1.0f + expf(-s[e])) : 0.f;
            acc = fmaf(gate, row[1024 + (h * Ee + e) * 64 + d], acc);
        }
        v[u] = acc;

        if (d < Ee) {
            const float* dl = row + 3624 + h * Ee;
            float tq[Ee];
#pragma unroll
            for (int e = 0; e < Ee; e++) tq[e] = dl[e];
            int e = d, rank = 0;
#pragma unroll
            for (int j = 0; j < Ee; j++)
                rank += (tq[j] > tq[e]) || (tq[j] == tq[e] && j < e);
            g_sdg[(b * 1024 + t) * HE + h * Ee + e] = (rank < KK) ? 1.f : 0.f;
        }
    }
    uint32_t vh = packbf(v[0], v[1]);
    tvh[kp & 3][d] = vh;
    tvl[kp & 3][d] = packres(vh, v[0], v[1]);
    __syncthreads();
    int td  = threadIdx.x >> 2;
    int tk4 = threadIdx.x & 3;
    int kp0 = (blockIdx.x * 4) & 511;
    size_t oidx = ((size_t)bh * 64 + td) * 512 + kp0 + tk4;
    g_Vh[oidx] = tvh[tk4][td];
    g_Vl[oidx] = tvl[tk4][td];
}

// ---------------- tensor-core causal flash attention, paired q-tiles ---------
#define AQS   (64 * 36)
#define ATL   (64 * 36)
#define ASTG  (4 * ATL)
#define AWG_U (2 * AQS + 2 * ASTG)
#define ATTN_SMEM (2 * AWG_U * 4)

__global__ __launch_bounds__(256) void attn_tc() {
    extern __shared__ uint32_t sm[];
    const int bh   = blockIdx.y;
    const int b    = bh >> 3, h = bh & 7;
    const int wg   = threadIdx.x >> 7;
    const int qt   = wg ? (15 - blockIdx.x) : blockIdx.x;
    const int tid  = threadIdx.x & 127;
    const int w    = tid >> 5;
    const int lane = tid & 31;
    const int g    = lane >> 2;
    const int tig  = lane & 3;
    uint32_t* smg  = sm + wg * AWG_U;
    const uint32_t sb = smem_u32(smg);

    auto issue = [&](int kt, int s) {
#pragma unroll
        for (int i = 0; i < 16; i++) {
            int a = i >> 2;
            int r = (i & 3) * 16 + (tid >> 3);
            int c = tid & 7;
            uint32_t dst = sb + (2 * AQS + s * ASTG + a * ATL + r * 36) * 4 + c * 16;
            const uint32_t* srcb;
            if      (a == 0) srcb = g_Kh + ((size_t)(bh << 10) + kt * 64 + r) * 32;
            else if (a == 1) srcb = g_Kl + ((size_t)(bh << 10) + kt * 64 + r) * 32;
            else if (a == 2) srcb = g_Vh + ((size_t)bh * 64 + r) * 512 + kt * 32;
            else             srcb = g_Vl + ((size_t)bh * 64 + r) * 512 + kt * 32;
            cpasync16(dst, (const char*)srcb + c * 16);
        }
    };
    issue(0, 0); cp_commit();

    {
        const uint32_t* qhsrc = g_Qh + ((size_t)(bh << 10) + qt * 64) * 32;
        const uint32_t* qlsrc = g_Ql + ((size_t)(bh << 10) + qt * 64) * 32;
#pragma unroll
        for (int j = 0; j < 4; j++) {
            int idx = tid + j * 128;
            int row = idx >> 3, po = (idx & 7) * 4;
            *(uint4*)&smg[row * 36 + po]       = *(const uint4*)(qhsrc + row * 32 + po);
            *(uint4*)&smg[AQS + row * 36 + po] = *(const uint4*)(qlsrc + row * 32 + po);
        }
    }
    WGBAR(wg);

    uint32_t qa[2][4][4];
#pragma unroll
    for (int hl = 0; hl < 2; hl++) {
        int qb = hl * AQS;
#pragma unroll
        for (int kb = 0; kb < 4; kb++) {
            qa[hl][kb][0] = smg[qb + (w * 16 + g)     * 36 + kb * 8 + tig];
            qa[hl][kb][1] = smg[qb + (w * 16 + g + 8) * 36 + kb * 8 + tig];
            qa[hl][kb][2] = smg[qb + (w * 16 + g)     * 36 + kb * 8 + 4 + tig];
            qa[hl][kb][3] = smg[qb + (w * 16 + g + 8) * 36 + kb * 8 + 4 + tig];
        }
    }

    const int li   = lane >> 3;
    const uint32_t lbase = (((li >> 1) * 8 + (lane & 7)) * 36 + (li & 1) * 4) * 4;

    float o[8][4];
#pragma unroll
    for (int a = 0; a < 8; a++)
#pragma unroll
        for (int q = 0; q < 4; q++) o[a][q] = 0.f;
    float m[2] = {-1e30f, -1e30f}, l[2] = {0.f, 0.f};

    for (int kt = 0; kt <= qt; kt++) {
        if (kt < qt) { issue(kt + 1, (kt + 1) & 1); cp_commit(); cp_wait<1>(); }
        else         { cp_wait<0>(); }
        WGBAR(wg);

        const uint32_t su = sb + (2 * AQS + (kt & 1) * ASTG) * 4;
        const uint32_t Khb = su,               Klb = su + ATL * 4;
        const uint32_t Vhb = su + 2 * ATL * 4, Vlb = su + 3 * ATL * 4;

        float s[8][4];
#pragma unroll
        for (int a = 0; a < 8; a++)
#pragma unroll
            for (int q = 0; q < 4; q++) s[a][q] = 0.f;

#pragma unroll
        for (int kb = 0; kb < 4; kb++) {
            uint32_t bb[4][4];
#pragma unroll
            for (int j = 0; j < 4; j++)
                ldm_x4(bb[j], Khb + lbase + (j * 576 + kb * 8) * 4);
#pragma unroll
            for (int j = 0; j < 4; j++) {
                mma16816(s[2*j],   qa[0][kb], &bb[j][0]);
                mma16816(s[2*j+1], qa[0][kb], &bb[j][2]);
            }
#pragma unroll
            for (int j = 0; j < 4; j++) {
                mma16816(s[2*j],   qa[1][kb], &bb[j][0]);
                mma16816(s[2*j+1], qa[1][kb], &bb[j][2]);
            }
#pragma unroll
            for (int j = 0; j < 4; j++)
                ldm_x4(bb[j], Klb + lbase + (j * 576 + kb * 8) * 4);
#pragma unroll
            for (int j = 0; j < 4; j++) {
                mma16816(s[2*j],   qa[0][kb], &bb[j][0]);
                mma16816(s[2*j+1], qa[0][kb], &bb[j][2]);
            }
        }

        if (kt == qt) {
            int r0 = w * 16 + g;
#pragma unroll
            for (int na = 0; na < 8; na++) {
                int c0 = na * 8 + 2 * tig;
                if (c0     > r0)     s[na][0] = -1e9f;
                if (c0 + 1 > r0)     s[na][1] = -1e9f;
                if (c0     > r0 + 8) s[na][2] = -1e9f;
                if (c0 + 1 > r0 + 8) s[na][3] = -1e9f;
            }
        }

#pragma unroll
        for (int ri = 0; ri < 2; ri++) {
            float mx = -1e30f;
#pragma unroll
            for (int a = 0; a < 8; a++)
                mx = fmaxf(mx, fmaxf(s[a][2 * ri], s[a][2 * ri + 1]));
            mx = fmaxf(mx, __shfl_xor_sync(0xffffffffu, mx, 1));
            mx = fmaxf(mx, __shfl_xor_sync(0xffffffffu, mx, 2));
            float mnew = fmaxf(m[ri], mx);
            float corr = __expf(m[ri] - mnew);
            float rs = 0.f;
#pragma unroll
            for (int a = 0; a < 8; a++) {
                float p0 = __expf(s[a][2 * ri]     - mnew);
                float p1 = __expf(s[a][2 * ri + 1] - mnew);
                s[a][2 * ri] = p0; s[a][2 * ri + 1] = p1;
                rs += p0 + p1;
            }
            rs += __shfl_xor_sync(0xffffffffu, rs, 1);
            rs += __shfl_xor_sync(0xffffffffu, rs, 2);
            l[ri] = l[ri] * corr + rs;
            m[ri] = mnew;
#pragma unroll
            for (int a = 0; a < 8; a++) { o[a][2 * ri] *= corr; o[a][2 * ri + 1] *= corr; }
        }

#pragma unroll
        for (int kb = 0; kb < 4; kb++) {
            uint32_t ph[4], pl[4];
            ph[0] = packbf(s[2*kb][0],   s[2*kb][1]);
            ph[1] = packbf(s[2*kb][2],   s[2*kb][3]);
            ph[2] = packbf(s[2*kb+1][0], s[2*kb+1][1]);
            ph[3] = packbf(s[2*kb+1][2], s[2*kb+1][3]);
            pl[0] = packres(ph[0], s[2*kb][0],   s[2*kb][1]);
            pl[1] = packres(ph[1], s[2*kb][2],   s[2*kb][3]);
            pl[2] = packres(ph[2], s[2*kb+1][0], s[2*kb+1][1]);
            pl[3] = packres(ph[3], s[2*kb+1][2], s[2*kb+1][3]);

            uint32_t bb[4][4];
#pragma unroll
            for (int j = 0; j < 4; j++)
                ldm_x4(bb[j], Vhb + lbase + (j * 576 + kb * 8) * 4);
#pragma unroll
            for (int j = 0; j < 4; j++) {
                mma16816(o[2*j],   ph, &bb[j][0]);
                mma16816(o[2*j+1], ph, &bb[j][2]);
            }
#pragma unroll
            for (int j = 0; j < 4; j++) {
                mma16816(o[2*j],   pl, &bb[j][0]);
                mma16816(o[2*j+1], pl, &bb[j][2]);
            }
#pragma unroll
            for (int j = 0; j < 4; j++)
                ldm_x4(bb[j], Vlb + lbase + (j * 576 + kb * 8) * 4);
#pragma unroll
            for (int j = 0; j < 4; j++) {
                mma16816(o[2*j],   ph, &bb[j][0]);
                mma16816(o[2*j+1], ph, &bb[j][2]);
            }
        }
        WGBAR(wg);
    }

    // ---- fused epilogue: A2 = fp16-split(sd * O) for all 5 experts ----
    float inv0 = 1.0f / l[0], inv1 = 1.0f / l[1];
    int row0 = qt * 64 + w * 16 + g;
    int bt0  = b * 1024 + row0;

    float g0[Ee], g1[Ee];
#pragma unroll
    for (int e = 0; e < Ee; e++) {
        g0[e] = g_sdg[bt0 * HE + h * Ee + e];
        g1[e] = g_sdg[(bt0 + 8) * HE + h * Ee + e];
    }
    uint32_t* a2h0 = (uint32_t*)(g_W2 + A2H + (size_t)bt0 * V2);
    uint32_t* a2l0 = (uint32_t*)(g_W2 + A2L + (size_t)bt0 * V2);
    uint32_t* a2h1 = (uint32_t*)(g_W2 + A2H + (size_t)(bt0 + 8) * V2);
    uint32_t* a2l1 = (uint32_t*)(g_W2 + A2L + (size_t)(bt0 + 8) * V2);

#pragma unroll
    for (int na = 0; na < 8; na++) {
        int c0 = na * 8 + 2 * tig;
        float v00 = o[na][0] * inv0, v01 = o[na][1] * inv0;
        float v10 = o[na][2] * inv1, v11 = o[na][3] * inv1;
        __half2 hh0 = __floats2half2_rn(v00, v01);
        float2  bk0 = __half22float2(hh0);
        __half2 ll0 = __floats2half2_rn(v00 - bk0.x, v01 - bk0.y);
        __half2 hh1 = __floats2half2_rn(v10, v11);
        float2  bk1 = __half22float2(hh1);
        __half2 ll1 = __floats2half2_rn(v10 - bk1.x, v11 - bk1.y);
        uint32_t h0u = *(uint32_t*)&hh0, l0u = *(uint32_t*)&ll0;
        uint32_t h1u = *(uint32_t*)&hh1, l1u = *(uint32_t*)&ll1;
#pragma unroll
        for (int e = 0; e < Ee; e++) {
            int cw = ((h * Ee + e) * 64 + c0) >> 1;
            a2h0[cw] = (g0[e] != 0.f) ? h0u : 0u;
            a2l0[cw] = (g0[e] != 0.f) ? l0u : 0u;
            a2h1[cw] = (g1[e] != 0.f) ? h1u : 0u;
            a2l1[cw] = (g1[e] != 0.f) ? l1u : 0u;
        }
    }
}

// ---------------- launch ------------------------------------------------------
extern "C" void kernel_launch(void* const* d_in, const int* in_sizes, int n_in,
                              void* d_out, int out_size)
{
    const float* x  = (const float*)d_in[0];
    const float* Wq = (const float*)d_in[1];
    const float* Wk = (const float*)d_in[2];
    const float* Wv = (const float*)d_in[3];
    const float* Ws = (const float*)d_in[4];
    const float* Wd = (const float*)d_in[5];
    const float* Wo = (const float*)d_in[6];
    float* out = (float*)d_out;

    cudaFuncSetAttribute(gemm1,   cudaFuncAttributeMaxDynamicSharedMemorySize, GEMM_SMEM3);
    cudaFuncSetAttribute(gemm2,   cudaFuncAttributeMaxDynamicSharedMemorySize, GEMM_SMEM3);
    cudaFuncSetAttribute(attn_tc, cudaFuncAttributeMaxDynamicSharedMemorySize, ATTN_SMEM);

    prep_a1   <<<BT * DIMD / 256, 256>>>(x);
    prep_b1   <<<dim3(32, 120), dim3(32, 8)>>>(Wq, Wk, Wv, Ws, Wd);
    prep_b2   <<<HE * DIMD * 64 / 256, 256>>>(Wo);
    gemm1     <<<dim3(N1 / 64, BT / 128), 256, GEMM_SMEM3>>>();
    route_pack<<<16 * 512 * 64 / 256, 256>>>();
    attn_tc   <<<dim3(8, 16), 256, ATTN_SMEM>>>();
    gemm2     <<<dim3(N2 / 64, BT / 128), 256, GEMM_SMEM3>>>(out);
}

// round 11
// speedup vs baseline: 4.4121x; 1.0873x over previous
#include <cuda_runtime.h>
#include <cuda_bf16.h>
#include <cuda_fp16.h>
#include <cstdint>

#define Tt   1024
#define DIMD 1024
#define Hh   8
#define Ee   5
#define KK   3
#define BT   2048
#define HS   512
#define HE   40
#define QSCALE 0.125f

#define N1 3840
#define N2 1024
#define V2 2560

// ---------------- scratch ----------------------------------------------------
__device__ float g_C1 [BT * N1];
// bf16 blob: A(hi,lo) full; B(hi,lo) used only for SsSd rows (n>=3584)
#define A1H 0
#define A1L (BT * 1024)
#define B1H (2 * BT * 1024)
#define B1L (2 * BT * 1024 + N1 * 1024)
__device__ __nv_bfloat16 g_W1b[2 * BT * 1024 + 2 * N1 * 1024];
// fp16 blob: A(hi,lo); B(hi) for Q/K/V rows (n<3584)
#define A1Hf 0
#define A1Lf (BT * 1024)
#define B1Hf (2 * BT * 1024)
__device__ __half g_W1f[2 * BT * 1024 + N1 * 1024];
// fp16 blob for gemm2
#define A2H 0
#define A2L (BT * V2)
#define B2H (2 * BT * V2)
__device__ __half g_W2[2 * BT * V2 + N2 * V2];

__device__ float g_sdg[BT * HE];
// attention operands: packed fp16x2 pairs
__device__ uint32_t g_Qh[16 * 1024 * 32];   // [bh][t][dpair]
__device__ uint32_t g_Ql[16 * 1024 * 32];
__device__ uint32_t g_Kh[16 * 1024 * 32];   // single-rounded fp16
__device__ uint32_t g_Vh[16 * 64 * 512];    // [bh][d][tpair], single-rounded fp16

// ---------------- helpers -----------------------------------------------------
__device__ __forceinline__ uint32_t smem_u32(const void* p) {
    uint32_t a;
    asm("{ .reg .u64 t; cvta.to.shared.u64 t, %1; cvt.u32.u64 %0, t; }" : "=r"(a) : "l"(p));
    return a;
}
__device__ __forceinline__ void cpasync16(uint32_t dst, const void* src) {
    asm volatile("cp.async.cg.shared.global [%0], [%1], 16;\n" :: "r"(dst), "l"(src));
}
__device__ __forceinline__ void cp_commit() { asm volatile("cp.async.commit_group;\n"); }
template<int N> __device__ __forceinline__ void cp_wait() { asm volatile("cp.async.wait_group %0;\n" :: "n"(N)); }

__device__ __forceinline__ void mma16816(float* c, const uint32_t* a, const uint32_t* b) {
    asm volatile(
        "mma.sync.aligned.m16n8k16.row.col.f32.bf16.bf16.f32 "
        "{%0,%1,%2,%3}, {%4,%5,%6,%7}, {%8,%9}, {%0,%1,%2,%3};"
        : "+f"(c[0]), "+f"(c[1]), "+f"(c[2]), "+f"(c[3])
        : "r"(a[0]), "r"(a[1]), "r"(a[2]), "r"(a[3]), "r"(b[0]), "r"(b[1]));
}
__device__ __forceinline__ void mma16816f(float* c, const uint32_t* a, const uint32_t* b) {
    asm volatile(
        "mma.sync.aligned.m16n8k16.row.col.f32.f16.f16.f32 "
        "{%0,%1,%2,%3}, {%4,%5,%6,%7}, {%8,%9}, {%0,%1,%2,%3};"
        : "+f"(c[0]), "+f"(c[1]), "+f"(c[2]), "+f"(c[3])
        : "r"(a[0]), "r"(a[1]), "r"(a[2]), "r"(a[3]), "r"(b[0]), "r"(b[1]));
}
__device__ __forceinline__ void ldm_x4(uint32_t* r, uint32_t addr) {
    asm volatile("ldmatrix.sync.aligned.m8n8.x4.shared.b16 {%0,%1,%2,%3}, [%4];"
        : "=r"(r[0]), "=r"(r[1]), "=r"(r[2]), "=r"(r[3]) : "r"(addr));
}
__device__ __forceinline__ uint32_t packh2(float lo, float hi) {
    __half2 h = __floats2half2_rn(lo, hi);
    return *(uint32_t*)&h;
}
__device__ __forceinline__ uint32_t packh2res(uint32_t p, float lo, float hi) {
    __half2 ph = *(__half2*)&p;
    float2 bk = __half22float2(ph);
    return packh2(lo - bk.x, hi - bk.y);
}
__device__ __forceinline__ uint32_t packbf(float lo, float hi) {
    uint32_t r;
    asm("cvt.rn.bf16x2.f32 %0, %1, %2;" : "=r"(r) : "f"(hi), "f"(lo));
    return r;
}
#define WGBAR(id) asm volatile("bar.sync %0, 128;" :: "r"((id) + 1) : "memory")

// ---------------- bf16 3-term GEMM (SsSd path) -------------------------------
template<int NT, int KTOT>
__device__ __forceinline__ void gemm3_body(const char* __restrict__ W,
                                           uint32_t offAh, uint32_t offAl,
                                           uint32_t offBh, uint32_t offBl,
                                           float* __restrict__ C, int Ntot)
{
    constexpr int ROWS  = 256 + 2 * NT;
    constexpr int STAGE = ROWS * 64;
    constexpr int NSTEP = KTOT / 32;
    constexpr int NTW   = NT / 2;
    constexpr int NPAIR = NTW / 16;
    constexpr int NA    = NTW / 8;
    constexpr int CPT   = ROWS / 64;
    constexpr int NB    = NT / 64;
    constexpr size_t K2B = KTOT * 2;

    extern __shared__ char sm_raw[];
    const uint32_t sb = smem_u32(sm_raw);
    const int tid = threadIdx.x, wid = tid >> 5, lane = tid & 31;
    const int wm = wid & 3, wn = wid >> 2;
    const int m0 = blockIdx.y * 128, n0 = blockIdx.x * NT;

    const int r0 = tid >> 2;
    const int cc = (tid & 3) * 16;
    const uint32_t dst0 = r0 * 64 + (cc ^ (((r0 >> 1) & 3) * 16));
    const char* pAh = W + offAh + (size_t)(m0 + r0) * K2B + cc;
    const char* pAl = W + offAl + (size_t)(m0 + r0) * K2B + cc;
    const char* pBh = W + offBh + (size_t)(n0 + r0) * K2B + cc;
    const char* pBl = W + offBl + (size_t)(n0 + r0) * K2B + cc;

    auto issue = [&](int kt, int slot) {
        const uint32_t st = sb + slot * STAGE + dst0;
        const size_t gk = (size_t)kt * 64;
#pragma unroll
        for (int i = 0; i < CPT; i++) {
            const char* src;
            if      (i < 2)      src = pAh + (size_t)i * (64 * K2B);
            else if (i < 4)      src = pAl + (size_t)(i - 2) * (64 * K2B);
            else if (i < 4 + NB) src = pBh + (size_t)(i - 4) * (64 * K2B);
            else                 src = pBl + (size_t)(i - 4 - NB) * (64 * K2B);
            cpasync16(st + i * 4096, src + gk);
        }
    };

    const uint32_t ahi = (lane >> 4) * 16;
    const uint32_t bhi = ((lane >> 3) & 1) * 16;
    uint32_t aof[2], aswz[2], bof[NPAIR], bswz[NPAIR];
#pragma unroll
    for (int mi = 0; mi < 2; mi++) {
        int r = wm * 32 + mi * 16 + (lane & 15);
        aof[mi] = r * 64; aswz[mi] = ((r >> 1) & 3) * 16;
    }
#pragma unroll
    for (int pj = 0; pj < NPAIR; pj++) {
        int r = wn * NTW + pj * 16 + ((lane >> 4) << 3) + (lane & 7);
        bof[pj] = (256 + r) * 64; bswz[pj] = ((r >> 1) & 3) * 16;
    }

    float acc[2][NA][4];
#pragma unroll
    for (int mi = 0; mi < 2; mi++)
#pragma unroll
        for (int na = 0; na < NA; na++)
#pragma unroll
            for (int q = 0; q < 4; q++) acc[mi][na][q] = 0.f;

    issue(0, 0); cp_commit();
    issue(1, 1); cp_commit();

    for (int kt = 0; kt < NSTEP; kt++) {
        if (kt + 1 < NSTEP) cp_wait<1>(); else cp_wait<0>();
        __syncthreads();
        if (kt + 2 < NSTEP) { issue(kt + 2, (kt + 2) % 3); cp_commit(); }

        uint32_t stg = sb + (kt % 3) * STAGE;
#pragma unroll
        for (int ks = 0; ks < 2; ks++) {
            const uint32_t ca = (uint32_t)ks * 32 + ahi;
            const uint32_t cb = (uint32_t)ks * 32 + bhi;
            uint32_t ah[2][4], al[2][4], bb[NPAIR][4];
            ldm_x4(ah[0], stg + aof[0] + (ca ^ aswz[0]));
            ldm_x4(ah[1], stg + aof[1] + (ca ^ aswz[1]));
            ldm_x4(al[0], stg + 8192 + aof[0] + (ca ^ aswz[0]));
            ldm_x4(al[1], stg + 8192 + aof[1] + (ca ^ aswz[1]));
#pragma unroll
            for (int pj = 0; pj < NPAIR; pj++)
                ldm_x4(bb[pj], stg + bof[pj] + (cb ^ bswz[pj]));
#pragma unroll
            for (int mi = 0; mi < 2; mi++)
#pragma unroll
                for (int pj = 0; pj < NPAIR; pj++) {
                    mma16816(acc[mi][2 * pj],     ah[mi], &bb[pj][0]);
                    mma16816(acc[mi][2 * pj + 1], ah[mi], &bb[pj][2]);
                }
#pragma unroll
            for (int mi = 0; mi < 2; mi++)
#pragma unroll
                for (int pj = 0; pj < NPAIR; pj++) {
                    mma16816(acc[mi][2 * pj],     al[mi], &bb[pj][0]);
                    mma16816(acc[mi][2 * pj + 1], al[mi], &bb[pj][2]);
                }
#pragma unroll
            for (int pj = 0; pj < NPAIR; pj++)
                ldm_x4(bb[pj], stg + bof[pj] + NT * 64 + (cb ^ bswz[pj]));
#pragma unroll
            for (int mi = 0; mi < 2; mi++)
#pragma unroll
                for (int pj = 0; pj < NPAIR; pj++) {
                    mma16816(acc[mi][2 * pj],     ah[mi], &bb[pj][0]);
                    mma16816(acc[mi][2 * pj + 1], ah[mi], &bb[pj][2]);
                }
        }
    }

    const int g  = lane >> 2;
    const int tg = lane & 3;
#pragma unroll
    for (int mi = 0; mi < 2; mi++) {
        int r = m0 + wm * 32 + mi * 16 + g;
#pragma unroll
        for (int na = 0; na < NA; na++) {
            int ccc = n0 + wn * NTW + na * 8 + tg * 2;
            *(float2*)(C + (size_t)r * Ntot + ccc)       = make_float2(acc[mi][na][0], acc[mi][na][1]);
            *(float2*)(C + (size_t)(r + 8) * Ntot + ccc) = make_float2(acc[mi][na][2], acc[mi][na][3]);
        }
    }
}

// ---------------- fp16 2-term GEMM: C = Ah@Bh^T + Al@Bh^T --------------------
// FUSEQK: tiles with n0<1024 write fp16 Q(split)/K(rounded) pair arrays.
template<int NT, int KTOT, bool FUSEQK>
__device__ __forceinline__ void gemm2f_body(const char* __restrict__ W,
                                            uint32_t offAh, uint32_t offAl,
                                            uint32_t offBh,
                                            float* __restrict__ C, int Ntot)
{
    constexpr int ROWS  = 256 + NT;
    constexpr int STAGE = ROWS * 64;
    constexpr int NSTEP = KTOT / 32;
    constexpr int NTW   = NT / 2;
    constexpr int NPAIR = NTW / 16;
    constexpr int NA    = NTW / 8;
    constexpr int CPT   = ROWS / 64;
    constexpr size_t K2B = KTOT * 2;

    extern __shared__ char sm_raw[];
    const uint32_t sb = smem_u32(sm_raw);
    const int tid = threadIdx.x, wid = tid >> 5, lane = tid & 31;
    const int wm = wid & 3, wn = wid >> 2;
    const int m0 = blockIdx.y * 128, n0 = blockIdx.x * NT;

    const int r0 = tid >> 2;
    const int cc = (tid & 3) * 16;
    const uint32_t dst0 = r0 * 64 + (cc ^ (((r0 >> 1) & 3) * 16));
    const char* pAh = W + offAh + (size_t)(m0 + r0) * K2B + cc;
    const char* pAl = W + offAl + (size_t)(m0 + r0) * K2B + cc;
    const char* pBh = W + offBh + (size_t)(n0 + r0) * K2B + cc;

    auto issue = [&](int kt, int slot) {
        const uint32_t st = sb + slot * STAGE + dst0;
        const size_t gk = (size_t)kt * 64;
#pragma unroll
        for (int i = 0; i < CPT; i++) {
            const char* src;
            if      (i < 2) src = pAh + (size_t)i * (64 * K2B);
            else if (i < 4) src = pAl + (size_t)(i - 2) * (64 * K2B);
            else            src = pBh + (size_t)(i - 4) * (64 * K2B);
            cpasync16(st + i * 4096, src + gk);
        }
    };

    const uint32_t ahi = (lane >> 4) * 16;
    const uint32_t bhi = ((lane >> 3) & 1) * 16;
    uint32_t aof[2], aswz[2], bof[NPAIR], bswz[NPAIR];
#pragma unroll
    for (int mi = 0; mi < 2; mi++) {
        int r = wm * 32 + mi * 16 + (lane & 15);
        aof[mi] = r * 64; aswz[mi] = ((r >> 1) & 3) * 16;
    }
#pragma unroll
    for (int pj = 0; pj < NPAIR; pj++) {
        int r = wn * NTW + pj * 16 + ((lane >> 4) << 3) + (lane & 7);
        bof[pj] = (256 + r) * 64; bswz[pj] = ((r >> 1) & 3) * 16;
    }

    float acc[2][NA][4];
#pragma unroll
    for (int mi = 0; mi < 2; mi++)
#pragma unroll
        for (int na = 0; na < NA; na++)
#pragma unroll
            for (int q = 0; q < 4; q++) acc[mi][na][q] = 0.f;

    issue(0, 0); cp_commit();
    issue(1, 1); cp_commit();

    for (int kt = 0; kt < NSTEP; kt++) {
        if (kt + 1 < NSTEP) cp_wait<1>(); else cp_wait<0>();
        __syncthreads();
        if (kt + 2 < NSTEP) { issue(kt + 2, (kt + 2) % 3); cp_commit(); }

        uint32_t stg = sb + (kt % 3) * STAGE;
#pragma unroll
        for (int ks = 0; ks < 2; ks++) {
            const uint32_t ca = (uint32_t)ks * 32 + ahi;
            const uint32_t cb = (uint32_t)ks * 32 + bhi;
            uint32_t ah[2][4], al[2][4], bb[NPAIR][4];
            ldm_x4(ah[0], stg + aof[0] + (ca ^ aswz[0]));
            ldm_x4(ah[1], stg + aof[1] + (ca ^ aswz[1]));
            ldm_x4(al[0], stg + 8192 + aof[0] + (ca ^ aswz[0]));
            ldm_x4(al[1], stg + 8192 + aof[1] + (ca ^ aswz[1]));
#pragma unroll
            for (int pj = 0; pj < NPAIR; pj++)
                ldm_x4(bb[pj], stg + bof[pj] + (cb ^ bswz[pj]));
#pragma unroll
            for (int mi = 0; mi < 2; mi++)
#pragma unroll
                for (int pj = 0; pj < NPAIR; pj++) {
                    mma16816f(acc[mi][2 * pj],     ah[mi], &bb[pj][0]);
                    mma16816f(acc[mi][2 * pj + 1], ah[mi], &bb[pj][2]);
                }
#pragma unroll
            for (int mi = 0; mi < 2; mi++)
#pragma unroll
                for (int pj = 0; pj < NPAIR; pj++) {
                    mma16816f(acc[mi][2 * pj],     al[mi], &bb[pj][0]);
                    mma16816f(acc[mi][2 * pj + 1], al[mi], &bb[pj][2]);
                }
        }
    }

    const int g  = lane >> 2;
    const int tg = lane & 3;

    if (FUSEQK && n0 < 1024) {
        const bool isQ = (n0 < 512);
        const float sc = isQ ? QSCALE : 1.0f;
#pragma unroll
        for (int mi = 0; mi < 2; mi++) {
            int r = m0 + wm * 32 + mi * 16 + g;
            int b_ = r >> 10, t = r & 1023;
#pragma unroll
            for (int na = 0; na < NA; na++) {
                int ccc = n0 + wn * NTW + na * 8 + tg * 2;
                int h = (ccc >> 6) & 7;
                int p = (ccc & 63) >> 1;
                size_t base = (((size_t)(b_ * 8 + h) << 10) + t) * 32 + p;
                float v0 = acc[mi][na][0] * sc, v1 = acc[mi][na][1] * sc;
                float w0 = acc[mi][na][2] * sc, w1 = acc[mi][na][3] * sc;
                uint32_t h0 = packh2(v0, v1);
                uint32_t h1 = packh2(w0, w1);
                if (isQ) {
                    g_Qh[base] = h0; g_Ql[base] = packh2res(h0, v0, v1);
                    g_Qh[base + 8 * 32] = h1; g_Ql[base + 8 * 32] = packh2res(h1, w0, w1);
                } else {
                    g_Kh[base] = h0;
                    g_Kh[base + 8 * 32] = h1;
                }
            }
        }
    } else {
#pragma unroll
        for (int mi = 0; mi < 2; mi++) {
            int r = m0 + wm * 32 + mi * 16 + g;
#pragma unroll
            for (int na = 0; na < NA; na++) {
                int ccc = n0 + wn * NTW + na * 8 + tg * 2;
                *(float2*)(C + (size_t)r * Ntot + ccc)       = make_float2(acc[mi][na][0], acc[mi][na][1]);
                *(float2*)(C + (size_t)(r + 8) * Ntot + ccc) = make_float2(acc[mi][na][2], acc[mi][na][3]);
            }
        }
    }
}

#define GEMM_SMEM3 (3 * (256 + 128) * 64)   // 73728

__global__ __launch_bounds__(256, 3)
void gemm1() {
    if (blockIdx.x < 16)
        gemm2f_body<64, 1024, true>((const char*)g_W1f, A1Hf * 2, A1Lf * 2, B1Hf * 2, g_C1, N1);
    else if (blockIdx.x < 56)
        gemm2f_body<64, 1024, false>((const char*)g_W1f, A1Hf * 2, A1Lf * 2, B1Hf * 2, g_C1, N1);
    else
        gemm3_body<64, 1024>((const char*)g_W1b, A1H * 2, A1L * 2, B1H * 2, B1L * 2, g_C1, N1);
}
__global__ __launch_bounds__(256, 3)
void gemm2(float* __restrict__ out) {
    gemm2f_body<64, 2560, false>((const char*)g_W2, A2H * 2, A2L * 2, B2H * 2, out, N2);
}

// ---------------- prep kernels ----------------------------------------------
__device__ __forceinline__ void split_bf16(float v, __nv_bfloat16& hi, __nv_bfloat16& lo) {
    hi = __float2bfloat16(v);
    lo = __float2bfloat16(v - __bfloat162float(hi));
}

__global__ __launch_bounds__(256) void prep_a1(const float* __restrict__ x) {
    int gid = blockIdx.x * 256 + threadIdx.x;
    float v = x[gid];
    __nv_bfloat16 hi, lo; split_bf16(v, hi, lo);
    g_W1b[A1H + gid] = hi;
    g_W1b[A1L + gid] = lo;
    __half fh = __float2half_rn(v);
    __half fl = __float2half_rn(v - __half2float(fh));
    g_W1f[A1Hf + gid] = fh;
    g_W1f[A1Lf + gid] = fl;
}

__global__ void prep_b1(const float* __restrict__ Wq, const float* __restrict__ Wk,
                        const float* __restrict__ Wv, const float* __restrict__ Ws,
                        const float* __restrict__ Wd)
{
    __shared__ float tile[32][33];
    int k0 = blockIdx.x * 32;
    int n0 = blockIdx.y * 32;
    int tx = threadIdx.x, ty = threadIdx.y;
#pragma unroll
    for (int yy = 0; yy < 32; yy += 8) {
        int k = k0 + ty + yy, n = n0 + tx;
        float w;
        if      (n < 512)  w = Wq[(size_t)k * 512  + n];
        else if (n < 1024) w = Wk[(size_t)k * 512  + n - 512];
        else if (n < 3584) w = Wv[(size_t)k * 2560 + n - 1024];
        else if (n < 3624) w = Ws[(size_t)k * 40   + n - 3584];
        else if (n < 3664) w = Wd[(size_t)k * 40   + n - 3624];
        else               w = 0.f;
        tile[ty + yy][tx] = w;
    }
    __syncthreads();
#pragma unroll
    for (int yy = 0; yy < 32; yy += 8) {
        int n = n0 + ty + yy, k = k0 + tx;
        float w = tile[tx][ty + yy];
        int idx = n * 1024 + k;
        if (n < 3584) {                         // Q/K/V: fp16 2-term
            g_W1f[B1Hf + idx] = __float2half_rn(w);
        } else {                                // SsSd: bf16 3-term
            __nv_bfloat16 hi, lo; split_bf16(w, hi, lo);
            g_W1b[B1H + idx] = hi;
            g_W1b[B1L + idx] = lo;
        }
    }
}

__global__ __launch_bounds__(256) void prep_b2(const float* __restrict__ Wo) {
    int gid = blockIdx.x * 256 + threadIdx.x;
    int he = gid >> 16;
    int d  = (gid >> 6) & 1023;
    int c  = gid & 63;
    g_W2[B2H + d * V2 + he * 64 + c] = __float2half_rn(Wo[gid]);
}

// ---------------- fused routing gates + expert V mix + transposed pack -------
__global__ __launch_bounds__(256) void route_pack() {
    __shared__ uint32_t tvh[4][65];
    int gid = blockIdx.x * 256 + threadIdx.x;
    int d  = gid & 63;
    int kp = (gid >> 6) & 511;
    int bh = gid >> 15;
    int b = bh >> 3, h = bh & 7;

    float v[2];
#pragma unroll
    for (int u = 0; u < 2; u++) {
        int t = kp * 2 + u;
        const float* row = g_C1 + (size_t)(b * 1024 + t) * N1;
        const float* sl = row + 3584 + h * Ee;
        float s[Ee];
#pragma unroll
        for (int e = 0; e < Ee; e++) s[e] = sl[e];
        float acc = 0.f;
#pragma unroll
        for (int e = 0; e < Ee; e++) {
            int rank = 0;
#pragma unroll
            for (int j = 0; j < Ee; j++)
                rank += (s[j] > s[e]) || (s[j] == s[e] && j < e);
            float gate = (rank < KK) ? 1.0f / (1.0f + expf(-s[e])) : 0.f;
            acc = fmaf(gate, row[1024 + (h * Ee + e) * 64 + d], acc);
        }
        v[u] = acc;

        if (d < Ee) {
            const float* dl = row + 3624 + h * Ee;
            float tq[Ee];
#pragma unroll
            for (int e = 0; e < Ee; e++) tq[e] = dl[e];
            int e = d, rank = 0;
#pragma unroll
            for (int j = 0; j < Ee; j++)
                rank += (tq[j] > tq[e]) || (tq[j] == tq[e] && j < e);
            g_sdg[(b * 1024 + t) * HE + h * Ee + e] = (rank < KK) ? 1.f : 0.f;
        }
    }
    tvh[kp & 3][d] = packh2(v[0], v[1]);
    __syncthreads();
    int td  = threadIdx.x >> 2;
    int tk4 = threadIdx.x & 3;
    int kp0 = (blockIdx.x * 4) & 511;
    g_Vh[((size_t)bh * 64 + td) * 512 + kp0 + tk4] = tvh[tk4][td];
}

// ---------------- tensor-core causal flash attention (fp16 2-term) -----------
// Per wg smem (u32): Qh[64][36], Ql[64][36], 2 stages x {Kh,Vh}[64][36].
#define AQS   (64 * 36)
#define ATL   (64 * 36)
#define ASTG  (2 * ATL)
#define AWG_U (2 * AQS + 2 * ASTG)
#define ATTN_SMEM (2 * AWG_U * 4)

__global__ __launch_bounds__(256) void attn_tc() {
    extern __shared__ uint32_t sm[];
    const int bh   = blockIdx.y;
    const int b    = bh >> 3, h = bh & 7;
    const int wg   = threadIdx.x >> 7;
    const int qt   = wg ? (15 - blockIdx.x) : blockIdx.x;
    const int tid  = threadIdx.x & 127;
    const int w    = tid >> 5;
    const int lane = tid & 31;
    const int g    = lane >> 2;
    const int tig  = lane & 3;
    uint32_t* smg  = sm + wg * AWG_U;
    const uint32_t sb = smem_u32(smg);

    auto issue = [&](int kt, int s) {
#pragma unroll
        for (int i = 0; i < 8; i++) {
            int a = i >> 2;               // 0=Kh, 1=Vh
            int r = (i & 3) * 16 + (tid >> 3);
            int c = tid & 7;
            uint32_t dst = sb + (2 * AQS + s * ASTG + a * ATL + r * 36) * 4 + c * 16;
            const uint32_t* srcb;
            if (a == 0) srcb = g_Kh + ((size_t)(bh << 10) + kt * 64 + r) * 32;
            else        srcb = g_Vh + ((size_t)bh * 64 + r) * 512 + kt * 32;
            cpasync16(dst, (const char*)srcb + c * 16);
        }
    };
    issue(0, 0); cp_commit();

    {
        const uint32_t* qhsrc = g_Qh + ((size_t)(bh << 10) + qt * 64) * 32;
        const uint32_t* qlsrc = g_Ql + ((size_t)(bh << 10) + qt * 64) * 32;
#pragma unroll
        for (int j = 0; j < 4; j++) {
            int idx = tid + j * 128;
            int row = idx >> 3, po = (idx & 7) * 4;
            *(uint4*)&smg[row * 36 + po]       = *(const uint4*)(qhsrc + row * 32 + po);
            *(uint4*)&smg[AQS + row * 36 + po] = *(const uint4*)(qlsrc + row * 32 + po);
        }
    }
    WGBAR(wg);

    uint32_t qa[2][4][4];
#pragma unroll
    for (int hl = 0; hl < 2; hl++) {
        int qb = hl * AQS;
#pragma unroll
        for (int kb = 0; kb < 4; kb++) {
            qa[hl][kb][0] = smg[qb + (w * 16 + g)     * 36 + kb * 8 + tig];
            qa[hl][kb][1] = smg[qb + (w * 16 + g + 8) * 36 + kb * 8 + tig];
            qa[hl][kb][2] = smg[qb + (w * 16 + g)     * 36 + kb * 8 + 4 + tig];
            qa[hl][kb][3] = smg[qb + (w * 16 + g + 8) * 36 + kb * 8 + 4 + tig];
        }
    }

    const int li   = lane >> 3;
    const uint32_t lbase = (((li >> 1) * 8 + (lane & 7)) * 36 + (li & 1) * 4) * 4;

    float o[8][4];
#pragma unroll
    for (int a = 0; a < 8; a++)
#pragma unroll
        for (int q = 0; q < 4; q++) o[a][q] = 0.f;
    float m[2] = {-1e30f, -1e30f}, l[2] = {0.f, 0.f};

    for (int kt = 0; kt <= qt; kt++) {
        if (kt < qt) { issue(kt + 1, (kt + 1) & 1); cp_commit(); cp_wait<1>(); }
        else         { cp_wait<0>(); }
        WGBAR(wg);

        const uint32_t su  = sb + (2 * AQS + (kt & 1) * ASTG) * 4;
        const uint32_t Khb = su, Vhb = su + ATL * 4;

        float s[8][4];
#pragma unroll
        for (int a = 0; a < 8; a++)
#pragma unroll
            for (int q = 0; q < 4; q++) s[a][q] = 0.f;

        // ---- S = (Qh + Ql) * Kh ----
#pragma unroll
        for (int kb = 0; kb < 4; kb++) {
            uint32_t bb[4][4];
#pragma unroll
            for (int j = 0; j < 4; j++)
                ldm_x4(bb[j], Khb + lbase + (j * 576 + kb * 8) * 4);
#pragma unroll
            for (int j = 0; j < 4; j++) {
                mma16816f(s[2*j],   qa[0][kb], &bb[j][0]);
                mma16816f(s[2*j+1], qa[0][kb], &bb[j][2]);
            }
#pragma unroll
            for (int j = 0; j < 4; j++) {
                mma16816f(s[2*j],   qa[1][kb], &bb[j][0]);
                mma16816f(s[2*j+1], qa[1][kb], &bb[j][2]);
            }
        }

        if (kt == qt) {
            int r0 = w * 16 + g;
#pragma unroll
            for (int na = 0; na < 8; na++) {
                int c0 = na * 8 + 2 * tig;
                if (c0     > r0)     s[na][0] = -1e9f;
                if (c0 + 1 > r0)     s[na][1] = -1e9f;
                if (c0     > r0 + 8) s[na][2] = -1e9f;
                if (c0 + 1 > r0 + 8) s[na][3] = -1e9f;
            }
        }

#pragma unroll
        for (int ri = 0; ri < 2; ri++) {
            float mx = -1e30f;
#pragma unroll
            for (int a = 0; a < 8; a++)
                mx = fmaxf(mx, fmaxf(s[a][2 * ri], s[a][2 * ri + 1]));
            mx = fmaxf(mx, __shfl_xor_sync(0xffffffffu, mx, 1));
            mx = fmaxf(mx, __shfl_xor_sync(0xffffffffu, mx, 2));
            float mnew = fmaxf(m[ri], mx);
            float corr = __expf(m[ri] - mnew);
            float rs = 0.f;
#pragma unroll
            for (int a = 0; a < 8; a++) {
                float p0 = __expf(s[a][2 * ri]     - mnew);
                float p1 = __expf(s[a][2 * ri + 1] - mnew);
                s[a][2 * ri] = p0; s[a][2 * ri + 1] = p1;
                rs += p0 + p1;
            }
            rs += __shfl_xor_sync(0xffffffffu, rs, 1);
            rs += __shfl_xor_sync(0xffffffffu, rs, 2);
            l[ri] = l[ri] * corr + rs;
            m[ri] = mnew;
#pragma unroll
            for (int a = 0; a < 8; a++) { o[a][2 * ri] *= corr; o[a][2 * ri + 1] *= corr; }
        }

        // ---- O += (Ph + Pl) * Vh ----
#pragma unroll
        for (int kb = 0; kb < 4; kb++) {
            uint32_t ph[4], pl[4];
            ph[0] = packh2(s[2*kb][0],   s[2*kb][1]);
            ph[1] = packh2(s[2*kb][2],   s[2*kb][3]);
            ph[2] = packh2(s[2*kb+1][0], s[2*kb+1][1]);
            ph[3] = packh2(s[2*kb+1][2], s[2*kb+1][3]);
            pl[0] = packh2res(ph[0], s[2*kb][0],   s[2*kb][1]);
            pl[1] = packh2res(ph[1], s[2*kb][2],   s[2*kb][3]);
            pl[2] = packh2res(ph[2], s[2*kb+1][0], s[2*kb+1][1]);
            pl[3] = packh2res(ph[3], s[2*kb+1][2], s[2*kb+1][3]);

            uint32_t bb[4][4];
#pragma unroll
            for (int j = 0; j < 4; j++)
                ldm_x4(bb[j], Vhb + lbase + (j * 576 + kb * 8) * 4);
#pragma unroll
            for (int j = 0; j < 4; j++) {
                mma16816f(o[2*j],   ph, &bb[j][0]);
                mma16816f(o[2*j+1], ph, &bb[j][2]);
            }
#pragma unroll
            for (int j = 0; j < 4; j++) {
                mma16816f(o[2*j],   pl, &bb[j][0]);
                mma16816f(o[2*j+1], pl, &bb[j][2]);
            }
        }
        WGBAR(wg);
    }

    // ---- fused epilogue: A2 = fp16-split(sd * O) for all 5 experts ----
    float inv0 = 1.0f / l[0], inv1 = 1.0f / l[1];
    int row0 = qt * 64 + w * 16 + g;
    int bt0  = b * 1024 + row0;

    float g0[Ee], g1[Ee];
#pragma unroll
    for (int e = 0; e < Ee; e++) {
        g0[e] = g_sdg[bt0 * HE + h * Ee + e];
        g1[e] = g_sdg[(bt0 + 8) * HE + h * Ee + e];
    }
    uint32_t* a2h0 = (uint32_t*)(g_W2 + A2H + (size_t)bt0 * V2);
    uint32_t* a2l0 = (uint32_t*)(g_W2 + A2L + (size_t)bt0 * V2);
    uint32_t* a2h1 = (uint32_t*)(g_W2 + A2H + (size_t)(bt0 + 8) * V2);
    uint32_t* a2l1 = (uint32_t*)(g_W2 + A2L + (size_t)(bt0 + 8) * V2);

#pragma unroll
    for (int na = 0; na < 8; na++) {
        int c0 = na * 8 + 2 * tig;
        float v00 = o[na][0] * inv0, v01 = o[na][1] * inv0;
        float v10 = o[na][2] * inv1, v11 = o[na][3] * inv1;
        uint32_t h0u = packh2(v00, v01), l0u = packh2res(h0u, v00, v01);
        uint32_t h1u = packh2(v10, v11), l1u = packh2res(h1u, v10, v11);
#pragma unroll
        for (int e = 0; e < Ee; e++) {
            int cw = ((h * Ee + e) * 64 + c0) >> 1;
            a2h0[cw] = (g0[e] != 0.f) ? h0u : 0u;
            a2l0[cw] = (g0[e] != 0.f) ? l0u : 0u;
            a2h1[cw] = (g1[e] != 0.f) ? h1u : 0u;
            a2l1[cw] = (g1[e] != 0.f) ? l1u : 0u;
        }
    }
}

// ---------------- launch ------------------------------------------------------
extern "C" void kernel_launch(void* const* d_in, const int* in_sizes, int n_in,
                              void* d_out, int out_size)
{
    const float* x  = (const float*)d_in[0];
    const float* Wq = (const float*)d_in[1];
    const float* Wk = (const float*)d_in[2];
    const float* Wv = (const float*)d_in[3];
    const float* Ws = (const float*)d_in[4];
    const float* Wd = (const float*)d_in[5];
    const float* Wo = (const float*)d_in[6];
    float* out = (float*)d_out;

    cudaFuncSetAttribute(gemm1,   cudaFuncAttributeMaxDynamicSharedMemorySize, GEMM_SMEM3);
    cudaFuncSetAttribute(gemm2,   cudaFuncAttributeMaxDynamicSharedMemorySize, GEMM_SMEM3);
    cudaFuncSetAttribute(attn_tc, cudaFuncAttributeMaxDynamicSharedMemorySize, ATTN_SMEM);

    prep_a1   <<<BT * DIMD / 256, 256>>>(x);
    prep_b1   <<<dim3(32, 120), dim3(32, 8)>>>(Wq, Wk, Wv, Ws, Wd);
    prep_b2   <<<HE * DIMD * 64 / 256, 256>>>(Wo);
    gemm1     <<<dim3(N1 / 64, BT / 128), 256, GEMM_SMEM3>>>();
    route_pack<<<16 * 512 * 64 / 256, 256>>>();
    attn_tc   <<<dim3(8, 16), 256, ATTN_SMEM>>>();
    gemm2     <<<dim3(N2 / 64, BT / 128), 256, GEMM_SMEM3>>>(out);
}